// round 1
// baseline (speedup 1.0000x reference)
#include <cuda_runtime.h>
#include <cstdint>

#define D 128
#define TILE_ROWS 128
#define NTHREADS 256

// ---------------- static scratch (allocation-free rule) ----------------
__device__ float g_g0[100000 * 128];   // h0 @ Wagg[128:256]
__device__ float g_g1[150000 * 128];   // h1 @ Wagg[256:384]
__device__ float g_g2[80000 * 128];    // h2 @ Wagg[384:512]
__device__ float g_a1_0[100000];
__device__ float g_a2_0[100000];
__device__ float g_a2_1[150000];
__device__ float g_a2_2[80000];

// ---------------- f32x2 packed helpers ----------------
__device__ __forceinline__ unsigned long long splat2(float x) {
    unsigned long long r;
    asm("mov.b64 %0, {%1, %1};" : "=l"(r) : "f"(x));
    return r;
}
__device__ __forceinline__ unsigned long long fma2(unsigned long long a,
                                                   unsigned long long b,
                                                   unsigned long long c) {
    unsigned long long d;
    asm("fma.rn.f32x2 %0, %1, %2, %3;" : "=l"(d) : "l"(a), "l"(b), "l"(c));
    return d;
}
__device__ __forceinline__ void unpack2(unsigned long long v, float& lo, float& hi) {
    asm("mov.b64 {%0, %1}, %2;" : "=f"(lo), "=f"(hi) : "l"(v));
}

// 64-row x 128-col microtiled GEMM from smem A (row stride D) x smem W (row-major 128x128).
// Thread (tx,ty): rows r0=ty*4..+3, cols c0=tx*8..+7, accumulators as f32x2 pairs.
__device__ __forceinline__ void mm64(const float* __restrict__ sA,
                                     const float* __restrict__ sW,
                                     int r0, int c0,
                                     unsigned long long acc[4][4]) {
#pragma unroll
    for (int i = 0; i < 4; i++)
#pragma unroll
        for (int j = 0; j < 4; j++) acc[i][j] = 0ULL;

#pragma unroll 4
    for (int k = 0; k < D; k++) {
        unsigned long long xs[4];
#pragma unroll
        for (int i = 0; i < 4; i++) xs[i] = splat2(sA[(r0 + i) * D + k]);
        const ulonglong2* wp = (const ulonglong2*)(sW + k * D + c0);
        ulonglong2 wa = wp[0];
        ulonglong2 wb = wp[1];
        unsigned long long w[4] = {wa.x, wa.y, wb.x, wb.y};
#pragma unroll
        for (int i = 0; i < 4; i++)
#pragma unroll
            for (int j = 0; j < 4; j++) acc[i][j] = fma2(xs[i], w[j], acc[i][j]);
    }
}

// ---------------- node kernel ----------------
// Per 128-row tile:
//   h  = relu(x @ W1 + b1)         (h kept in smem only)
//   a1 = h @ a1_w + a1_b  (optional), a2 = h @ a2_w + a2_b
//   g  = h @ Wg                     -> gout
//   self = h @ Wself + bagg         -> selfout (optional; initializes d_out)
__global__ __launch_bounds__(NTHREADS, 1)
void node_kernel(const float* __restrict__ x, int nrows,
                 const float* __restrict__ W1, const float* __restrict__ b1,
                 const float* __restrict__ a1w, const float* __restrict__ a1bp,
                 const float* __restrict__ a2w, const float* __restrict__ a2bp,
                 const float* __restrict__ Wg,
                 const float* __restrict__ Wself,
                 const float* __restrict__ bagg,
                 float* __restrict__ gout,
                 float* __restrict__ a1out,
                 float* __restrict__ a2out,
                 float* __restrict__ selfout) {
    extern __shared__ float smem[];
    float* sW = smem;            // 16384 floats (64KB), ping-ponged W1 -> Wg -> Wself
    float* sX = sW + 16384;      // 8192  floats (32KB), 64-row x staging
    float* sH = sX + 8192;       // 16384 floats (64KB), full 128-row h tile

    const int tid = threadIdx.x;
    const int tx = tid & 15;
    const int ty = tid >> 4;
    const int c0 = tx * 8;
    const int r0 = ty * 4;
    const int rbase = blockIdx.x * TILE_ROWS;

    // stage W1
    {
        const float4* src = (const float4*)W1;
        float4* dst = (float4*)sW;
#pragma unroll
        for (int i = 0; i < 16; i++) dst[tid + i * 256] = src[tid + i * 256];
    }
    float bb[8], aw1[8], aw2[8], bg[8];
#pragma unroll
    for (int j = 0; j < 8; j++) {
        bb[j] = b1[c0 + j];
        aw1[j] = a1w[c0 + j];
        aw2[j] = a2w[c0 + j];
        bg[j] = bagg[c0 + j];
    }
    const float a1b = *a1bp;
    const float a2b = *a2bp;
    __syncthreads();

    // ---- phase 1: h = relu(x @ W1 + b1), a1/a2, h -> sH ----
#pragma unroll 1
    for (int sub = 0; sub < 2; sub++) {
        const int rs = rbase + sub * 64;
        // stage x subtile (guarded)
#pragma unroll
        for (int i = 0; i < 8; i++) {
            int idx = tid + i * 256;     // float4 index within 64x128 tile
            int row = idx >> 5;
            int col = idx & 31;
            float4 v = make_float4(0.f, 0.f, 0.f, 0.f);
            if (rs + row < nrows) v = ((const float4*)(x + (size_t)(rs + row) * D))[col];
            ((float4*)sX)[idx] = v;
        }
        __syncthreads();

        unsigned long long acc[4][4];
        mm64(sX, sW, r0, c0, acc);

        // epilogue: bias+relu, attention partials, write sH
#pragma unroll
        for (int i = 0; i < 4; i++) {
            float h[8];
#pragma unroll
            for (int j = 0; j < 4; j++) unpack2(acc[i][j], h[2 * j], h[2 * j + 1]);
            float pa1 = 0.f, pa2 = 0.f;
#pragma unroll
            for (int j = 0; j < 8; j++) {
                h[j] = fmaxf(h[j] + bb[j], 0.f);
                pa1 += h[j] * aw1[j];
                pa2 += h[j] * aw2[j];
            }
            const int rr = sub * 64 + r0 + i;
            float4* hp = (float4*)(sH + rr * D + c0);
            hp[0] = make_float4(h[0], h[1], h[2], h[3]);
            hp[1] = make_float4(h[4], h[5], h[6], h[7]);
            // reduce partials across the 16 tx lanes (lanes 0-15 / 16-31 stay disjoint)
#pragma unroll
            for (int off = 8; off >= 1; off >>= 1) {
                pa1 += __shfl_down_sync(0xffffffffu, pa1, off);
                pa2 += __shfl_down_sync(0xffffffffu, pa2, off);
            }
            if (tx == 0 && (rs + r0 + i) < nrows) {
                if (a1out) a1out[rs + r0 + i] = pa1 + a1b;
                a2out[rs + r0 + i] = pa2 + a2b;
            }
        }
        __syncthreads();
    }

    // ---- phase 2: g = h @ Wg ----
    {
        const float4* src = (const float4*)Wg;
        float4* dst = (float4*)sW;
#pragma unroll
        for (int i = 0; i < 16; i++) dst[tid + i * 256] = src[tid + i * 256];
    }
    __syncthreads();
#pragma unroll 1
    for (int sub = 0; sub < 2; sub++) {
        unsigned long long acc[4][4];
        mm64(sH + sub * 64 * D, sW, r0, c0, acc);
#pragma unroll
        for (int i = 0; i < 4; i++) {
            int grow = rbase + sub * 64 + r0 + i;
            if (grow < nrows) {
                float v[8];
#pragma unroll
                for (int j = 0; j < 4; j++) unpack2(acc[i][j], v[2 * j], v[2 * j + 1]);
                float4* op = (float4*)(gout + (size_t)grow * D + c0);
                op[0] = make_float4(v[0], v[1], v[2], v[3]);
                op[1] = make_float4(v[4], v[5], v[6], v[7]);
            }
        }
    }

    // ---- phase 3 (x0 only): selfout = h @ Wself + bagg ----
    if (selfout) {
        __syncthreads();
        {
            const float4* src = (const float4*)Wself;
            float4* dst = (float4*)sW;
#pragma unroll
            for (int i = 0; i < 16; i++) dst[tid + i * 256] = src[tid + i * 256];
        }
        __syncthreads();
#pragma unroll 1
        for (int sub = 0; sub < 2; sub++) {
            unsigned long long acc[4][4];
            mm64(sH + sub * 64 * D, sW, r0, c0, acc);
#pragma unroll
            for (int i = 0; i < 4; i++) {
                int grow = rbase + sub * 64 + r0 + i;
                if (grow < nrows) {
                    float v[8];
#pragma unroll
                    for (int j = 0; j < 4; j++) unpack2(acc[i][j], v[2 * j], v[2 * j + 1]);
#pragma unroll
                    for (int j = 0; j < 8; j++) v[j] += bg[j];
                    float4* op = (float4*)(selfout + (size_t)grow * D + c0);
                    op[0] = make_float4(v[0], v[1], v[2], v[3]);
                    op[1] = make_float4(v[4], v[5], v[6], v[7]);
                }
            }
        }
    }
}

// ---------------- edge kernel: one warp per edge ----------------
// out[row] += sigmoid(a1[row] + a2[col]) * g[col]   (128 floats, vector RED)
__global__ __launch_bounds__(256)
void edge_kernel(const int* __restrict__ rows, const int* __restrict__ cols, int E,
                 const float* __restrict__ a1, const float* __restrict__ a2,
                 const float* __restrict__ g, float* __restrict__ out) {
    int gw = (int)((blockIdx.x * (unsigned)blockDim.x + threadIdx.x) >> 5);
    int lane = threadIdx.x & 31;
    if (gw >= E) return;
    int r = __ldg(rows + gw);
    int c = __ldg(cols + gw);
    float s = __ldg(a1 + r) + __ldg(a2 + c);
    s = 1.0f / (1.0f + __expf(-s));
    float4 v = __ldg(((const float4*)(g + (size_t)c * D)) + lane);
    float* dst = out + (size_t)r * D + (size_t)lane * 4;
    asm volatile("red.global.add.v4.f32 [%0], {%1, %2, %3, %4};"
                 :: "l"(dst), "f"(s * v.x), "f"(s * v.y), "f"(s * v.z), "f"(s * v.w)
                 : "memory");
}

// ---------------- launch ----------------
extern "C" void kernel_launch(void* const* d_in, const int* in_sizes, int n_in,
                              void* d_out, int out_size) {
    const float* x0   = (const float*)d_in[0];
    const float* x1   = (const float*)d_in[1];
    const float* x2   = (const float*)d_in[2];
    const float* W1   = (const float*)d_in[3];
    const float* b1   = (const float*)d_in[4];
    const float* a1w  = (const float*)d_in[5];
    const float* a1b  = (const float*)d_in[6];
    const float* a2w  = (const float*)d_in[7];
    const float* a2b  = (const float*)d_in[8];
    const float* Wagg = (const float*)d_in[9];
    const float* bagg = (const float*)d_in[10];
    const int* ar0 = (const int*)d_in[11];
    const int* ac0 = (const int*)d_in[12];
    const int* ar1 = (const int*)d_in[13];
    const int* ac1 = (const int*)d_in[14];
    const int* ar2 = (const int*)d_in[15];
    const int* ac2 = (const int*)d_in[16];
    float* out = (float*)d_out;

    const int N0 = in_sizes[0] / D;
    const int N1 = in_sizes[1] / D;
    const int N2 = in_sizes[2] / D;
    const int E0 = in_sizes[11];
    const int E1 = in_sizes[13];
    const int E2 = in_sizes[15];

    float *pg0, *pg1, *pg2, *pa10, *pa20, *pa21, *pa22;
    cudaGetSymbolAddress((void**)&pg0, g_g0);
    cudaGetSymbolAddress((void**)&pg1, g_g1);
    cudaGetSymbolAddress((void**)&pg2, g_g2);
    cudaGetSymbolAddress((void**)&pa10, g_a1_0);
    cudaGetSymbolAddress((void**)&pa20, g_a2_0);
    cudaGetSymbolAddress((void**)&pa21, g_a2_1);
    cudaGetSymbolAddress((void**)&pa22, g_a2_2);

    const int smem_bytes = (16384 + 8192 + 16384) * (int)sizeof(float);  // 160KB
    cudaFuncSetAttribute(node_kernel, cudaFuncAttributeMaxDynamicSharedMemorySize, smem_bytes);

    // node kernels: x0 (self init + g0 + a1/a2), x1 (g1 + a2), x2 (g2 + a2)
    node_kernel<<<(N0 + TILE_ROWS - 1) / TILE_ROWS, NTHREADS, smem_bytes>>>(
        x0, N0, W1, b1, a1w, a1b, a2w, a2b,
        Wagg + 1 * D * D, Wagg + 0 * D * D, bagg,
        pg0, pa10, pa20, out);
    node_kernel<<<(N1 + TILE_ROWS - 1) / TILE_ROWS, NTHREADS, smem_bytes>>>(
        x1, N1, W1, b1, a1w, a1b, a2w, a2b,
        Wagg + 2 * D * D, nullptr, bagg,
        pg1, nullptr, pa21, nullptr);
    node_kernel<<<(N2 + TILE_ROWS - 1) / TILE_ROWS, NTHREADS, smem_bytes>>>(
        x2, N2, W1, b1, a1w, a1b, a2w, a2b,
        Wagg + 3 * D * D, nullptr, bagg,
        pg2, nullptr, pa22, nullptr);

    // edge scatter kernels: accumulate directly into d_out
    edge_kernel<<<(E0 + 7) / 8, 256>>>(ar0, ac0, E0, pa10, pa20, pg0, out);
    edge_kernel<<<(E1 + 7) / 8, 256>>>(ar1, ac1, E1, pa10, pa21, pg1, out);
    edge_kernel<<<(E2 + 7) / 8, 256>>>(ar2, ac2, E2, pa10, pa22, pg2, out);
}

// round 2
// speedup vs baseline: 1.2063x; 1.2063x over previous
#include <cuda_runtime.h>
#include <cstdint>

#define D 128
#define N0MAX 100000
#define EMAX  1000000
#define NTHREADS 256

typedef unsigned long long ull;

// ---------------- static scratch (allocation-free rule) ----------------
__device__ float g_g0[N0MAX * 128];           // h0 @ Wagg[128:256]
__device__ float g_g1[150000 * 128];          // h1 @ Wagg[256:384]
__device__ float g_g2[80000 * 128];           // h2 @ Wagg[384:512]
__device__ float g_a1_0[N0MAX];
__device__ float g_a2_0[N0MAX];
__device__ float g_a2_1[150000];
__device__ float g_a2_2[80000];
// CSR binning scratch
__device__ int g_cnt[3 * (N0MAX + 1)];
__device__ int g_off[3 * (N0MAX + 1)];
__device__ int g_cur[3 * N0MAX];
__device__ int g_sc0[EMAX];
__device__ int g_sc1[EMAX];
__device__ int g_sc2[EMAX];

// ---------------- f32x2 packed helpers ----------------
__device__ __forceinline__ ull splat2(float x) {
    ull r;
    asm("mov.b64 %0, {%1, %1};" : "=l"(r) : "f"(x));
    return r;
}
__device__ __forceinline__ ull fma2(ull a, ull b, ull c) {
    ull d;
    asm("fma.rn.f32x2 %0, %1, %2, %3;" : "=l"(d) : "l"(a), "l"(b), "l"(c));
    return d;
}
__device__ __forceinline__ void unpack2(ull v, float& lo, float& hi) {
    asm("mov.b64 {%0, %1}, %2;" : "=f"(lo), "=f"(hi) : "l"(v));
}

// ---------------- 128x128 GEMM core ----------------
// sA: row-major 128x128 with row-swizzle (k index XORed by 16 when row bit3 set)
// sW: 128x128 with half-split column perm (see stage_w)
// Thread (tx,ty): rows r0=ty*8..+7, cols c0=tx*8..+7. acc as f32x2 pairs.
__device__ __forceinline__ void mm128(const float* __restrict__ sA,
                                      const float* __restrict__ sW,
                                      int r0, int tx, int xsw,
                                      ull acc[8][4]) {
#pragma unroll
    for (int i = 0; i < 8; i++)
#pragma unroll
        for (int j = 0; j < 4; j++) acc[i][j] = 0ULL;

    const float* a0 = sA + r0 * D;
#pragma unroll 4
    for (int k = 0; k < D; k++) {
        const int kx = k ^ xsw;
        ull xs[8];
#pragma unroll
        for (int i = 0; i < 8; i++) xs[i] = splat2(a0[i * D + kx]);
        ulonglong2 wa = *(const ulonglong2*)(sW + k * D + tx * 4);
        ulonglong2 wb = *(const ulonglong2*)(sW + k * D + 64 + tx * 4);
#pragma unroll
        for (int i = 0; i < 8; i++) {
            acc[i][0] = fma2(xs[i], wa.x, acc[i][0]);
            acc[i][1] = fma2(xs[i], wa.y, acc[i][1]);
            acc[i][2] = fma2(xs[i], wb.x, acc[i][2]);
            acc[i][3] = fma2(xs[i], wb.y, acc[i][3]);
        }
    }
}

// Stage a 128x128 weight matrix into sW with the half-split column perm:
// logical col j -> phys float index ((j>>3)<<2) + (j&3) + ((j&4)?64:0)
// In float4 units: src float4 index f (k=f>>5, c4=f&31) -> dst k*32 + ((c4&1)<<4) + (c4>>1)
__device__ __forceinline__ void stage_w(const float* __restrict__ W, float* __restrict__ sW,
                                        int tid) {
    const float4* src = (const float4*)W;
    float4* dst = (float4*)sW;
#pragma unroll
    for (int i = 0; i < 16; i++) {
        int f = tid + i * 256;
        int k = f >> 5, c4 = f & 31;
        dst[k * 32 + ((c4 & 1) << 4) + (c4 >> 1)] = src[f];
    }
}

// ---------------- node kernel ----------------
__global__ __launch_bounds__(NTHREADS, 1)
void node_kernel(const float* __restrict__ x, int nrows,
                 const float* __restrict__ W1, const float* __restrict__ b1,
                 const float* __restrict__ a1w, const float* __restrict__ a1bp,
                 const float* __restrict__ a2w, const float* __restrict__ a2bp,
                 const float* __restrict__ Wg,
                 const float* __restrict__ Wself,
                 const float* __restrict__ bagg,
                 float* __restrict__ gout,
                 float* __restrict__ a1out,
                 float* __restrict__ a2out,
                 float* __restrict__ selfout) {
    extern __shared__ float smem[];
    float* sW = smem;            // 16384 floats (64KB)
    float* sX = smem + 16384;    // 16384 floats (64KB), row-swizzled x tile
    float* sH = smem + 32768;    // 16384 floats (64KB), row-swizzled h tile

    const int tid = threadIdx.x;
    const int tx = tid & 15;
    const int ty = tid >> 4;
    const int c0 = tx * 8;
    const int r0 = ty * 8;
    const int xsw = (ty & 1) << 4;     // row bit3 -> XOR k by 16
    const int rbase = blockIdx.x * 128;

    stage_w(W1, sW, tid);

    float bb[8], aw1[8], aw2[8], bg[8];
#pragma unroll
    for (int j = 0; j < 8; j++) {
        bb[j] = b1[c0 + j];
        aw1[j] = a1w[c0 + j];
        aw2[j] = a2w[c0 + j];
        bg[j] = bagg[c0 + j];
    }
    const float a1b = *a1bp;
    const float a2b = *a2bp;

    // stage x: 128 rows, row-swizzled (float4 index XORed by 4 when row bit3 set)
    {
#pragma unroll
        for (int i = 0; i < 16; i++) {
            int f = tid + i * 256;
            int row = f >> 5, c4 = f & 31;
            float4 v = make_float4(0.f, 0.f, 0.f, 0.f);
            if (rbase + row < nrows) v = ((const float4*)(x + (size_t)(rbase + row) * D))[c4];
            ((float4*)sX)[row * 32 + (c4 ^ ((row & 8) >> 1))] = v;
        }
    }
    __syncthreads();

    ull acc[8][4];

    // ---- phase 1: h = relu(x @ W1 + b1); a1/a2; h -> sH ----
    mm128(sX, sW, r0, tx, xsw, acc);
#pragma unroll
    for (int i = 0; i < 8; i++) {
        float h[8];
#pragma unroll
        for (int j = 0; j < 4; j++) unpack2(acc[i][j], h[2 * j], h[2 * j + 1]);
        float pa1 = 0.f, pa2 = 0.f;
#pragma unroll
        for (int j = 0; j < 8; j++) {
            h[j] = fmaxf(h[j] + bb[j], 0.f);
            pa1 += h[j] * aw1[j];
            pa2 += h[j] * aw2[j];
        }
        const int row = r0 + i;
        const int c4s = (row & 8) >> 1;
        float4* hp = (float4*)sH + row * 32;
        hp[(tx * 2) ^ c4s]     = make_float4(h[0], h[1], h[2], h[3]);
        hp[(tx * 2 + 1) ^ c4s] = make_float4(h[4], h[5], h[6], h[7]);
#pragma unroll
        for (int off = 8; off >= 1; off >>= 1) {
            pa1 += __shfl_down_sync(0xffffffffu, pa1, off);
            pa2 += __shfl_down_sync(0xffffffffu, pa2, off);
        }
        const int grow = rbase + row;
        if (tx == 0 && grow < nrows) {
            if (a1out) a1out[grow] = pa1 + a1b;
            a2out[grow] = pa2 + a2b;
        }
    }
    __syncthreads();

    // ---- phase 2: g = h @ Wg ----
    stage_w(Wg, sW, tid);
    __syncthreads();
    mm128(sH, sW, r0, tx, xsw, acc);
#pragma unroll
    for (int i = 0; i < 8; i++) {
        const int grow = rbase + r0 + i;
        if (grow < nrows) {
            float v[8];
#pragma unroll
            for (int j = 0; j < 4; j++) unpack2(acc[i][j], v[2 * j], v[2 * j + 1]);
            float4* op = (float4*)(gout + (size_t)grow * D + c0);
            op[0] = make_float4(v[0], v[1], v[2], v[3]);
            op[1] = make_float4(v[4], v[5], v[6], v[7]);
        }
    }

    // ---- phase 3 (x0 only): selfout = h @ Wself + bagg ----
    if (selfout) {
        __syncthreads();
        stage_w(Wself, sW, tid);
        __syncthreads();
        mm128(sH, sW, r0, tx, xsw, acc);
#pragma unroll
        for (int i = 0; i < 8; i++) {
            const int grow = rbase + r0 + i;
            if (grow < nrows) {
                float v[8];
#pragma unroll
                for (int j = 0; j < 4; j++) unpack2(acc[i][j], v[2 * j], v[2 * j + 1]);
#pragma unroll
                for (int j = 0; j < 8; j++) v[j] += bg[j];
                float4* op = (float4*)(selfout + (size_t)grow * D + c0);
                op[0] = make_float4(v[0], v[1], v[2], v[3]);
                op[1] = make_float4(v[4], v[5], v[6], v[7]);
            }
        }
    }
}

// ---------------- binning kernels ----------------
__global__ void zero_kernel(int* p, int n) {
    int i = blockIdx.x * blockDim.x + threadIdx.x;
    if (i < n) p[i] = 0;
}

__global__ void hist3_kernel(const int* __restrict__ r0, int E0,
                             const int* __restrict__ r1, int E1,
                             const int* __restrict__ r2, int E2,
                             int* __restrict__ c0, int* __restrict__ c1,
                             int* __restrict__ c2) {
    int t = blockIdx.x * blockDim.x + threadIdx.x;
    if (t < E0) { atomicAdd(&c0[__ldg(r0 + t)], 1); return; }
    t -= E0;
    if (t < E1) { atomicAdd(&c1[__ldg(r1 + t)], 1); return; }
    t -= E1;
    if (t < E2) { atomicAdd(&c2[__ldg(r2 + t)], 1); }
}

__device__ void scan_one(const int* __restrict__ cnt, int n,
                         int* __restrict__ offs, int* __restrict__ cur) {
    __shared__ int wsum[32];
    __shared__ int s_carry;
    const int tid = threadIdx.x, lane = tid & 31, wid = tid >> 5;
    if (tid == 0) s_carry = 0;
    __syncthreads();
    for (int base = 0; base < n; base += 4096) {
        int idx = base + tid * 4;
        int v[4];
#pragma unroll
        for (int j = 0; j < 4; j++) v[j] = (idx + j < n) ? cnt[idx + j] : 0;
        int tsum = v[0] + v[1] + v[2] + v[3];
        int xv = tsum;
#pragma unroll
        for (int off = 1; off < 32; off <<= 1) {
            int t = __shfl_up_sync(0xffffffffu, xv, off);
            if (lane >= off) xv += t;
        }
        if (lane == 31) wsum[wid] = xv;
        __syncthreads();
        if (wid == 0) {
            int y = wsum[lane];
#pragma unroll
            for (int off = 1; off < 32; off <<= 1) {
                int t = __shfl_up_sync(0xffffffffu, y, off);
                if (lane >= off) y += t;
            }
            wsum[lane] = y;
        }
        __syncthreads();
        int warpoff = (wid == 0) ? 0 : wsum[wid - 1];
        int carry = s_carry;
        int excl = carry + warpoff + xv - tsum;
#pragma unroll
        for (int j = 0; j < 4; j++) {
            if (idx + j < n) { offs[idx + j] = excl; cur[idx + j] = excl; }
            excl += v[j];
        }
        __syncthreads();
        if (tid == 0) s_carry = carry + wsum[31];
        __syncthreads();
    }
    if (tid == 0) offs[n] = s_carry;
    __syncthreads();
}

__global__ void scan3_kernel(const int* c0, const int* c1, const int* c2, int n,
                             int* o0, int* u0, int* o1, int* u1, int* o2, int* u2) {
    scan_one(c0, n, o0, u0);
    scan_one(c1, n, o1, u1);
    scan_one(c2, n, o2, u2);
}

__global__ void scat3_kernel(const int* __restrict__ r0, const int* __restrict__ col0, int E0,
                             const int* __restrict__ r1, const int* __restrict__ col1, int E1,
                             const int* __restrict__ r2, const int* __restrict__ col2, int E2,
                             int* __restrict__ u0, int* __restrict__ u1, int* __restrict__ u2,
                             int* __restrict__ s0, int* __restrict__ s1, int* __restrict__ s2) {
    int t = blockIdx.x * blockDim.x + threadIdx.x;
    if (t < E0) { int p = atomicAdd(&u0[__ldg(r0 + t)], 1); s0[p] = __ldg(col0 + t); return; }
    t -= E0;
    if (t < E1) { int p = atomicAdd(&u1[__ldg(r1 + t)], 1); s1[p] = __ldg(col1 + t); return; }
    t -= E1;
    if (t < E2) { int p = atomicAdd(&u2[__ldg(r2 + t)], 1); s2[p] = __ldg(col2 + t); }
}

// ---------------- aggregate: one warp per output row ----------------
__device__ __forceinline__ void agg_list(int row, int lane, float va1,
                                         const int* __restrict__ offs,
                                         const int* __restrict__ scols,
                                         const float* __restrict__ a2,
                                         const float* __restrict__ g,
                                         float4& acc) {
    int s = __ldg(offs + row), e = __ldg(offs + row + 1);
    for (int i = s; i < e; i++) {
        int c = __ldg(scols + i);
        float sv = va1 + __ldg(a2 + c);
        sv = 1.0f / (1.0f + __expf(-sv));
        float4 v = __ldg((const float4*)(g + (size_t)c * D) + lane);
        acc.x += sv * v.x;
        acc.y += sv * v.y;
        acc.z += sv * v.z;
        acc.w += sv * v.w;
    }
}

__global__ __launch_bounds__(256)
void agg_kernel(const int* __restrict__ o0, const int* __restrict__ s0,
                const float* __restrict__ g0, const float* __restrict__ a20,
                const int* __restrict__ o1, const int* __restrict__ s1,
                const float* __restrict__ g1, const float* __restrict__ a21,
                const int* __restrict__ o2, const int* __restrict__ s2,
                const float* __restrict__ g2, const float* __restrict__ a22,
                const float* __restrict__ a1, float* __restrict__ out, int n0) {
    int row = blockIdx.x * 8 + (threadIdx.x >> 5);
    if (row >= n0) return;
    int lane = threadIdx.x & 31;
    float va1 = __ldg(a1 + row);
    float4 acc = make_float4(0.f, 0.f, 0.f, 0.f);
    agg_list(row, lane, va1, o0, s0, a20, g0, acc);
    agg_list(row, lane, va1, o1, s1, a21, g1, acc);
    agg_list(row, lane, va1, o2, s2, a22, g2, acc);
    float4* op = (float4*)(out + (size_t)row * D) + lane;
    float4 c = *op;
    c.x += acc.x; c.y += acc.y; c.z += acc.z; c.w += acc.w;
    *op = c;
}

// ---------------- launch ----------------
extern "C" void kernel_launch(void* const* d_in, const int* in_sizes, int n_in,
                              void* d_out, int out_size) {
    const float* x0   = (const float*)d_in[0];
    const float* x1   = (const float*)d_in[1];
    const float* x2   = (const float*)d_in[2];
    const float* W1   = (const float*)d_in[3];
    const float* b1   = (const float*)d_in[4];
    const float* a1w  = (const float*)d_in[5];
    const float* a1b  = (const float*)d_in[6];
    const float* a2w  = (const float*)d_in[7];
    const float* a2b  = (const float*)d_in[8];
    const float* Wagg = (const float*)d_in[9];
    const float* bagg = (const float*)d_in[10];
    const int* ar0 = (const int*)d_in[11];
    const int* ac0 = (const int*)d_in[12];
    const int* ar1 = (const int*)d_in[13];
    const int* ac1 = (const int*)d_in[14];
    const int* ar2 = (const int*)d_in[15];
    const int* ac2 = (const int*)d_in[16];
    float* out = (float*)d_out;

    const int N0 = in_sizes[0] / D;
    const int N1 = in_sizes[1] / D;
    const int N2 = in_sizes[2] / D;
    const int E0 = in_sizes[11];
    const int E1 = in_sizes[13];
    const int E2 = in_sizes[15];

    float *pg0, *pg1, *pg2, *pa10, *pa20, *pa21, *pa22;
    int *pcnt, *poff, *pcur, *ps0, *ps1, *ps2;
    cudaGetSymbolAddress((void**)&pg0, g_g0);
    cudaGetSymbolAddress((void**)&pg1, g_g1);
    cudaGetSymbolAddress((void**)&pg2, g_g2);
    cudaGetSymbolAddress((void**)&pa10, g_a1_0);
    cudaGetSymbolAddress((void**)&pa20, g_a2_0);
    cudaGetSymbolAddress((void**)&pa21, g_a2_1);
    cudaGetSymbolAddress((void**)&pa22, g_a2_2);
    cudaGetSymbolAddress((void**)&pcnt, g_cnt);
    cudaGetSymbolAddress((void**)&poff, g_off);
    cudaGetSymbolAddress((void**)&pcur, g_cur);
    cudaGetSymbolAddress((void**)&ps0, g_sc0);
    cudaGetSymbolAddress((void**)&ps1, g_sc1);
    cudaGetSymbolAddress((void**)&ps2, g_sc2);

    int* c0p = pcnt;
    int* c1p = pcnt + (N0MAX + 1);
    int* c2p = pcnt + 2 * (N0MAX + 1);
    int* o0p = poff;
    int* o1p = poff + (N0MAX + 1);
    int* o2p = poff + 2 * (N0MAX + 1);
    int* u0p = pcur;
    int* u1p = pcur + N0MAX;
    int* u2p = pcur + 2 * N0MAX;

    const int smem_bytes = 3 * 16384 * (int)sizeof(float);  // 192KB
    cudaFuncSetAttribute(node_kernel, cudaFuncAttributeMaxDynamicSharedMemorySize, smem_bytes);

    // --- binning chain (independent of node outputs) ---
    const int ZN = 3 * (N0MAX + 1);
    zero_kernel<<<(ZN + 255) / 256, 256>>>(pcnt, ZN);
    const int ET = E0 + E1 + E2;
    hist3_kernel<<<(ET + 255) / 256, 256>>>(ar0, E0, ar1, E1, ar2, E2, c0p, c1p, c2p);
    scan3_kernel<<<1, 1024>>>(c0p, c1p, c2p, N0, o0p, u0p, o1p, u1p, o2p, u2p);
    scat3_kernel<<<(ET + 255) / 256, 256>>>(ar0, ac0, E0, ar1, ac1, E1, ar2, ac2, E2,
                                            u0p, u1p, u2p, ps0, ps1, ps2);

    // --- node kernels ---
    node_kernel<<<(N0 + 127) / 128, NTHREADS, smem_bytes>>>(
        x0, N0, W1, b1, a1w, a1b, a2w, a2b,
        Wagg + 1 * D * D, Wagg + 0 * D * D, bagg,
        pg0, pa10, pa20, out);
    node_kernel<<<(N1 + 127) / 128, NTHREADS, smem_bytes>>>(
        x1, N1, W1, b1, a1w, a1b, a2w, a2b,
        Wagg + 2 * D * D, nullptr, bagg,
        pg1, nullptr, pa21, nullptr);
    node_kernel<<<(N2 + 127) / 128, NTHREADS, smem_bytes>>>(
        x2, N2, W1, b1, a1w, a1b, a2w, a2b,
        Wagg + 3 * D * D, nullptr, bagg,
        pg2, nullptr, pa22, nullptr);

    // --- aggregate: one warp per row, all three lists, single RMW of out ---
    agg_kernel<<<(N0 + 7) / 8, 256>>>(o0p, ps0, pg0, pa20,
                                      o1p, ps1, pg1, pa21,
                                      o2p, ps2, pg2, pa22,
                                      pa10, out, N0);
}

// round 3
// speedup vs baseline: 1.5248x; 1.2641x over previous
#include <cuda_runtime.h>
#include <cuda_fp16.h>
#include <cstdint>

#define D 128
#define N0MAX 100000
#define NALL  (100000 + 150000 + 80000)
#define EALL  3000000
#define NTHREADS 256

typedef unsigned long long ull;

// ---------------- static scratch (allocation-free rule) ----------------
__device__ __half g_gall[(size_t)NALL * 128];   // fp16 projected features, concat [g0|g1|g2]
__device__ float g_a2all[NALL];                 // concat [a2_0|a2_1|a2_2]
__device__ float g_a1_0[N0MAX];
// combined CSR scratch
__device__ int g_cnt[N0MAX + 1];
__device__ int g_off[N0MAX + 1];
__device__ int g_cur[N0MAX];
__device__ int g_scols[EALL];

// ---------------- f32x2 packed helpers ----------------
__device__ __forceinline__ ull splat2(float x) {
    ull r;
    asm("mov.b64 %0, {%1, %1};" : "=l"(r) : "f"(x));
    return r;
}
__device__ __forceinline__ ull fma2(ull a, ull b, ull c) {
    ull d;
    asm("fma.rn.f32x2 %0, %1, %2, %3;" : "=l"(d) : "l"(a), "l"(b), "l"(c));
    return d;
}
__device__ __forceinline__ void unpack2(ull v, float& lo, float& hi) {
    asm("mov.b64 {%0, %1}, %2;" : "=f"(lo), "=f"(hi) : "l"(v));
}

// ---------------- 128x128 GEMM core ----------------
// sA: row-major 128x128, row-swizzled (k XORed by 16 when row bit3 set)
// sW: 128x128 with half-split column perm (see stage_w)
// Thread (tx,ty): rows r0=ty*8..+7, cols c0=tx*8..+7. acc as f32x2 pairs.
__device__ __forceinline__ void mm128(const float* __restrict__ sA,
                                      const float* __restrict__ sW,
                                      int r0, int tx, int xsw,
                                      ull acc[8][4]) {
#pragma unroll
    for (int i = 0; i < 8; i++)
#pragma unroll
        for (int j = 0; j < 4; j++) acc[i][j] = 0ULL;

    const float* a0 = sA + r0 * D;
#pragma unroll 4
    for (int k = 0; k < D; k++) {
        const int kx = k ^ xsw;
        ull xs[8];
#pragma unroll
        for (int i = 0; i < 8; i++) xs[i] = splat2(a0[i * D + kx]);
        ulonglong2 wa = *(const ulonglong2*)(sW + k * D + tx * 4);
        ulonglong2 wb = *(const ulonglong2*)(sW + k * D + 64 + tx * 4);
#pragma unroll
        for (int i = 0; i < 8; i++) {
            acc[i][0] = fma2(xs[i], wa.x, acc[i][0]);
            acc[i][1] = fma2(xs[i], wa.y, acc[i][1]);
            acc[i][2] = fma2(xs[i], wb.x, acc[i][2]);
            acc[i][3] = fma2(xs[i], wb.y, acc[i][3]);
        }
    }
}

// Stage 128x128 weights with half-split column perm:
// src float4 index f (k=f>>5, c4=f&31) -> dst k*32 + ((c4&1)<<4) + (c4>>1)
__device__ __forceinline__ void stage_w(const float* __restrict__ W, float* __restrict__ sW,
                                        int tid) {
    const float4* src = (const float4*)W;
    float4* dst = (float4*)sW;
#pragma unroll
    for (int i = 0; i < 16; i++) {
        int f = tid + i * 256;
        int k = f >> 5, c4 = f & 31;
        dst[k * 32 + ((c4 & 1) << 4) + (c4 >> 1)] = src[f];
    }
}

// ---------------- node kernel ----------------
__global__ __launch_bounds__(NTHREADS, 1)
void node_kernel(const float* __restrict__ x, int nrows,
                 const float* __restrict__ W1, const float* __restrict__ b1,
                 const float* __restrict__ a1w, const float* __restrict__ a1bp,
                 const float* __restrict__ a2w, const float* __restrict__ a2bp,
                 const float* __restrict__ Wg,
                 const float* __restrict__ Wself,
                 const float* __restrict__ bagg,
                 __half* __restrict__ gout,
                 float* __restrict__ a1out,
                 float* __restrict__ a2out,
                 float* __restrict__ selfout) {
    extern __shared__ float smem[];
    float* sW = smem;            // 16384 floats (64KB)
    float* sX = smem + 16384;    // 16384 floats (64KB), row-swizzled x tile
    float* sH = smem + 32768;    // 16384 floats (64KB), row-swizzled h tile

    const int tid = threadIdx.x;
    const int tx = tid & 15;
    const int ty = tid >> 4;
    const int c0 = tx * 8;
    const int r0 = ty * 8;
    const int xsw = (ty & 1) << 4;
    const int rbase = blockIdx.x * 128;

    stage_w(W1, sW, tid);

    float bb[8], aw1[8], aw2[8], bg[8];
#pragma unroll
    for (int j = 0; j < 8; j++) {
        bb[j] = b1[c0 + j];
        aw1[j] = a1w[c0 + j];
        aw2[j] = a2w[c0 + j];
        bg[j] = bagg[c0 + j];
    }
    const float a1b = *a1bp;
    const float a2b = *a2bp;

    // stage x: 128 rows, row-swizzled
    {
#pragma unroll
        for (int i = 0; i < 16; i++) {
            int f = tid + i * 256;
            int row = f >> 5, c4 = f & 31;
            float4 v = make_float4(0.f, 0.f, 0.f, 0.f);
            if (rbase + row < nrows) v = ((const float4*)(x + (size_t)(rbase + row) * D))[c4];
            ((float4*)sX)[row * 32 + (c4 ^ ((row & 8) >> 1))] = v;
        }
    }
    __syncthreads();

    ull acc[8][4];

    // ---- phase 1: h = relu(x @ W1 + b1); a1/a2; h -> sH ----
    mm128(sX, sW, r0, tx, xsw, acc);
#pragma unroll
    for (int i = 0; i < 8; i++) {
        float h[8];
#pragma unroll
        for (int j = 0; j < 4; j++) unpack2(acc[i][j], h[2 * j], h[2 * j + 1]);
        float pa1 = 0.f, pa2 = 0.f;
#pragma unroll
        for (int j = 0; j < 8; j++) {
            h[j] = fmaxf(h[j] + bb[j], 0.f);
            pa1 += h[j] * aw1[j];
            pa2 += h[j] * aw2[j];
        }
        const int row = r0 + i;
        const int c4s = (row & 8) >> 1;
        float4* hp = (float4*)sH + row * 32;
        hp[(tx * 2) ^ c4s]     = make_float4(h[0], h[1], h[2], h[3]);
        hp[(tx * 2 + 1) ^ c4s] = make_float4(h[4], h[5], h[6], h[7]);
#pragma unroll
        for (int off = 8; off >= 1; off >>= 1) {
            pa1 += __shfl_down_sync(0xffffffffu, pa1, off);
            pa2 += __shfl_down_sync(0xffffffffu, pa2, off);
        }
        const int grow = rbase + row;
        if (tx == 0 && grow < nrows) {
            if (a1out) a1out[grow] = pa1 + a1b;
            a2out[grow] = pa2 + a2b;
        }
    }
    __syncthreads();

    // ---- phase 2: g = h @ Wg -> fp16 ----
    stage_w(Wg, sW, tid);
    __syncthreads();
    mm128(sH, sW, r0, tx, xsw, acc);
#pragma unroll
    for (int i = 0; i < 8; i++) {
        const int grow = rbase + r0 + i;
        if (grow < nrows) {
            float v[8];
#pragma unroll
            for (int j = 0; j < 4; j++) unpack2(acc[i][j], v[2 * j], v[2 * j + 1]);
            __half2 h0 = __floats2half2_rn(v[0], v[1]);
            __half2 h1 = __floats2half2_rn(v[2], v[3]);
            __half2 h2 = __floats2half2_rn(v[4], v[5]);
            __half2 h3 = __floats2half2_rn(v[6], v[7]);
            uint4 pk;
            pk.x = *(unsigned*)&h0;
            pk.y = *(unsigned*)&h1;
            pk.z = *(unsigned*)&h2;
            pk.w = *(unsigned*)&h3;
            *(uint4*)(gout + (size_t)grow * D + c0) = pk;
        }
    }

    // ---- phase 3 (x0 only): selfout = h @ Wself + bagg ----
    if (selfout) {
        __syncthreads();
        stage_w(Wself, sW, tid);
        __syncthreads();
        mm128(sH, sW, r0, tx, xsw, acc);
#pragma unroll
        for (int i = 0; i < 8; i++) {
            const int grow = rbase + r0 + i;
            if (grow < nrows) {
                float v[8];
#pragma unroll
                for (int j = 0; j < 4; j++) unpack2(acc[i][j], v[2 * j], v[2 * j + 1]);
#pragma unroll
                for (int j = 0; j < 8; j++) v[j] += bg[j];
                float4* op = (float4*)(selfout + (size_t)grow * D + c0);
                op[0] = make_float4(v[0], v[1], v[2], v[3]);
                op[1] = make_float4(v[4], v[5], v[6], v[7]);
            }
        }
    }
}

// ---------------- binning kernels (combined CSR over all 3 lists) ----------------
__global__ void zero_kernel(int* p, int n) {
    int i = blockIdx.x * blockDim.x + threadIdx.x;
    if (i < n) p[i] = 0;
}

__global__ void hist_kernel(const int* __restrict__ r0, int E0,
                            const int* __restrict__ r1, int E1,
                            const int* __restrict__ r2, int E2,
                            int* __restrict__ cnt) {
    int t = blockIdx.x * blockDim.x + threadIdx.x;
    int row;
    if (t < E0) row = __ldg(r0 + t);
    else if ((t -= E0) < E1) row = __ldg(r1 + t);
    else if ((t -= E1) < E2) row = __ldg(r2 + t);
    else return;
    atomicAdd(&cnt[row], 1);
}

__global__ void scan_kernel(const int* __restrict__ cnt, int n,
                            int* __restrict__ offs, int* __restrict__ cur) {
    __shared__ int wsum[32];
    __shared__ int s_carry;
    const int tid = threadIdx.x, lane = tid & 31, wid = tid >> 5;
    if (tid == 0) s_carry = 0;
    __syncthreads();
    for (int base = 0; base < n; base += 4096) {
        int idx = base + tid * 4;
        int v[4];
#pragma unroll
        for (int j = 0; j < 4; j++) v[j] = (idx + j < n) ? cnt[idx + j] : 0;
        int tsum = v[0] + v[1] + v[2] + v[3];
        int xv = tsum;
#pragma unroll
        for (int off = 1; off < 32; off <<= 1) {
            int t = __shfl_up_sync(0xffffffffu, xv, off);
            if (lane >= off) xv += t;
        }
        if (lane == 31) wsum[wid] = xv;
        __syncthreads();
        if (wid == 0) {
            int y = wsum[lane];
#pragma unroll
            for (int off = 1; off < 32; off <<= 1) {
                int t = __shfl_up_sync(0xffffffffu, y, off);
                if (lane >= off) y += t;
            }
            wsum[lane] = y;
        }
        __syncthreads();
        int warpoff = (wid == 0) ? 0 : wsum[wid - 1];
        int carry = s_carry;
        int excl = carry + warpoff + xv - tsum;
#pragma unroll
        for (int j = 0; j < 4; j++) {
            if (idx + j < n) { offs[idx + j] = excl; cur[idx + j] = excl; }
            excl += v[j];
        }
        __syncthreads();
        if (tid == 0) s_carry = carry + wsum[31];
        __syncthreads();
    }
    if (tid == 0) offs[n] = s_carry;
}

__global__ void scat_kernel(const int* __restrict__ r0, const int* __restrict__ c0, int E0,
                            const int* __restrict__ r1, const int* __restrict__ c1, int E1,
                            const int* __restrict__ r2, const int* __restrict__ c2, int E2,
                            int base1, int base2,
                            int* __restrict__ cur, int* __restrict__ scols) {
    int t = blockIdx.x * blockDim.x + threadIdx.x;
    int row, col;
    if (t < E0) { row = __ldg(r0 + t); col = __ldg(c0 + t); }
    else if ((t -= E0) < E1) { row = __ldg(r1 + t); col = __ldg(c1 + t) + base1; }
    else if ((t -= E1) < E2) { row = __ldg(r2 + t); col = __ldg(c2 + t) + base2; }
    else return;
    int p = atomicAdd(&cur[row], 1);
    scols[p] = col;
}

// ---------------- aggregate: one warp per output row ----------------
__device__ __forceinline__ void gacc(int c, float sv, int lane,
                                     const __half* __restrict__ g, float4& acc) {
    uint2 u = __ldg((const uint2*)(g + (size_t)c * D) + lane);
    __half2 p0 = *reinterpret_cast<__half2*>(&u.x);
    __half2 p1 = *reinterpret_cast<__half2*>(&u.y);
    float2 f0 = __half22float2(p0);
    float2 f1 = __half22float2(p1);
    acc.x += sv * f0.x;
    acc.y += sv * f0.y;
    acc.z += sv * f1.x;
    acc.w += sv * f1.y;
}

__global__ __launch_bounds__(256)
void agg_kernel(const int* __restrict__ offs, const int* __restrict__ scols,
                const __half* __restrict__ g, const float* __restrict__ a2,
                const float* __restrict__ a1, float* __restrict__ out, int n0) {
    int row = blockIdx.x * 8 + (threadIdx.x >> 5);
    if (row >= n0) return;
    int lane = threadIdx.x & 31;
    float va1 = __ldg(a1 + row);
    float4 acc = make_float4(0.f, 0.f, 0.f, 0.f);
    int s = __ldg(offs + row), e = __ldg(offs + row + 1);
    int i = s;
    for (; i + 2 <= e; i += 2) {
        int ca = __ldg(scols + i);
        int cb = __ldg(scols + i + 1);
        float sa = va1 + __ldg(a2 + ca);
        float sb = va1 + __ldg(a2 + cb);
        sa = 1.0f / (1.0f + __expf(-sa));
        sb = 1.0f / (1.0f + __expf(-sb));
        gacc(ca, sa, lane, g, acc);
        gacc(cb, sb, lane, g, acc);
    }
    if (i < e) {
        int ca = __ldg(scols + i);
        float sa = va1 + __ldg(a2 + ca);
        sa = 1.0f / (1.0f + __expf(-sa));
        gacc(ca, sa, lane, g, acc);
    }
    float4* op = (float4*)(out + (size_t)row * D) + lane;
    float4 c = *op;
    c.x += acc.x; c.y += acc.y; c.z += acc.z; c.w += acc.w;
    *op = c;
}

// ---------------- launch ----------------
extern "C" void kernel_launch(void* const* d_in, const int* in_sizes, int n_in,
                              void* d_out, int out_size) {
    const float* x0   = (const float*)d_in[0];
    const float* x1   = (const float*)d_in[1];
    const float* x2   = (const float*)d_in[2];
    const float* W1   = (const float*)d_in[3];
    const float* b1   = (const float*)d_in[4];
    const float* a1w  = (const float*)d_in[5];
    const float* a1b  = (const float*)d_in[6];
    const float* a2w  = (const float*)d_in[7];
    const float* a2b  = (const float*)d_in[8];
    const float* Wagg = (const float*)d_in[9];
    const float* bagg = (const float*)d_in[10];
    const int* ar0 = (const int*)d_in[11];
    const int* ac0 = (const int*)d_in[12];
    const int* ar1 = (const int*)d_in[13];
    const int* ac1 = (const int*)d_in[14];
    const int* ar2 = (const int*)d_in[15];
    const int* ac2 = (const int*)d_in[16];
    float* out = (float*)d_out;

    const int N0 = in_sizes[0] / D;
    const int N1 = in_sizes[1] / D;
    const int N2 = in_sizes[2] / D;
    const int E0 = in_sizes[11];
    const int E1 = in_sizes[13];
    const int E2 = in_sizes[15];

    __half* pg;
    float *pa2, *pa1;
    int *pcnt, *poff, *pcur, *pscols;
    cudaGetSymbolAddress((void**)&pg, g_gall);
    cudaGetSymbolAddress((void**)&pa2, g_a2all);
    cudaGetSymbolAddress((void**)&pa1, g_a1_0);
    cudaGetSymbolAddress((void**)&pcnt, g_cnt);
    cudaGetSymbolAddress((void**)&poff, g_off);
    cudaGetSymbolAddress((void**)&pcur, g_cur);
    cudaGetSymbolAddress((void**)&pscols, g_scols);

    const int smem_bytes = 3 * 16384 * (int)sizeof(float);  // 192KB
    cudaFuncSetAttribute(node_kernel, cudaFuncAttributeMaxDynamicSharedMemorySize, smem_bytes);

    // --- combined binning chain ---
    zero_kernel<<<(N0 + 256) / 256, 256>>>(pcnt, N0 + 1);
    const int ET = E0 + E1 + E2;
    hist_kernel<<<(ET + 255) / 256, 256>>>(ar0, E0, ar1, E1, ar2, E2, pcnt);
    scan_kernel<<<1, 1024>>>(pcnt, N0, poff, pcur);
    scat_kernel<<<(ET + 255) / 256, 256>>>(ar0, ac0, E0, ar1, ac1, E1, ar2, ac2, E2,
                                           N0, N0 + N1, pcur, pscols);

    // --- node kernels (g slices concatenated: [0:N0) [N0:N0+N1) [N0+N1:...) ) ---
    node_kernel<<<(N0 + 127) / 128, NTHREADS, smem_bytes>>>(
        x0, N0, W1, b1, a1w, a1b, a2w, a2b,
        Wagg + 1 * D * D, Wagg + 0 * D * D, bagg,
        pg, pa1, pa2, out);
    node_kernel<<<(N1 + 127) / 128, NTHREADS, smem_bytes>>>(
        x1, N1, W1, b1, a1w, a1b, a2w, a2b,
        Wagg + 2 * D * D, nullptr, bagg,
        pg + (size_t)N0 * D, nullptr, pa2 + N0, nullptr);
    node_kernel<<<(N2 + 127) / 128, NTHREADS, smem_bytes>>>(
        x2, N2, W1, b1, a1w, a1b, a2w, a2b,
        Wagg + 3 * D * D, nullptr, bagg,
        pg + (size_t)(N0 + N1) * D, nullptr, pa2 + N0 + N1, nullptr);

    // --- aggregate: one warp per row over the single combined CSR ---
    agg_kernel<<<(N0 + 7) / 8, 256>>>(poff, pscols, pg, pa2, pa1, out, N0);
}

// round 8
// speedup vs baseline: 2.1495x; 1.4097x over previous
#include <cuda_runtime.h>
#include <cuda_fp16.h>
#include <cstdint>

#define D 128
#define N0MAX 100000
#define NALL  (100000 + 150000 + 80000)
#define EALL  3000000

typedef unsigned long long ull;
typedef unsigned int u32;

// ---------------- static scratch (allocation-free rule) ----------------
__device__ __half g_gall[(size_t)NALL * 128];   // fp16 projected features, concat [g0|g1|g2]
__device__ float g_a2all[NALL];                 // concat [a2_0|a2_1|a2_2]
__device__ float g_a1_0[N0MAX];
// prepped weights: 5 matrices (W1, Wagg0..3) x {hi,lo} x 32KB fp16 tiles,
// transposed to [n][k], 16B-chunk XOR-swizzled (ldmatrix-ready, raw smem copy)
__device__ unsigned char g_wprep[5 * 2 * 32768];
// combined CSR scratch
__device__ int g_cnt[N0MAX + 1];
__device__ int g_off[N0MAX + 1];
__device__ int g_cur[N0MAX];
__device__ int g_scols[EALL];

__device__ __forceinline__ u32 smem_to_u32(const void* p) {
    u32 a;
    asm("{ .reg .u64 t; cvta.to.shared.u64 t, %1; cvt.u32.u64 %0, t; }" : "=r"(a) : "l"(p));
    return a;
}

// byte offset of 16B chunk (row, kc) in a 128x128 fp16 tile (256B rows),
// XOR swizzle on chunk index by row&7 -> conflict-free ldmatrix + staging
#define CH(row, kc) ((u32)((row) * 256 + ((((kc)) ^ ((row) & 7)) << 4)))

// split 8 fp32 -> fp16 hi + fp16 lo packed uint4 (16B each)
__device__ __forceinline__ void split8h(const float* v, uint4& hi, uint4& lo) {
    u32 hw[4], lw[4];
#pragma unroll
    for (int j = 0; j < 4; j++) {
        float a = v[2 * j], b = v[2 * j + 1];
        __half ah = __float2half_rn(a), bh = __float2half_rn(b);
        float ar = a - __half2float(ah), br = b - __half2float(bh);
        __half2 hh = __halves2half2(ah, bh);
        __half2 ll = __floats2half2_rn(ar, br);
        hw[j] = *(u32*)&hh;
        lw[j] = *(u32*)&ll;
    }
    hi = make_uint4(hw[0], hw[1], hw[2], hw[3]);
    lo = make_uint4(lw[0], lw[1], lw[2], lw[3]);
}

// ---------------- weight prep: transpose + fp16 split + swizzle ----------------
__global__ void prep_w(const float* __restrict__ W1, const float* __restrict__ Wagg,
                       unsigned char* __restrict__ wp) {
    int m = blockIdx.x, tid = threadIdx.x;
    unsigned char* hip = wp + (size_t)m * 2 * 32768;
    unsigned char* lop = hip + 32768;
#pragma unroll 1
    for (int it = 0; it < 8; it++) {
        int f = tid + it * 256;           // chunk id 0..2047
        int n = f >> 4, kc = f & 15, k0 = kc * 8;
        float v[8];
#pragma unroll
        for (int j = 0; j < 8; j++) {
            int k = k0 + j;
            v[j] = (m == 0) ? W1[k * 128 + n] : Wagg[((m - 1) * 128 + k) * 128 + n];
        }
        uint4 hi, lo;
        split8h(v, hi, lo);
        u32 ad = CH(n, kc);
        *(uint4*)(hip + ad) = hi;
        *(uint4*)(lop + ad) = lo;
    }
}

// ---------------- node kernel (mma.sync m16n8k16 fp16, 3-pass split) ----------
#define OFF_A_HI 0
#define OFF_A_LO 32768
#define OFF_W_HI 65536
#define OFF_W_LO 98304
#define OFF_HDR  131072
#define SMEM_REQ (131072 + 3072 + 1024)

__device__ __forceinline__ void copy32k(void* dst, const void* src, int tid) {
    const uint4* s = (const uint4*)src;
    uint4* d = (uint4*)dst;
#pragma unroll
    for (int i = 0; i < 8; i++) d[tid + i * 256] = s[tid + i * 256];
}

__device__ __forceinline__ void warp_gemm(u32 aHi, u32 aLo, u32 wHi, u32 wLo,
                                          int r0, int cbase, int lane,
                                          float c[2][8][4]) {
    const int q = lane >> 3, sr = lane & 7;
#pragma unroll
    for (int mt = 0; mt < 2; mt++)
#pragma unroll
        for (int nt = 0; nt < 8; nt++)
#pragma unroll
            for (int j = 0; j < 4; j++) c[mt][nt][j] = 0.f;

#pragma unroll 1
    for (int pass = 0; pass < 3; pass++) {
        const u32 Ab = (pass == 2) ? aLo : aHi;
        const u32 Bb = (pass == 1) ? wLo : wHi;
#pragma unroll 1
        for (int ks = 0; ks < 8; ks++) {
            u32 a[2][4];
#pragma unroll
            for (int mt = 0; mt < 2; mt++) {
                int row = r0 + mt * 16 + ((q & 1) << 3) + sr;
                int kc = 2 * ks + (q >> 1);
                u32 ad = Ab + CH(row, kc);
                asm volatile("ldmatrix.sync.aligned.m8n8.x4.shared.b16 {%0,%1,%2,%3}, [%4];"
                             : "=r"(a[mt][0]), "=r"(a[mt][1]), "=r"(a[mt][2]), "=r"(a[mt][3])
                             : "r"(ad));
            }
            u32 b[8][2];
#pragma unroll
            for (int nb = 0; nb < 4; nb++) {
                int rown = cbase + nb * 16 + ((q >> 1) << 3) + sr;
                int kc = 2 * ks + (q & 1);
                u32 ad = Bb + CH(rown, kc);
                asm volatile("ldmatrix.sync.aligned.m8n8.x4.shared.b16 {%0,%1,%2,%3}, [%4];"
                             : "=r"(b[2 * nb][0]), "=r"(b[2 * nb][1]),
                               "=r"(b[2 * nb + 1][0]), "=r"(b[2 * nb + 1][1])
                             : "r"(ad));
            }
#pragma unroll
            for (int mt = 0; mt < 2; mt++)
#pragma unroll
                for (int nt = 0; nt < 8; nt++)
                    asm volatile("mma.sync.aligned.m16n8k16.row.col.f32.f16.f16.f32 "
                                 "{%0,%1,%2,%3}, {%4,%5,%6,%7}, {%8,%9}, {%0,%1,%2,%3};"
                                 : "+f"(c[mt][nt][0]), "+f"(c[mt][nt][1]),
                                   "+f"(c[mt][nt][2]), "+f"(c[mt][nt][3])
                                 : "r"(a[mt][0]), "r"(a[mt][1]), "r"(a[mt][2]), "r"(a[mt][3]),
                                   "r"(b[nt][0]), "r"(b[nt][1]));
        }
    }
}

__global__ __launch_bounds__(256, 1)
void node_mm(const float* __restrict__ x, int nrows,
             const unsigned char* __restrict__ w1h, const unsigned char* __restrict__ w1l,
             const unsigned char* __restrict__ wgh, const unsigned char* __restrict__ wgl,
             const unsigned char* __restrict__ wsh, const unsigned char* __restrict__ wsl,
             const float* __restrict__ b1,
             const float* __restrict__ a1w, const float* __restrict__ a1bp,
             const float* __restrict__ a2w, const float* __restrict__ a2bp,
             const float* __restrict__ bagg,
             __half* __restrict__ gout, float* __restrict__ a1out,
             float* __restrict__ a2out, float* __restrict__ selfout) {
    extern __shared__ char sraw[];
    const u32 sb = smem_to_u32(sraw);
    const u32 base = (sb + 1023u) & ~1023u;
    char* bp = sraw + (base - sb);
    float* sBB  = (float*)(bp + OFF_HDR);
    float* sAW1 = sBB + 128;
    float* sAW2 = sAW1 + 128;
    float* sBG  = sAW2 + 128;
    float* sPA1 = sBG + 128;
    float* sPA2 = sPA1 + 128;

    const int tid = threadIdx.x, wid = tid >> 5, lane = tid & 31;
    const int wm = wid & 3, wn = wid >> 2;
    const int r0 = wm * 32, cbase = wn * 64;
    const int rbase = blockIdx.x * 128;
    const u32 aHi = base + OFF_A_HI, aLo = base + OFF_A_LO;
    const u32 wHi = base + OFF_W_HI, wLo = base + OFF_W_LO;

    if (tid < 128) {
        sBB[tid] = b1[tid];
        sAW1[tid] = a1w[tid];
        sAW2[tid] = a2w[tid];
        sBG[tid] = bagg[tid];
    }
    copy32k(bp + OFF_W_HI, w1h, tid);
    copy32k(bp + OFF_W_LO, w1l, tid);
#pragma unroll 1
    for (int it = 0; it < 8; it++) {
        int f = tid + it * 256;
        int row = f >> 4, kc = f & 15;
        float v[8];
        if (rbase + row < nrows) {
            const float4* xp = (const float4*)(x + (size_t)(rbase + row) * 128 + kc * 8);
            float4 p0 = xp[0], p1 = xp[1];
            v[0] = p0.x; v[1] = p0.y; v[2] = p0.z; v[3] = p0.w;
            v[4] = p1.x; v[5] = p1.y; v[6] = p1.z; v[7] = p1.w;
        } else {
#pragma unroll
            for (int j = 0; j < 8; j++) v[j] = 0.f;
        }
        uint4 hi, lo;
        split8h(v, hi, lo);
        u32 ad = CH(row, kc);
        *(uint4*)(bp + OFF_A_HI + ad) = hi;
        *(uint4*)(bp + OFF_A_LO + ad) = lo;
    }
    __syncthreads();

    float c[2][8][4];
    float pph1[4], pph2[4];

    // ---- GEMM1: h = x @ W1^T ----
    warp_gemm(aHi, aLo, wHi, wLo, r0, cbase, lane, c);
    __syncthreads();   // all warps done reading sA(x), sW(W1)

    // epilogue 1: bias+relu, attention dots, h -> sA fp16 hi/lo
#pragma unroll
    for (int mt = 0; mt < 2; mt++)
#pragma unroll
        for (int half = 0; half < 2; half++) {
            int row = r0 + mt * 16 + half * 8 + (lane >> 2);
            float ph1 = 0.f, ph2 = 0.f;
#pragma unroll
            for (int nt = 0; nt < 8; nt++) {
                int col = cbase + nt * 8 + 2 * (lane & 3);
                float h0 = fmaxf(c[mt][nt][half * 2 + 0] + sBB[col], 0.f);
                float h1 = fmaxf(c[mt][nt][half * 2 + 1] + sBB[col + 1], 0.f);
                ph1 += h0 * sAW1[col] + h1 * sAW1[col + 1];
                ph2 += h0 * sAW2[col] + h1 * sAW2[col + 1];
                __half hh0 = __float2half_rn(h0), hh1 = __float2half_rn(h1);
                __half2 hhi = __halves2half2(hh0, hh1);
                __half2 hlo = __floats2half2_rn(h0 - __half2float(hh0),
                                                h1 - __half2float(hh1));
                u32 ao = (u32)(row * 256 + (((col >> 3) ^ (row & 7)) << 4) + (col & 7) * 2);
                *(u32*)(bp + OFF_A_HI + ao) = *(u32*)&hhi;
                *(u32*)(bp + OFF_A_LO + ao) = *(u32*)&hlo;
            }
            ph1 += __shfl_xor_sync(0xffffffffu, ph1, 1);
            ph1 += __shfl_xor_sync(0xffffffffu, ph1, 2);
            ph2 += __shfl_xor_sync(0xffffffffu, ph2, 1);
            ph2 += __shfl_xor_sync(0xffffffffu, ph2, 2);
            pph1[mt * 2 + half] = ph1;
            pph2[mt * 2 + half] = ph2;
            if (wn == 0 && (lane & 3) == 0) {
                sPA1[row] = ph1;
                sPA2[row] = ph2;
            }
        }
    copy32k(bp + OFF_W_HI, wgh, tid);   // stage Wg (safe: post-GEMM1 barrier above)
    copy32k(bp + OFF_W_LO, wgl, tid);
    __syncthreads();
    if (wn == 1 && (lane & 3) == 0) {
        const float a1b = *a1bp, a2b = *a2bp;
#pragma unroll
        for (int mt = 0; mt < 2; mt++)
#pragma unroll
            for (int half = 0; half < 2; half++) {
                int row = r0 + mt * 16 + half * 8 + (lane >> 2);
                int grow = rbase + row;
                if (grow < nrows) {
                    if (a1out) a1out[grow] = sPA1[row] + pph1[mt * 2 + half] + a1b;
                    a2out[grow] = sPA2[row] + pph2[mt * 2 + half] + a2b;
                }
            }
    }

    // ---- GEMM2: g = h @ Wg^T -> fp16 global ----
    warp_gemm(aHi, aLo, wHi, wLo, r0, cbase, lane, c);
#pragma unroll
    for (int mt = 0; mt < 2; mt++)
#pragma unroll
        for (int half = 0; half < 2; half++) {
            int row = r0 + mt * 16 + half * 8 + (lane >> 2);
            int grow = rbase + row;
            if (grow < nrows) {
#pragma unroll
                for (int nt = 0; nt < 8; nt++) {
                    int col = cbase + nt * 8 + 2 * (lane & 3);
                    __half2 hv = __floats2half2_rn(c[mt][nt][half * 2 + 0],
                                                   c[mt][nt][half * 2 + 1]);
                    *(u32*)(gout + (size_t)grow * D + col) = *(u32*)&hv;
                }
            }
        }

    // ---- GEMM3 (x0 only): self = h @ Wself^T + bagg -> out ----
    if (wsh) {
        __syncthreads();   // all warps done reading sW(Wg)
        copy32k(bp + OFF_W_HI, wsh, tid);
        copy32k(bp + OFF_W_LO, wsl, tid);
        __syncthreads();
        warp_gemm(aHi, aLo, wHi, wLo, r0, cbase, lane, c);
#pragma unroll
        for (int mt = 0; mt < 2; mt++)
#pragma unroll
            for (int half = 0; half < 2; half++) {
                int row = r0 + mt * 16 + half * 8 + (lane >> 2);
                int grow = rbase + row;
                if (grow < nrows) {
#pragma unroll
                    for (int nt = 0; nt < 8; nt++) {
                        int col = cbase + nt * 8 + 2 * (lane & 3);
                        float2 v = make_float2(c[mt][nt][half * 2 + 0] + sBG[col],
                                               c[mt][nt][half * 2 + 1] + sBG[col + 1]);
                        *(float2*)(selfout + (size_t)grow * D + col) = v;
                    }
                }
            }
    }
}

// ---------------- binning kernels (combined CSR over all 3 lists) ----------------
__global__ void zero_kernel(int* p, int n) {
    int i = blockIdx.x * blockDim.x + threadIdx.x;
    if (i < n) p[i] = 0;
}

__global__ void hist_kernel(const int* __restrict__ r0, int E0,
                            const int* __restrict__ r1, int E1,
                            const int* __restrict__ r2, int E2,
                            int* __restrict__ cnt) {
    int t = blockIdx.x * blockDim.x + threadIdx.x;
    int row;
    if (t < E0) row = __ldg(r0 + t);
    else if ((t -= E0) < E1) row = __ldg(r1 + t);
    else if ((t -= E1) < E2) row = __ldg(r2 + t);
    else return;
    atomicAdd(&cnt[row], 1);
}

__global__ void scan_kernel(const int* __restrict__ cnt, int n,
                            int* __restrict__ offs, int* __restrict__ cur) {
    __shared__ int wsum[32];
    __shared__ int s_carry;
    const int tid = threadIdx.x, lane = tid & 31, wid = tid >> 5;
    if (tid == 0) s_carry = 0;
    __syncthreads();
    for (int base = 0; base < n; base += 4096) {
        int idx = base + tid * 4;
        int v[4];
#pragma unroll
        for (int j = 0; j < 4; j++) v[j] = (idx + j < n) ? cnt[idx + j] : 0;
        int tsum = v[0] + v[1] + v[2] + v[3];
        int xv = tsum;
#pragma unroll
        for (int off = 1; off < 32; off <<= 1) {
            int t = __shfl_up_sync(0xffffffffu, xv, off);
            if (lane >= off) xv += t;
        }
        if (lane == 31) wsum[wid] = xv;
        __syncthreads();
        if (wid == 0) {
            int y = wsum[lane];
#pragma unroll
            for (int off = 1; off < 32; off <<= 1) {
                int t = __shfl_up_sync(0xffffffffu, y, off);
                if (lane >= off) y += t;
            }
            wsum[lane] = y;
        }
        __syncthreads();
        int warpoff = (wid == 0) ? 0 : wsum[wid - 1];
        int carry = s_carry;
        int excl = carry + warpoff + xv - tsum;
#pragma unroll
        for (int j = 0; j < 4; j++) {
            if (idx + j < n) { offs[idx + j] = excl; cur[idx + j] = excl; }
            excl += v[j];
        }
        __syncthreads();
        if (tid == 0) s_carry = carry + wsum[31];
        __syncthreads();
    }
    if (tid == 0) offs[n] = s_carry;
}

__global__ void scat_kernel(const int* __restrict__ r0, const int* __restrict__ c0, int E0,
                            const int* __restrict__ r1, const int* __restrict__ c1, int E1,
                            const int* __restrict__ r2, const int* __restrict__ c2, int E2,
                            int base1, int base2,
                            int* __restrict__ cur, int* __restrict__ scols) {
    int t = blockIdx.x * blockDim.x + threadIdx.x;
    int row, col;
    if (t < E0) { row = __ldg(r0 + t); col = __ldg(c0 + t); }
    else if ((t -= E0) < E1) { row = __ldg(r1 + t); col = __ldg(c1 + t) + base1; }
    else if ((t -= E1) < E2) { row = __ldg(r2 + t); col = __ldg(c2 + t) + base2; }
    else return;
    int p = atomicAdd(&cur[row], 1);
    scols[p] = col;
}

// ---------------- aggregate: one warp per output row ----------------
__device__ __forceinline__ void gacc(int c, float sv, int lane,
                                     const __half* __restrict__ g, float4& acc) {
    uint2 u = __ldg((const uint2*)(g + (size_t)c * D) + lane);
    __half2 p0 = *reinterpret_cast<__half2*>(&u.x);
    __half2 p1 = *reinterpret_cast<__half2*>(&u.y);
    float2 f0 = __half22float2(p0);
    float2 f1 = __half22float2(p1);
    acc.x += sv * f0.x;
    acc.y += sv * f0.y;
    acc.z += sv * f1.x;
    acc.w += sv * f1.y;
}

__global__ __launch_bounds__(256)
void agg_kernel(const int* __restrict__ offs, const int* __restrict__ scols,
                const __half* __restrict__ g, const float* __restrict__ a2,
                const float* __restrict__ a1, float* __restrict__ out, int n0) {
    int row = blockIdx.x * 8 + (threadIdx.x >> 5);
    if (row >= n0) return;
    int lane = threadIdx.x & 31;
    float va1 = __ldg(a1 + row);
    float4 acc = make_float4(0.f, 0.f, 0.f, 0.f);
    int s = __ldg(offs + row), e = __ldg(offs + row + 1);
    int i = s;
    for (; i + 2 <= e; i += 2) {
        int ca = __ldg(scols + i);
        int cb = __ldg(scols + i + 1);
        float sa = va1 + __ldg(a2 + ca);
        float sb = va1 + __ldg(a2 + cb);
        sa = 1.0f / (1.0f + __expf(-sa));
        sb = 1.0f / (1.0f + __expf(-sb));
        gacc(ca, sa, lane, g, acc);
        gacc(cb, sb, lane, g, acc);
    }
    if (i < e) {
        int ca = __ldg(scols + i);
        float sa = va1 + __ldg(a2 + ca);
        sa = 1.0f / (1.0f + __expf(-sa));
        gacc(ca, sa, lane, g, acc);
    }
    float4* op = (float4*)(out + (size_t)row * D) + lane;
    float4 c = *op;
    c.x += acc.x; c.y += acc.y; c.z += acc.z; c.w += acc.w;
    *op = c;
}

// ---------------- launch ----------------
extern "C" void kernel_launch(void* const* d_in, const int* in_sizes, int n_in,
                              void* d_out, int out_size) {
    const float* x0   = (const float*)d_in[0];
    const float* x1   = (const float*)d_in[1];
    const float* x2   = (const float*)d_in[2];
    const float* W1   = (const float*)d_in[3];
    const float* b1   = (const float*)d_in[4];
    const float* a1w  = (const float*)d_in[5];
    const float* a1b  = (const float*)d_in[6];
    const float* a2w  = (const float*)d_in[7];
    const float* a2b  = (const float*)d_in[8];
    const float* Wagg = (const float*)d_in[9];
    const float* bagg = (const float*)d_in[10];
    const int* ar0 = (const int*)d_in[11];
    const int* ac0 = (const int*)d_in[12];
    const int* ar1 = (const int*)d_in[13];
    const int* ac1 = (const int*)d_in[14];
    const int* ar2 = (const int*)d_in[15];
    const int* ac2 = (const int*)d_in[16];
    float* out = (float*)d_out;

    const int N0 = in_sizes[0] / D;
    const int N1 = in_sizes[1] / D;
    const int N2 = in_sizes[2] / D;
    const int E0 = in_sizes[11];
    const int E1 = in_sizes[13];
    const int E2 = in_sizes[15];

    __half* pg;
    float *pa2, *pa1;
    int *pcnt, *poff, *pcur, *pscols;
    unsigned char* pwp;
    cudaGetSymbolAddress((void**)&pg, g_gall);
    cudaGetSymbolAddress((void**)&pa2, g_a2all);
    cudaGetSymbolAddress((void**)&pa1, g_a1_0);
    cudaGetSymbolAddress((void**)&pcnt, g_cnt);
    cudaGetSymbolAddress((void**)&poff, g_off);
    cudaGetSymbolAddress((void**)&pcur, g_cur);
    cudaGetSymbolAddress((void**)&pscols, g_scols);
    cudaGetSymbolAddress((void**)&pwp, g_wprep);

    cudaFuncSetAttribute(node_mm, cudaFuncAttributeMaxDynamicSharedMemorySize, SMEM_REQ);

    #define WHI(m) (pwp + (size_t)(m) * 2 * 32768)
    #define WLO(m) (pwp + (size_t)(m) * 2 * 32768 + 32768)

    prep_w<<<5, 256>>>(W1, Wagg, pwp);
    zero_kernel<<<(N0 + 256) / 256, 256>>>(pcnt, N0 + 1);
    const int ET = E0 + E1 + E2;
    hist_kernel<<<(ET + 255) / 256, 256>>>(ar0, E0, ar1, E1, ar2, E2, pcnt);
    scan_kernel<<<1, 1024>>>(pcnt, N0, poff, pcur);
    scat_kernel<<<(ET + 255) / 256, 256>>>(ar0, ac0, E0, ar1, ac1, E1, ar2, ac2, E2,
                                           N0, N0 + N1, pcur, pscols);

    node_mm<<<(N0 + 127) / 128, 256, SMEM_REQ>>>(
        x0, N0, WHI(0), WLO(0), WHI(2), WLO(2), WHI(1), WLO(1),
        b1, a1w, a1b, a2w, a2b, bagg,
        pg, pa1, pa2, out);
    node_mm<<<(N1 + 127) / 128, 256, SMEM_REQ>>>(
        x1, N1, WHI(0), WLO(0), WHI(3), WLO(3), nullptr, nullptr,
        b1, a1w, a1b, a2w, a2b, bagg,
        pg + (size_t)N0 * D, nullptr, pa2 + N0, nullptr);
    node_mm<<<(N2 + 127) / 128, 256, SMEM_REQ>>>(
        x2, N2, WHI(0), WLO(0), WHI(4), WLO(4), nullptr, nullptr,
        b1, a1w, a1b, a2w, a2b, bagg,
        pg + (size_t)(N0 + N1) * D, nullptr, pa2 + N0 + N1, nullptr);

    agg_kernel<<<(N0 + 7) / 8, 256>>>(poff, pscols, pg, pa2, pa1, out, N0);
}

// round 9
// speedup vs baseline: 2.3746x; 1.1047x over previous
#include <cuda_runtime.h>
#include <cuda_fp16.h>
#include <cstdint>

#define D 128
#define N0MAX 100000
#define NALL  (100000 + 150000 + 80000)
#define EALL  3000000
#define SCAN_CHUNK 4096
#define SCAN_BLOCKS ((N0MAX + SCAN_CHUNK - 1) / SCAN_CHUNK)

typedef unsigned long long ull;
typedef unsigned int u32;

// ---------------- static scratch (allocation-free rule) ----------------
__device__ __half g_gall[(size_t)NALL * 128];   // fp16 projected features, concat [g0|g1|g2]
__device__ float g_a2all[NALL];                 // concat [a2_0|a2_1|a2_2]
__device__ float g_a1_0[N0MAX];
// prepped weights: 5 matrices (W1, Wagg0..3) x {hi,lo} x 32KB fp16 tiles,
// transposed to [n][k], 16B-chunk XOR-swizzled (ldmatrix-ready, raw smem copy)
__device__ unsigned char g_wprep[5 * 2 * 32768];
// combined CSR scratch
__device__ int g_cnt[N0MAX + 1];
__device__ int g_off[N0MAX + 1];
__device__ int g_cur[N0MAX];
__device__ int g_scols[EALL];
__device__ int g_bsum[SCAN_BLOCKS + 1];

__device__ __forceinline__ u32 smem_to_u32(const void* p) {
    u32 a;
    asm("{ .reg .u64 t; cvta.to.shared.u64 t, %1; cvt.u32.u64 %0, t; }" : "=r"(a) : "l"(p));
    return a;
}

// byte offset of 16B chunk (row, kc) in a 128x128 fp16 tile (256B rows),
// XOR swizzle on chunk index by row&7 -> conflict-free ldmatrix + staging
#define CH(row, kc) ((u32)((row) * 256 + ((((kc)) ^ ((row) & 7)) << 4)))

// split 8 fp32 -> fp16 hi + fp16 lo packed uint4 (16B each)
__device__ __forceinline__ void split8h(const float* v, uint4& hi, uint4& lo) {
    u32 hw[4], lw[4];
#pragma unroll
    for (int j = 0; j < 4; j++) {
        float a = v[2 * j], b = v[2 * j + 1];
        __half ah = __float2half_rn(a), bh = __float2half_rn(b);
        float ar = a - __half2float(ah), br = b - __half2float(bh);
        __half2 hh = __halves2half2(ah, bh);
        __half2 ll = __floats2half2_rn(ar, br);
        hw[j] = *(u32*)&hh;
        lw[j] = *(u32*)&ll;
    }
    hi = make_uint4(hw[0], hw[1], hw[2], hw[3]);
    lo = make_uint4(lw[0], lw[1], lw[2], lw[3]);
}

// ---------------- weight prep: transpose + fp16 split + swizzle ----------------
__global__ void prep_w(const float* __restrict__ W1, const float* __restrict__ Wagg,
                       unsigned char* __restrict__ wp) {
    int m = blockIdx.x, tid = threadIdx.x;
    unsigned char* hip = wp + (size_t)m * 2 * 32768;
    unsigned char* lop = hip + 32768;
#pragma unroll 1
    for (int it = 0; it < 8; it++) {
        int f = tid + it * 256;           // chunk id 0..2047
        int n = f >> 4, kc = f & 15, k0 = kc * 8;
        float v[8];
#pragma unroll
        for (int j = 0; j < 8; j++) {
            int k = k0 + j;
            v[j] = (m == 0) ? W1[k * 128 + n] : Wagg[((m - 1) * 128 + k) * 128 + n];
        }
        uint4 hi, lo;
        split8h(v, hi, lo);
        u32 ad = CH(n, kc);
        *(uint4*)(hip + ad) = hi;
        *(uint4*)(lop + ad) = lo;
    }
}

// ---------------- node kernel (mma.sync m16n8k16 fp16, 3-pass split) ----------
#define OFF_A_HI 0
#define OFF_A_LO 32768
#define OFF_W_HI 65536
#define OFF_W_LO 98304
#define OFF_HDR  131072
#define SMEM_REQ (131072 + 3072 + 1024)

__device__ __forceinline__ void copy32k(void* dst, const void* src, int tid) {
    const uint4* s = (const uint4*)src;
    uint4* d = (uint4*)dst;
#pragma unroll
    for (int i = 0; i < 8; i++) d[tid + i * 256] = s[tid + i * 256];
}

__device__ __forceinline__ void warp_gemm(u32 aHi, u32 aLo, u32 wHi, u32 wLo,
                                          int r0, int cbase, int lane,
                                          float c[2][8][4]) {
    const int q = lane >> 3, sr = lane & 7;
#pragma unroll
    for (int mt = 0; mt < 2; mt++)
#pragma unroll
        for (int nt = 0; nt < 8; nt++)
#pragma unroll
            for (int j = 0; j < 4; j++) c[mt][nt][j] = 0.f;

#pragma unroll 1
    for (int pass = 0; pass < 3; pass++) {
        const u32 Ab = (pass == 2) ? aLo : aHi;
        const u32 Bb = (pass == 1) ? wLo : wHi;
#pragma unroll 1
        for (int ks = 0; ks < 8; ks++) {
            u32 a[2][4];
#pragma unroll
            for (int mt = 0; mt < 2; mt++) {
                int row = r0 + mt * 16 + ((q & 1) << 3) + sr;
                int kc = 2 * ks + (q >> 1);
                u32 ad = Ab + CH(row, kc);
                asm volatile("ldmatrix.sync.aligned.m8n8.x4.shared.b16 {%0,%1,%2,%3}, [%4];"
                             : "=r"(a[mt][0]), "=r"(a[mt][1]), "=r"(a[mt][2]), "=r"(a[mt][3])
                             : "r"(ad));
            }
            u32 b[8][2];
#pragma unroll
            for (int nb = 0; nb < 4; nb++) {
                int rown = cbase + nb * 16 + ((q >> 1) << 3) + sr;
                int kc = 2 * ks + (q & 1);
                u32 ad = Bb + CH(rown, kc);
                asm volatile("ldmatrix.sync.aligned.m8n8.x4.shared.b16 {%0,%1,%2,%3}, [%4];"
                             : "=r"(b[2 * nb][0]), "=r"(b[2 * nb][1]),
                               "=r"(b[2 * nb + 1][0]), "=r"(b[2 * nb + 1][1])
                             : "r"(ad));
            }
#pragma unroll
            for (int mt = 0; mt < 2; mt++)
#pragma unroll
                for (int nt = 0; nt < 8; nt++)
                    asm volatile("mma.sync.aligned.m16n8k16.row.col.f32.f16.f16.f32 "
                                 "{%0,%1,%2,%3}, {%4,%5,%6,%7}, {%8,%9}, {%0,%1,%2,%3};"
                                 : "+f"(c[mt][nt][0]), "+f"(c[mt][nt][1]),
                                   "+f"(c[mt][nt][2]), "+f"(c[mt][nt][3])
                                 : "r"(a[mt][0]), "r"(a[mt][1]), "r"(a[mt][2]), "r"(a[mt][3]),
                                   "r"(b[nt][0]), "r"(b[nt][1]));
        }
    }
}

__global__ __launch_bounds__(256, 1)
void node_mm(const float* __restrict__ x, int nrows,
             const unsigned char* __restrict__ w1h, const unsigned char* __restrict__ w1l,
             const unsigned char* __restrict__ wgh, const unsigned char* __restrict__ wgl,
             const unsigned char* __restrict__ wsh, const unsigned char* __restrict__ wsl,
             const float* __restrict__ b1,
             const float* __restrict__ a1w, const float* __restrict__ a1bp,
             const float* __restrict__ a2w, const float* __restrict__ a2bp,
             const float* __restrict__ bagg,
             __half* __restrict__ gout, float* __restrict__ a1out,
             float* __restrict__ a2out, float* __restrict__ selfout) {
    extern __shared__ char sraw[];
    const u32 sb = smem_to_u32(sraw);
    const u32 base = (sb + 1023u) & ~1023u;
    char* bp = sraw + (base - sb);
    float* sBB  = (float*)(bp + OFF_HDR);
    float* sAW1 = sBB + 128;
    float* sAW2 = sAW1 + 128;
    float* sBG  = sAW2 + 128;
    float* sPA1 = sBG + 128;
    float* sPA2 = sPA1 + 128;

    const int tid = threadIdx.x, wid = tid >> 5, lane = tid & 31;
    const int wm = wid & 3, wn = wid >> 2;
    const int r0 = wm * 32, cbase = wn * 64;
    const int rbase = blockIdx.x * 128;
    const u32 aHi = base + OFF_A_HI, aLo = base + OFF_A_LO;
    const u32 wHi = base + OFF_W_HI, wLo = base + OFF_W_LO;

    if (tid < 128) {
        sBB[tid] = b1[tid];
        sAW1[tid] = a1w[tid];
        sAW2[tid] = a2w[tid];
        sBG[tid] = bagg[tid];
    }
    copy32k(bp + OFF_W_HI, w1h, tid);
    copy32k(bp + OFF_W_LO, w1l, tid);
#pragma unroll 1
    for (int it = 0; it < 8; it++) {
        int f = tid + it * 256;
        int row = f >> 4, kc = f & 15;
        float v[8];
        if (rbase + row < nrows) {
            const float4* xp = (const float4*)(x + (size_t)(rbase + row) * 128 + kc * 8);
            float4 p0 = xp[0], p1 = xp[1];
            v[0] = p0.x; v[1] = p0.y; v[2] = p0.z; v[3] = p0.w;
            v[4] = p1.x; v[5] = p1.y; v[6] = p1.z; v[7] = p1.w;
        } else {
#pragma unroll
            for (int j = 0; j < 8; j++) v[j] = 0.f;
        }
        uint4 hi, lo;
        split8h(v, hi, lo);
        u32 ad = CH(row, kc);
        *(uint4*)(bp + OFF_A_HI + ad) = hi;
        *(uint4*)(bp + OFF_A_LO + ad) = lo;
    }
    __syncthreads();

    float c[2][8][4];
    float pph1[4], pph2[4];

    // ---- GEMM1: h = x @ W1^T ----
    warp_gemm(aHi, aLo, wHi, wLo, r0, cbase, lane, c);
    __syncthreads();   // all warps done reading sA(x), sW(W1)

    // epilogue 1: bias+relu, attention dots, h -> sA fp16 hi/lo
#pragma unroll
    for (int mt = 0; mt < 2; mt++)
#pragma unroll
        for (int half = 0; half < 2; half++) {
            int row = r0 + mt * 16 + half * 8 + (lane >> 2);
            float ph1 = 0.f, ph2 = 0.f;
#pragma unroll
            for (int nt = 0; nt < 8; nt++) {
                int col = cbase + nt * 8 + 2 * (lane & 3);
                float h0 = fmaxf(c[mt][nt][half * 2 + 0] + sBB[col], 0.f);
                float h1 = fmaxf(c[mt][nt][half * 2 + 1] + sBB[col + 1], 0.f);
                ph1 += h0 * sAW1[col] + h1 * sAW1[col + 1];
                ph2 += h0 * sAW2[col] + h1 * sAW2[col + 1];
                __half hh0 = __float2half_rn(h0), hh1 = __float2half_rn(h1);
                __half2 hhi = __halves2half2(hh0, hh1);
                __half2 hlo = __floats2half2_rn(h0 - __half2float(hh0),
                                                h1 - __half2float(hh1));
                u32 ao = (u32)(row * 256 + (((col >> 3) ^ (row & 7)) << 4) + (col & 7) * 2);
                *(u32*)(bp + OFF_A_HI + ao) = *(u32*)&hhi;
                *(u32*)(bp + OFF_A_LO + ao) = *(u32*)&hlo;
            }
            ph1 += __shfl_xor_sync(0xffffffffu, ph1, 1);
            ph1 += __shfl_xor_sync(0xffffffffu, ph1, 2);
            ph2 += __shfl_xor_sync(0xffffffffu, ph2, 1);
            ph2 += __shfl_xor_sync(0xffffffffu, ph2, 2);
            pph1[mt * 2 + half] = ph1;
            pph2[mt * 2 + half] = ph2;
            if (wn == 0 && (lane & 3) == 0) {
                sPA1[row] = ph1;
                sPA2[row] = ph2;
            }
        }
    copy32k(bp + OFF_W_HI, wgh, tid);   // stage Wg (safe: post-GEMM1 barrier above)
    copy32k(bp + OFF_W_LO, wgl, tid);
    __syncthreads();
    if (wn == 1 && (lane & 3) == 0) {
        const float a1b = *a1bp, a2b = *a2bp;
#pragma unroll
        for (int mt = 0; mt < 2; mt++)
#pragma unroll
            for (int half = 0; half < 2; half++) {
                int row = r0 + mt * 16 + half * 8 + (lane >> 2);
                int grow = rbase + row;
                if (grow < nrows) {
                    if (a1out) a1out[grow] = sPA1[row] + pph1[mt * 2 + half] + a1b;
                    a2out[grow] = sPA2[row] + pph2[mt * 2 + half] + a2b;
                }
            }
    }

    // ---- GEMM2: g = h @ Wg^T -> fp16 global ----
    warp_gemm(aHi, aLo, wHi, wLo, r0, cbase, lane, c);
#pragma unroll
    for (int mt = 0; mt < 2; mt++)
#pragma unroll
        for (int half = 0; half < 2; half++) {
            int row = r0 + mt * 16 + half * 8 + (lane >> 2);
            int grow = rbase + row;
            if (grow < nrows) {
#pragma unroll
                for (int nt = 0; nt < 8; nt++) {
                    int col = cbase + nt * 8 + 2 * (lane & 3);
                    __half2 hv = __floats2half2_rn(c[mt][nt][half * 2 + 0],
                                                   c[mt][nt][half * 2 + 1]);
                    *(u32*)(gout + (size_t)grow * D + col) = *(u32*)&hv;
                }
            }
        }

    // ---- GEMM3 (x0 only): self = h @ Wself^T + bagg -> out ----
    if (wsh) {
        __syncthreads();   // all warps done reading sW(Wg)
        copy32k(bp + OFF_W_HI, wsh, tid);
        copy32k(bp + OFF_W_LO, wsl, tid);
        __syncthreads();
        warp_gemm(aHi, aLo, wHi, wLo, r0, cbase, lane, c);
#pragma unroll
        for (int mt = 0; mt < 2; mt++)
#pragma unroll
            for (int half = 0; half < 2; half++) {
                int row = r0 + mt * 16 + half * 8 + (lane >> 2);
                int grow = rbase + row;
                if (grow < nrows) {
#pragma unroll
                    for (int nt = 0; nt < 8; nt++) {
                        int col = cbase + nt * 8 + 2 * (lane & 3);
                        float2 v = make_float2(c[mt][nt][half * 2 + 0] + sBG[col],
                                               c[mt][nt][half * 2 + 1] + sBG[col + 1]);
                        *(float2*)(selfout + (size_t)grow * D + col) = v;
                    }
                }
            }
    }
}

// ---------------- binning kernels (combined CSR over all 3 lists) ----------------
__global__ void zero_kernel(int* p, int n) {
    int i = blockIdx.x * blockDim.x + threadIdx.x;
    if (i < n) p[i] = 0;
}

__global__ void hist_kernel(const int* __restrict__ r0, int E0,
                            const int* __restrict__ r1, int E1,
                            const int* __restrict__ r2, int E2,
                            int* __restrict__ cnt) {
    int t = blockIdx.x * blockDim.x + threadIdx.x;
    int row;
    if (t < E0) row = __ldg(r0 + t);
    else if ((t -= E0) < E1) row = __ldg(r1 + t);
    else if ((t -= E1) < E2) row = __ldg(r2 + t);
    else return;
    atomicAdd(&cnt[row], 1);
}

// ---- parallel scan phase A: per-block sums of 4096-element chunks ----
__global__ __launch_bounds__(1024)
void scanA_kernel(const int* __restrict__ cnt, int n, int* __restrict__ bsum) {
    __shared__ int wsum[32];
    const int tid = threadIdx.x, lane = tid & 31, wid = tid >> 5;
    int idx = blockIdx.x * SCAN_CHUNK + tid * 4;
    int s = 0;
#pragma unroll
    for (int j = 0; j < 4; j++) s += (idx + j < n) ? cnt[idx + j] : 0;
#pragma unroll
    for (int off = 16; off >= 1; off >>= 1) s += __shfl_down_sync(0xffffffffu, s, off);
    if (lane == 0) wsum[wid] = s;
    __syncthreads();
    if (wid == 0) {
        int y = wsum[lane];
#pragma unroll
        for (int off = 16; off >= 1; off >>= 1) y += __shfl_down_sync(0xffffffffu, y, off);
        if (lane == 0) bsum[blockIdx.x] = y;
    }
}

// ---- phase B: exclusive scan of block sums (1 warp) ----
__global__ void scanB_kernel(int* __restrict__ bsum, int nb) {
    int lane = threadIdx.x;
    int v = (lane < nb) ? bsum[lane] : 0;
    int x = v;
#pragma unroll
    for (int off = 1; off < 32; off <<= 1) {
        int t = __shfl_up_sync(0xffffffffu, x, off);
        if (lane >= off) x += t;
    }
    if (lane <= nb && lane < 32) bsum[lane] = x - v;   // exclusive
    // write total at bsum[nb] (lane nb holds incl sum of all if nb<32)
    if (lane == 31) bsum[nb] = x;   // x at lane31 = total (nb<=25<32)
}

// ---- phase C: per-block exclusive scan + block offset -> offs, cur ----
__global__ __launch_bounds__(1024)
void scanC_kernel(const int* __restrict__ cnt, int n, const int* __restrict__ bsum,
                  int* __restrict__ offs, int* __restrict__ cur) {
    __shared__ int wsum[32];
    const int tid = threadIdx.x, lane = tid & 31, wid = tid >> 5;
    int idx = blockIdx.x * SCAN_CHUNK + tid * 4;
    int v[4];
#pragma unroll
    for (int j = 0; j < 4; j++) v[j] = (idx + j < n) ? cnt[idx + j] : 0;
    int tsum = v[0] + v[1] + v[2] + v[3];
    int xv = tsum;
#pragma unroll
    for (int off = 1; off < 32; off <<= 1) {
        int t = __shfl_up_sync(0xffffffffu, xv, off);
        if (lane >= off) xv += t;
    }
    if (lane == 31) wsum[wid] = xv;
    __syncthreads();
    if (wid == 0) {
        int y = wsum[lane];
#pragma unroll
        for (int off = 1; off < 32; off <<= 1) {
            int t = __shfl_up_sync(0xffffffffu, y, off);
            if (lane >= off) y += t;
        }
        wsum[lane] = y;
    }
    __syncthreads();
    int warpoff = (wid == 0) ? 0 : wsum[wid - 1];
    int excl = bsum[blockIdx.x] + warpoff + xv - tsum;
#pragma unroll
    for (int j = 0; j < 4; j++) {
        if (idx + j < n) { offs[idx + j] = excl; cur[idx + j] = excl; }
        excl += v[j];
    }
    if (blockIdx.x == 0 && tid == 0) offs[n] = bsum[(n + SCAN_CHUNK - 1) / SCAN_CHUNK];
}

__global__ void scat_kernel(const int* __restrict__ r0, const int* __restrict__ c0, int E0,
                            const int* __restrict__ r1, const int* __restrict__ c1, int E1,
                            const int* __restrict__ r2, const int* __restrict__ c2, int E2,
                            int base1, int base2,
                            int* __restrict__ cur, int* __restrict__ scols) {
    int t = blockIdx.x * blockDim.x + threadIdx.x;
    int row, col;
    if (t < E0) { row = __ldg(r0 + t); col = __ldg(c0 + t); }
    else if ((t -= E0) < E1) { row = __ldg(r1 + t); col = __ldg(c1 + t) + base1; }
    else if ((t -= E1) < E2) { row = __ldg(r2 + t); col = __ldg(c2 + t) + base2; }
    else return;
    int p = atomicAdd(&cur[row], 1);
    scols[p] = col;
}

// ---------------- aggregate: one warp per output row ----------------
__device__ __forceinline__ void gacc(int c, float sv, int lane,
                                     const __half* __restrict__ g, float4& acc) {
    uint2 u = __ldg((const uint2*)(g + (size_t)c * D) + lane);
    __half2 p0 = *reinterpret_cast<__half2*>(&u.x);
    __half2 p1 = *reinterpret_cast<__half2*>(&u.y);
    float2 f0 = __half22float2(p0);
    float2 f1 = __half22float2(p1);
    acc.x += sv * f0.x;
    acc.y += sv * f0.y;
    acc.z += sv * f1.x;
    acc.w += sv * f1.y;
}

__device__ __forceinline__ float fsig(float s) {
    return 1.0f / (1.0f + __expf(-s));
}

__global__ __launch_bounds__(256)
void agg_kernel(const int* __restrict__ offs, const int* __restrict__ scols,
                const __half* __restrict__ g, const float* __restrict__ a2,
                const float* __restrict__ a1, float* __restrict__ out, int n0) {
    int row = blockIdx.x * 8 + (threadIdx.x >> 5);
    if (row >= n0) return;
    int lane = threadIdx.x & 31;
    float va1 = __ldg(a1 + row);
    float4 acc = make_float4(0.f, 0.f, 0.f, 0.f);
    int s = __ldg(offs + row), e = __ldg(offs + row + 1);
    int i = s;
    for (; i + 4 <= e; i += 4) {
        int c0 = __ldg(scols + i);
        int c1 = __ldg(scols + i + 1);
        int c2 = __ldg(scols + i + 2);
        int c3 = __ldg(scols + i + 3);
        float s0 = fsig(va1 + __ldg(a2 + c0));
        float s1 = fsig(va1 + __ldg(a2 + c1));
        float s2 = fsig(va1 + __ldg(a2 + c2));
        float s3 = fsig(va1 + __ldg(a2 + c3));
        gacc(c0, s0, lane, g, acc);
        gacc(c1, s1, lane, g, acc);
        gacc(c2, s2, lane, g, acc);
        gacc(c3, s3, lane, g, acc);
    }
    for (; i < e; i++) {
        int ca = __ldg(scols + i);
        gacc(ca, fsig(va1 + __ldg(a2 + ca)), lane, g, acc);
    }
    float4* op = (float4*)(out + (size_t)row * D) + lane;
    float4 c = *op;
    c.x += acc.x; c.y += acc.y; c.z += acc.z; c.w += acc.w;
    *op = c;
}

// ---------------- launch ----------------
extern "C" void kernel_launch(void* const* d_in, const int* in_sizes, int n_in,
                              void* d_out, int out_size) {
    const float* x0   = (const float*)d_in[0];
    const float* x1   = (const float*)d_in[1];
    const float* x2   = (const float*)d_in[2];
    const float* W1   = (const float*)d_in[3];
    const float* b1   = (const float*)d_in[4];
    const float* a1w  = (const float*)d_in[5];
    const float* a1b  = (const float*)d_in[6];
    const float* a2w  = (const float*)d_in[7];
    const float* a2b  = (const float*)d_in[8];
    const float* Wagg = (const float*)d_in[9];
    const float* bagg = (const float*)d_in[10];
    const int* ar0 = (const int*)d_in[11];
    const int* ac0 = (const int*)d_in[12];
    const int* ar1 = (const int*)d_in[13];
    const int* ac1 = (const int*)d_in[14];
    const int* ar2 = (const int*)d_in[15];
    const int* ac2 = (const int*)d_in[16];
    float* out = (float*)d_out;

    const int N0 = in_sizes[0] / D;
    const int N1 = in_sizes[1] / D;
    const int N2 = in_sizes[2] / D;
    const int E0 = in_sizes[11];
    const int E1 = in_sizes[13];
    const int E2 = in_sizes[15];

    __half* pg;
    float *pa2, *pa1;
    int *pcnt, *poff, *pcur, *pscols, *pbsum;
    unsigned char* pwp;
    cudaGetSymbolAddress((void**)&pg, g_gall);
    cudaGetSymbolAddress((void**)&pa2, g_a2all);
    cudaGetSymbolAddress((void**)&pa1, g_a1_0);
    cudaGetSymbolAddress((void**)&pcnt, g_cnt);
    cudaGetSymbolAddress((void**)&poff, g_off);
    cudaGetSymbolAddress((void**)&pcur, g_cur);
    cudaGetSymbolAddress((void**)&pscols, g_scols);
    cudaGetSymbolAddress((void**)&pwp, g_wprep);
    cudaGetSymbolAddress((void**)&pbsum, g_bsum);

    cudaFuncSetAttribute(node_mm, cudaFuncAttributeMaxDynamicSharedMemorySize, SMEM_REQ);

    #define WHI(m) (pwp + (size_t)(m) * 2 * 32768)
    #define WLO(m) (pwp + (size_t)(m) * 2 * 32768 + 32768)

    prep_w<<<5, 256>>>(W1, Wagg, pwp);
    zero_kernel<<<(N0 + 256) / 256, 256>>>(pcnt, N0 + 1);
    const int ET = E0 + E1 + E2;
    hist_kernel<<<(ET + 255) / 256, 256>>>(ar0, E0, ar1, E1, ar2, E2, pcnt);
    const int NB = (N0 + SCAN_CHUNK - 1) / SCAN_CHUNK;
    scanA_kernel<<<NB, 1024>>>(pcnt, N0, pbsum);
    scanB_kernel<<<1, 32>>>(pbsum, NB);
    scanC_kernel<<<NB, 1024>>>(pcnt, N0, pbsum, poff, pcur);
    scat_kernel<<<(ET + 255) / 256, 256>>>(ar0, ac0, E0, ar1, ac1, E1, ar2, ac2, E2,
                                           N0, N0 + N1, pcur, pscols);

    node_mm<<<(N0 + 127) / 128, 256, SMEM_REQ>>>(
        x0, N0, WHI(0), WLO(0), WHI(2), WLO(2), WHI(1), WLO(1),
        b1, a1w, a1b, a2w, a2b, bagg,
        pg, pa1, pa2, out);
    node_mm<<<(N1 + 127) / 128, 256, SMEM_REQ>>>(
        x1, N1, WHI(0), WLO(0), WHI(3), WLO(3), nullptr, nullptr,
        b1, a1w, a1b, a2w, a2b, bagg,
        pg + (size_t)N0 * D, nullptr, pa2 + N0, nullptr);
    node_mm<<<(N2 + 127) / 128, 256, SMEM_REQ>>>(
        x2, N2, WHI(0), WLO(0), WHI(4), WLO(4), nullptr, nullptr,
        b1, a1w, a1b, a2w, a2b, bagg,
        pg + (size_t)(N0 + N1) * D, nullptr, pa2 + N0 + N1, nullptr);

    agg_kernel<<<(N0 + 7) / 8, 256>>>(poff, pscols, pg, pa2, pa1, out, N0);
}

// round 10
// speedup vs baseline: 2.3843x; 1.0041x over previous
#include <cuda_runtime.h>
#include <cuda_fp16.h>
#include <cstdint>

#define D 128
#define N0MAX 100000
#define NALL  (100000 + 150000 + 80000)
#define EALL  3000000
#define SCAN_CHUNK 4096
#define SCAN_BLOCKS ((N0MAX + SCAN_CHUNK - 1) / SCAN_CHUNK)

typedef unsigned long long ull;
typedef unsigned int u32;

// ---------------- static scratch (allocation-free rule) ----------------
__device__ __half g_gall[(size_t)NALL * 128];   // fp16 projected features, concat [g0|g1|g2]
__device__ float g_a2all[NALL];                 // concat [a2_0|a2_1|a2_2]
__device__ float g_a1_0[N0MAX];
// prepped weights: 5 matrices (W1, Wagg0..3) x {hi,lo} x 32KB fp16 tiles,
// transposed to [n][k], 16B-chunk XOR-swizzled (ldmatrix-ready, raw smem copy)
__device__ unsigned char g_wprep[5 * 2 * 32768];
// combined CSR scratch
__device__ int g_cnt[N0MAX + 1];
__device__ int g_off[N0MAX + 1];
__device__ int g_cur[N0MAX];
__device__ int g_scols[EALL];
__device__ int g_bsum[SCAN_BLOCKS + 1];

__device__ __forceinline__ u32 smem_to_u32(const void* p) {
    u32 a;
    asm("{ .reg .u64 t; cvta.to.shared.u64 t, %1; cvt.u32.u64 %0, t; }" : "=r"(a) : "l"(p));
    return a;
}

// byte offset of 16B chunk (row, kc) in a 128x128 fp16 tile (256B rows),
// XOR swizzle on chunk index by row&7 -> conflict-free ldmatrix + staging
#define CH(row, kc) ((u32)((row) * 256 + ((((kc)) ^ ((row) & 7)) << 4)))

// split 8 fp32 -> fp16 hi + fp16 lo packed uint4 (16B each)
__device__ __forceinline__ void split8h(const float* v, uint4& hi, uint4& lo) {
    u32 hw[4], lw[4];
#pragma unroll
    for (int j = 0; j < 4; j++) {
        float a = v[2 * j], b = v[2 * j + 1];
        __half ah = __float2half_rn(a), bh = __float2half_rn(b);
        float ar = a - __half2float(ah), br = b - __half2float(bh);
        __half2 hh = __halves2half2(ah, bh);
        __half2 ll = __floats2half2_rn(ar, br);
        hw[j] = *(u32*)&hh;
        lw[j] = *(u32*)&ll;
    }
    hi = make_uint4(hw[0], hw[1], hw[2], hw[3]);
    lo = make_uint4(lw[0], lw[1], lw[2], lw[3]);
}

// ---------------- weight prep: transpose + fp16 split + swizzle ----------------
__global__ void prep_w(const float* __restrict__ W1, const float* __restrict__ Wagg,
                       unsigned char* __restrict__ wp) {
    int m = blockIdx.x, tid = threadIdx.x;
    unsigned char* hip = wp + (size_t)m * 2 * 32768;
    unsigned char* lop = hip + 32768;
#pragma unroll 1
    for (int it = 0; it < 8; it++) {
        int f = tid + it * 256;           // chunk id 0..2047
        int n = f >> 4, kc = f & 15, k0 = kc * 8;
        float v[8];
#pragma unroll
        for (int j = 0; j < 8; j++) {
            int k = k0 + j;
            v[j] = (m == 0) ? W1[k * 128 + n] : Wagg[((m - 1) * 128 + k) * 128 + n];
        }
        uint4 hi, lo;
        split8h(v, hi, lo);
        u32 ad = CH(n, kc);
        *(uint4*)(hip + ad) = hi;
        *(uint4*)(lop + ad) = lo;
    }
}

// ---------------- node kernel (mma.sync m16n8k16 fp16, 3-pass split) ----------
#define OFF_A_HI 0
#define OFF_A_LO 32768
#define OFF_W_HI 65536
#define OFF_W_LO 98304
#define OFF_HDR  131072
#define SMEM_REQ (131072 + 3072 + 1024)

__device__ __forceinline__ void copy32k(void* dst, const void* src, int tid) {
    const uint4* s = (const uint4*)src;
    uint4* d = (uint4*)dst;
#pragma unroll
    for (int i = 0; i < 8; i++) d[tid + i * 256] = s[tid + i * 256];
}

__device__ __forceinline__ void warp_gemm(u32 aHi, u32 aLo, u32 wHi, u32 wLo,
                                          int r0, int cbase, int lane,
                                          float c[2][8][4]) {
    const int q = lane >> 3, sr = lane & 7;
#pragma unroll
    for (int mt = 0; mt < 2; mt++)
#pragma unroll
        for (int nt = 0; nt < 8; nt++)
#pragma unroll
            for (int j = 0; j < 4; j++) c[mt][nt][j] = 0.f;

#pragma unroll 1
    for (int pass = 0; pass < 3; pass++) {
        const u32 Ab = (pass == 2) ? aLo : aHi;
        const u32 Bb = (pass == 1) ? wLo : wHi;
#pragma unroll 1
        for (int ks = 0; ks < 8; ks++) {
            u32 a[2][4];
#pragma unroll
            for (int mt = 0; mt < 2; mt++) {
                int row = r0 + mt * 16 + ((q & 1) << 3) + sr;
                int kc = 2 * ks + (q >> 1);
                u32 ad = Ab + CH(row, kc);
                asm volatile("ldmatrix.sync.aligned.m8n8.x4.shared.b16 {%0,%1,%2,%3}, [%4];"
                             : "=r"(a[mt][0]), "=r"(a[mt][1]), "=r"(a[mt][2]), "=r"(a[mt][3])
                             : "r"(ad));
            }
            u32 b[8][2];
#pragma unroll
            for (int nb = 0; nb < 4; nb++) {
                int rown = cbase + nb * 16 + ((q >> 1) << 3) + sr;
                int kc = 2 * ks + (q & 1);
                u32 ad = Bb + CH(rown, kc);
                asm volatile("ldmatrix.sync.aligned.m8n8.x4.shared.b16 {%0,%1,%2,%3}, [%4];"
                             : "=r"(b[2 * nb][0]), "=r"(b[2 * nb][1]),
                               "=r"(b[2 * nb + 1][0]), "=r"(b[2 * nb + 1][1])
                             : "r"(ad));
            }
#pragma unroll
            for (int mt = 0; mt < 2; mt++)
#pragma unroll
                for (int nt = 0; nt < 8; nt++)
                    asm volatile("mma.sync.aligned.m16n8k16.row.col.f32.f16.f16.f32 "
                                 "{%0,%1,%2,%3}, {%4,%5,%6,%7}, {%8,%9}, {%0,%1,%2,%3};"
                                 : "+f"(c[mt][nt][0]), "+f"(c[mt][nt][1]),
                                   "+f"(c[mt][nt][2]), "+f"(c[mt][nt][3])
                                 : "r"(a[mt][0]), "r"(a[mt][1]), "r"(a[mt][2]), "r"(a[mt][3]),
                                   "r"(b[nt][0]), "r"(b[nt][1]));
        }
    }
}

__global__ __launch_bounds__(256, 1)
void node_mm(const float* __restrict__ x, int nrows,
             const unsigned char* __restrict__ w1h, const unsigned char* __restrict__ w1l,
             const unsigned char* __restrict__ wgh, const unsigned char* __restrict__ wgl,
             const unsigned char* __restrict__ wsh, const unsigned char* __restrict__ wsl,
             const float* __restrict__ b1,
             const float* __restrict__ a1w, const float* __restrict__ a1bp,
             const float* __restrict__ a2w, const float* __restrict__ a2bp,
             const float* __restrict__ bagg,
             __half* __restrict__ gout, float* __restrict__ a1out,
             float* __restrict__ a2out, float* __restrict__ selfout) {
    extern __shared__ char sraw[];
    const u32 sb = smem_to_u32(sraw);
    const u32 base = (sb + 1023u) & ~1023u;
    char* bp = sraw + (base - sb);
    float* sBB  = (float*)(bp + OFF_HDR);
    float* sAW1 = sBB + 128;
    float* sAW2 = sAW1 + 128;
    float* sBG  = sAW2 + 128;
    float* sPA1 = sBG + 128;
    float* sPA2 = sPA1 + 128;

    const int tid = threadIdx.x, wid = tid >> 5, lane = tid & 31;
    const int wm = wid & 3, wn = wid >> 2;
    const int r0 = wm * 32, cbase = wn * 64;
    const int rbase = blockIdx.x * 128;
    const u32 aHi = base + OFF_A_HI, aLo = base + OFF_A_LO;
    const u32 wHi = base + OFF_W_HI, wLo = base + OFF_W_LO;

    if (tid < 128) {
        sBB[tid] = b1[tid];
        sAW1[tid] = a1w[tid];
        sAW2[tid] = a2w[tid];
        sBG[tid] = bagg[tid];
    }
    copy32k(bp + OFF_W_HI, w1h, tid);
    copy32k(bp + OFF_W_LO, w1l, tid);
#pragma unroll 1
    for (int it = 0; it < 8; it++) {
        int f = tid + it * 256;
        int row = f >> 4, kc = f & 15;
        float v[8];
        if (rbase + row < nrows) {
            const float4* xp = (const float4*)(x + (size_t)(rbase + row) * 128 + kc * 8);
            float4 p0 = xp[0], p1 = xp[1];
            v[0] = p0.x; v[1] = p0.y; v[2] = p0.z; v[3] = p0.w;
            v[4] = p1.x; v[5] = p1.y; v[6] = p1.z; v[7] = p1.w;
        } else {
#pragma unroll
            for (int j = 0; j < 8; j++) v[j] = 0.f;
        }
        uint4 hi, lo;
        split8h(v, hi, lo);
        u32 ad = CH(row, kc);
        *(uint4*)(bp + OFF_A_HI + ad) = hi;
        *(uint4*)(bp + OFF_A_LO + ad) = lo;
    }
    __syncthreads();

    float c[2][8][4];
    float pph1[4], pph2[4];

    // ---- GEMM1: h = x @ W1^T ----
    warp_gemm(aHi, aLo, wHi, wLo, r0, cbase, lane, c);
    __syncthreads();   // all warps done reading sA(x), sW(W1)

    // epilogue 1: bias+relu, attention dots, h -> sA fp16 hi/lo
#pragma unroll
    for (int mt = 0; mt < 2; mt++)
#pragma unroll
        for (int half = 0; half < 2; half++) {
            int row = r0 + mt * 16 + half * 8 + (lane >> 2);
            float ph1 = 0.f, ph2 = 0.f;
#pragma unroll
            for (int nt = 0; nt < 8; nt++) {
                int col = cbase + nt * 8 + 2 * (lane & 3);
                float h0 = fmaxf(c[mt][nt][half * 2 + 0] + sBB[col], 0.f);
                float h1 = fmaxf(c[mt][nt][half * 2 + 1] + sBB[col + 1], 0.f);
                ph1 += h0 * sAW1[col] + h1 * sAW1[col + 1];
                ph2 += h0 * sAW2[col] + h1 * sAW2[col + 1];
                __half hh0 = __float2half_rn(h0), hh1 = __float2half_rn(h1);
                __half2 hhi = __halves2half2(hh0, hh1);
                __half2 hlo = __floats2half2_rn(h0 - __half2float(hh0),
                                                h1 - __half2float(hh1));
                u32 ao = (u32)(row * 256 + (((col >> 3) ^ (row & 7)) << 4) + (col & 7) * 2);
                *(u32*)(bp + OFF_A_HI + ao) = *(u32*)&hhi;
                *(u32*)(bp + OFF_A_LO + ao) = *(u32*)&hlo;
            }
            ph1 += __shfl_xor_sync(0xffffffffu, ph1, 1);
            ph1 += __shfl_xor_sync(0xffffffffu, ph1, 2);
            ph2 += __shfl_xor_sync(0xffffffffu, ph2, 1);
            ph2 += __shfl_xor_sync(0xffffffffu, ph2, 2);
            pph1[mt * 2 + half] = ph1;
            pph2[mt * 2 + half] = ph2;
            if (wn == 0 && (lane & 3) == 0) {
                sPA1[row] = ph1;
                sPA2[row] = ph2;
            }
        }
    copy32k(bp + OFF_W_HI, wgh, tid);   // stage Wg (safe: post-GEMM1 barrier above)
    copy32k(bp + OFF_W_LO, wgl, tid);
    __syncthreads();
    if (wn == 1 && (lane & 3) == 0) {
        const float a1b = *a1bp, a2b = *a2bp;
#pragma unroll
        for (int mt = 0; mt < 2; mt++)
#pragma unroll
            for (int half = 0; half < 2; half++) {
                int row = r0 + mt * 16 + half * 8 + (lane >> 2);
                int grow = rbase + row;
                if (grow < nrows) {
                    if (a1out) a1out[grow] = sPA1[row] + pph1[mt * 2 + half] + a1b;
                    a2out[grow] = sPA2[row] + pph2[mt * 2 + half] + a2b;
                }
            }
    }

    // ---- GEMM2: g = h @ Wg^T -> fp16 global ----
    warp_gemm(aHi, aLo, wHi, wLo, r0, cbase, lane, c);
#pragma unroll
    for (int mt = 0; mt < 2; mt++)
#pragma unroll
        for (int half = 0; half < 2; half++) {
            int row = r0 + mt * 16 + half * 8 + (lane >> 2);
            int grow = rbase + row;
            if (grow < nrows) {
#pragma unroll
                for (int nt = 0; nt < 8; nt++) {
                    int col = cbase + nt * 8 + 2 * (lane & 3);
                    __half2 hv = __floats2half2_rn(c[mt][nt][half * 2 + 0],
                                                   c[mt][nt][half * 2 + 1]);
                    *(u32*)(gout + (size_t)grow * D + col) = *(u32*)&hv;
                }
            }
        }

    // ---- GEMM3 (x0 only): self = h @ Wself^T + bagg -> out ----
    if (wsh) {
        __syncthreads();   // all warps done reading sW(Wg)
        copy32k(bp + OFF_W_HI, wsh, tid);
        copy32k(bp + OFF_W_LO, wsl, tid);
        __syncthreads();
        warp_gemm(aHi, aLo, wHi, wLo, r0, cbase, lane, c);
#pragma unroll
        for (int mt = 0; mt < 2; mt++)
#pragma unroll
            for (int half = 0; half < 2; half++) {
                int row = r0 + mt * 16 + half * 8 + (lane >> 2);
                int grow = rbase + row;
                if (grow < nrows) {
#pragma unroll
                    for (int nt = 0; nt < 8; nt++) {
                        int col = cbase + nt * 8 + 2 * (lane & 3);
                        float2 v = make_float2(c[mt][nt][half * 2 + 0] + sBG[col],
                                               c[mt][nt][half * 2 + 1] + sBG[col + 1]);
                        *(float2*)(selfout + (size_t)grow * D + col) = v;
                    }
                }
            }
    }
}

// ---------------- binning kernels (combined CSR over all 3 lists) ----------------
__global__ void zero_kernel(int* p, int n) {
    int i = blockIdx.x * blockDim.x + threadIdx.x;
    if (i < n) p[i] = 0;
}

__global__ void hist_kernel(const int* __restrict__ r0, int E0,
                            const int* __restrict__ r1, int E1,
                            const int* __restrict__ r2, int E2,
                            int* __restrict__ cnt) {
    int t = blockIdx.x * blockDim.x + threadIdx.x;
    int row;
    if (t < E0) row = __ldg(r0 + t);
    else if ((t -= E0) < E1) row = __ldg(r1 + t);
    else if ((t -= E1) < E2) row = __ldg(r2 + t);
    else return;
    atomicAdd(&cnt[row], 1);
}

// ---- parallel scan phase A: per-block sums of 4096-element chunks ----
__global__ __launch_bounds__(1024)
void scanA_kernel(const int* __restrict__ cnt, int n, int* __restrict__ bsum) {
    __shared__ int wsum[32];
    const int tid = threadIdx.x, lane = tid & 31, wid = tid >> 5;
    int idx = blockIdx.x * SCAN_CHUNK + tid * 4;
    int s = 0;
#pragma unroll
    for (int j = 0; j < 4; j++) s += (idx + j < n) ? cnt[idx + j] : 0;
#pragma unroll
    for (int off = 16; off >= 1; off >>= 1) s += __shfl_down_sync(0xffffffffu, s, off);
    if (lane == 0) wsum[wid] = s;
    __syncthreads();
    if (wid == 0) {
        int y = wsum[lane];
#pragma unroll
        for (int off = 16; off >= 1; off >>= 1) y += __shfl_down_sync(0xffffffffu, y, off);
        if (lane == 0) bsum[blockIdx.x] = y;
    }
}

// ---- phase B: exclusive scan of block sums (1 warp) ----
__global__ void scanB_kernel(int* __restrict__ bsum, int nb) {
    int lane = threadIdx.x;
    int v = (lane < nb) ? bsum[lane] : 0;
    int x = v;
#pragma unroll
    for (int off = 1; off < 32; off <<= 1) {
        int t = __shfl_up_sync(0xffffffffu, x, off);
        if (lane >= off) x += t;
    }
    if (lane <= nb && lane < 32) bsum[lane] = x - v;   // exclusive
    if (lane == 31) bsum[nb] = x;   // total (nb<=25<32)
}

// ---- phase C: per-block exclusive scan + block offset -> offs, cur ----
__global__ __launch_bounds__(1024)
void scanC_kernel(const int* __restrict__ cnt, int n, const int* __restrict__ bsum,
                  int* __restrict__ offs, int* __restrict__ cur) {
    __shared__ int wsum[32];
    const int tid = threadIdx.x, lane = tid & 31, wid = tid >> 5;
    int idx = blockIdx.x * SCAN_CHUNK + tid * 4;
    int v[4];
#pragma unroll
    for (int j = 0; j < 4; j++) v[j] = (idx + j < n) ? cnt[idx + j] : 0;
    int tsum = v[0] + v[1] + v[2] + v[3];
    int xv = tsum;
#pragma unroll
    for (int off = 1; off < 32; off <<= 1) {
        int t = __shfl_up_sync(0xffffffffu, xv, off);
        if (lane >= off) xv += t;
    }
    if (lane == 31) wsum[wid] = xv;
    __syncthreads();
    if (wid == 0) {
        int y = wsum[lane];
#pragma unroll
        for (int off = 1; off < 32; off <<= 1) {
            int t = __shfl_up_sync(0xffffffffu, y, off);
            if (lane >= off) y += t;
        }
        wsum[lane] = y;
    }
    __syncthreads();
    int warpoff = (wid == 0) ? 0 : wsum[wid - 1];
    int excl = bsum[blockIdx.x] + warpoff + xv - tsum;
#pragma unroll
    for (int j = 0; j < 4; j++) {
        if (idx + j < n) { offs[idx + j] = excl; cur[idx + j] = excl; }
        excl += v[j];
    }
    if (blockIdx.x == 0 && tid == 0) offs[n] = bsum[(n + SCAN_CHUNK - 1) / SCAN_CHUNK];
}

__global__ void scat_kernel(const int* __restrict__ r0, const int* __restrict__ c0, int E0,
                            const int* __restrict__ r1, const int* __restrict__ c1, int E1,
                            const int* __restrict__ r2, const int* __restrict__ c2, int E2,
                            int base1, int base2,
                            int* __restrict__ cur, int* __restrict__ scols) {
    int t = blockIdx.x * blockDim.x + threadIdx.x;
    int row, col;
    if (t < E0) { row = __ldg(r0 + t); col = __ldg(c0 + t); }
    else if ((t -= E0) < E1) { row = __ldg(r1 + t); col = __ldg(c1 + t) + base1; }
    else if ((t -= E1) < E2) { row = __ldg(r2 + t); col = __ldg(c2 + t) + base2; }
    else return;
    int p = atomicAdd(&cur[row], 1);
    scols[p] = col;
}

// ---------------- aggregate: one warp per row, half-warp per edge ----------------
__device__ __forceinline__ float fsig(float s) {
    return 1.0f / (1.0f + __expf(-s));
}

// half-warp lane hl (0-15) accumulates cols hl*8..hl*8+7 for edge c
__device__ __forceinline__ void gacc16(int c, float sv, int hl,
                                       const __half* __restrict__ g, float acc[8]) {
    uint4 u = __ldg((const uint4*)(g + (size_t)c * D) + hl);
    float2 f0 = __half22float2(*reinterpret_cast<__half2*>(&u.x));
    float2 f1 = __half22float2(*reinterpret_cast<__half2*>(&u.y));
    float2 f2 = __half22float2(*reinterpret_cast<__half2*>(&u.z));
    float2 f3 = __half22float2(*reinterpret_cast<__half2*>(&u.w));
    acc[0] += sv * f0.x; acc[1] += sv * f0.y;
    acc[2] += sv * f1.x; acc[3] += sv * f1.y;
    acc[4] += sv * f2.x; acc[5] += sv * f2.y;
    acc[6] += sv * f3.x; acc[7] += sv * f3.y;
}

__global__ __launch_bounds__(256)
void agg_kernel(const int* __restrict__ offs, const int* __restrict__ scols,
                const __half* __restrict__ g, const float* __restrict__ a2,
                const float* __restrict__ a1, float* __restrict__ out, int n0) {
    int row = blockIdx.x * 8 + (threadIdx.x >> 5);
    if (row >= n0) return;
    int lane = threadIdx.x & 31;
    int hw = lane >> 4;        // half-warp id 0/1
    int hl = lane & 15;        // lane within half-warp
    float va1 = __ldg(a1 + row);
    float acc[8];
#pragma unroll
    for (int j = 0; j < 8; j++) acc[j] = 0.f;
    int s = __ldg(offs + row), e = __ldg(offs + row + 1);
    // half-warp hw handles edges s+hw, s+hw+2, ... (2-deep unroll -> 4 chains/warp)
    int i = s + hw;
    for (; i + 2 < e; i += 4) {
        int ca = __ldg(scols + i);
        int cb = __ldg(scols + i + 2);
        float sa = fsig(va1 + __ldg(a2 + ca));
        float sb = fsig(va1 + __ldg(a2 + cb));
        gacc16(ca, sa, hl, g, acc);
        gacc16(cb, sb, hl, g, acc);
    }
    for (; i < e; i += 2) {
        int ca = __ldg(scols + i);
        gacc16(ca, fsig(va1 + __ldg(a2 + ca)), hl, g, acc);
    }
    // merge the two half-warp accumulators into lanes 0-15
#pragma unroll
    for (int j = 0; j < 8; j++) acc[j] += __shfl_down_sync(0xffffffffu, acc[j], 16);
    if (hw == 0) {
        float4* op = (float4*)(out + (size_t)row * D + hl * 8);
        float4 c0 = op[0], c1 = op[1];
        c0.x += acc[0]; c0.y += acc[1]; c0.z += acc[2]; c0.w += acc[3];
        c1.x += acc[4]; c1.y += acc[5]; c1.z += acc[6]; c1.w += acc[7];
        op[0] = c0;
        op[1] = c1;
    }
}

// ---------------- launch ----------------
extern "C" void kernel_launch(void* const* d_in, const int* in_sizes, int n_in,
                              void* d_out, int out_size) {
    const float* x0   = (const float*)d_in[0];
    const float* x1   = (const float*)d_in[1];
    const float* x2   = (const float*)d_in[2];
    const float* W1   = (const float*)d_in[3];
    const float* b1   = (const float*)d_in[4];
    const float* a1w  = (const float*)d_in[5];
    const float* a1b  = (const float*)d_in[6];
    const float* a2w  = (const float*)d_in[7];
    const float* a2b  = (const float*)d_in[8];
    const float* Wagg = (const float*)d_in[9];
    const float* bagg = (const float*)d_in[10];
    const int* ar0 = (const int*)d_in[11];
    const int* ac0 = (const int*)d_in[12];
    const int* ar1 = (const int*)d_in[13];
    const int* ac1 = (const int*)d_in[14];
    const int* ar2 = (const int*)d_in[15];
    const int* ac2 = (const int*)d_in[16];
    float* out = (float*)d_out;

    const int N0 = in_sizes[0] / D;
    const int N1 = in_sizes[1] / D;
    const int N2 = in_sizes[2] / D;
    const int E0 = in_sizes[11];
    const int E1 = in_sizes[13];
    const int E2 = in_sizes[15];

    __half* pg;
    float *pa2, *pa1;
    int *pcnt, *poff, *pcur, *pscols, *pbsum;
    unsigned char* pwp;
    cudaGetSymbolAddress((void**)&pg, g_gall);
    cudaGetSymbolAddress((void**)&pa2, g_a2all);
    cudaGetSymbolAddress((void**)&pa1, g_a1_0);
    cudaGetSymbolAddress((void**)&pcnt, g_cnt);
    cudaGetSymbolAddress((void**)&poff, g_off);
    cudaGetSymbolAddress((void**)&pcur, g_cur);
    cudaGetSymbolAddress((void**)&pscols, g_scols);
    cudaGetSymbolAddress((void**)&pwp, g_wprep);
    cudaGetSymbolAddress((void**)&pbsum, g_bsum);

    cudaFuncSetAttribute(node_mm, cudaFuncAttributeMaxDynamicSharedMemorySize, SMEM_REQ);

    #define WHI(m) (pwp + (size_t)(m) * 2 * 32768)
    #define WLO(m) (pwp + (size_t)(m) * 2 * 32768 + 32768)

    prep_w<<<5, 256>>>(W1, Wagg, pwp);
    zero_kernel<<<(N0 + 256) / 256, 256>>>(pcnt, N0 + 1);
    const int ET = E0 + E1 + E2;
    hist_kernel<<<(ET + 255) / 256, 256>>>(ar0, E0, ar1, E1, ar2, E2, pcnt);
    const int NB = (N0 + SCAN_CHUNK - 1) / SCAN_CHUNK;
    scanA_kernel<<<NB, 1024>>>(pcnt, N0, pbsum);
    scanB_kernel<<<1, 32>>>(pbsum, NB);
    scanC_kernel<<<NB, 1024>>>(pcnt, N0, pbsum, poff, pcur);
    scat_kernel<<<(ET + 255) / 256, 256>>>(ar0, ac0, E0, ar1, ac1, E1, ar2, ac2, E2,
                                           N0, N0 + N1, pcur, pscols);

    node_mm<<<(N0 + 127) / 128, 256, SMEM_REQ>>>(
        x0, N0, WHI(0), WLO(0), WHI(2), WLO(2), WHI(1), WLO(1),
        b1, a1w, a1b, a2w, a2b, bagg,
        pg, pa1, pa2, out);
    node_mm<<<(N1 + 127) / 128, 256, SMEM_REQ>>>(
        x1, N1, WHI(0), WLO(0), WHI(3), WLO(3), nullptr, nullptr,
        b1, a1w, a1b, a2w, a2b, bagg,
        pg + (size_t)N0 * D, nullptr, pa2 + N0, nullptr);
    node_mm<<<(N2 + 127) / 128, 256, SMEM_REQ>>>(
        x2, N2, WHI(0), WLO(0), WHI(4), WLO(4), nullptr, nullptr,
        b1, a1w, a1b, a2w, a2b, bagg,
        pg + (size_t)(N0 + N1) * D, nullptr, pa2 + N0 + N1, nullptr);

    agg_kernel<<<(N0 + 7) / 8, 256>>>(poff, pscols, pg, pa2, pa1, out, N0);
}

// round 11
// speedup vs baseline: 2.8039x; 1.1760x over previous
#include <cuda_runtime.h>
#include <cuda_fp16.h>
#include <cstdint>

#define D 128
#define N0MAX 100000
#define NALL  (100000 + 150000 + 80000)
#define EALL  3000000
#define SCAN_CHUNK 4096
#define SCAN_BLOCKS ((N0MAX + SCAN_CHUNK - 1) / SCAN_CHUNK)

typedef unsigned long long ull;
typedef unsigned int u32;

// ---------------- static scratch (allocation-free rule) ----------------
__device__ __half g_gall[(size_t)NALL * 128];   // fp16 projected features, concat [g0|g1|g2]
__device__ float g_a2all[NALL];                 // concat [a2_0|a2_1|a2_2]
__device__ float g_a1_0[N0MAX];
// prepped weights: 5 matrices (W1, Wagg0..3) x {hi,lo} x 32KB fp16 tiles,
// transposed to [n][k], 16B-chunk XOR-swizzled (ldmatrix-ready, raw smem copy)
__device__ unsigned char g_wprep[5 * 2 * 32768];
// combined CSR scratch
__device__ int g_cnt[N0MAX + 1];
__device__ int g_off[N0MAX + 1];
__device__ int g_cur[N0MAX];
__device__ int g_scols[EALL];
__device__ int g_bsum[SCAN_BLOCKS + 1];

__device__ __forceinline__ u32 smem_to_u32(const void* p) {
    u32 a;
    asm("{ .reg .u64 t; cvta.to.shared.u64 t, %1; cvt.u32.u64 %0, t; }" : "=r"(a) : "l"(p));
    return a;
}

// byte offset of 16B chunk (row, kc) in a 128x128 fp16 tile (256B rows),
// XOR swizzle on chunk index by row&7 -> conflict-free ldmatrix + staging
#define CH(row, kc) ((u32)((row) * 256 + ((((kc)) ^ ((row) & 7)) << 4)))

// split 8 fp32 -> fp16 hi + fp16 lo packed uint4 (16B each)
__device__ __forceinline__ void split8h(const float* v, uint4& hi, uint4& lo) {
    u32 hw[4], lw[4];
#pragma unroll
    for (int j = 0; j < 4; j++) {
        float a = v[2 * j], b = v[2 * j + 1];
        __half ah = __float2half_rn(a), bh = __float2half_rn(b);
        float ar = a - __half2float(ah), br = b - __half2float(bh);
        __half2 hh = __halves2half2(ah, bh);
        __half2 ll = __floats2half2_rn(ar, br);
        hw[j] = *(u32*)&hh;
        lw[j] = *(u32*)&ll;
    }
    hi = make_uint4(hw[0], hw[1], hw[2], hw[3]);
    lo = make_uint4(lw[0], lw[1], lw[2], lw[3]);
}

// ---------------- weight prep: transpose + fp16 split + swizzle ----------------
__global__ void prep_w(const float* __restrict__ W1, const float* __restrict__ Wagg,
                       unsigned char* __restrict__ wp) {
    int m = blockIdx.x, tid = threadIdx.x;
    unsigned char* hip = wp + (size_t)m * 2 * 32768;
    unsigned char* lop = hip + 32768;
#pragma unroll 1
    for (int it = 0; it < 8; it++) {
        int f = tid + it * 256;           // chunk id 0..2047
        int n = f >> 4, kc = f & 15, k0 = kc * 8;
        float v[8];
#pragma unroll
        for (int j = 0; j < 8; j++) {
            int k = k0 + j;
            v[j] = (m == 0) ? W1[k * 128 + n] : Wagg[((m - 1) * 128 + k) * 128 + n];
        }
        uint4 hi, lo;
        split8h(v, hi, lo);
        u32 ad = CH(n, kc);
        *(uint4*)(hip + ad) = hi;
        *(uint4*)(lop + ad) = lo;
    }
}

// ---------------- node kernel (mma.sync m16n8k16 fp16, 3-pass split) ----------
// smem: A_hi | A_lo | W (single, phased hi->lo) | header  => 100KB, 2 CTAs/SM
#define OFF_A_HI 0
#define OFF_A_LO 32768
#define OFF_W    65536
#define OFF_HDR  98304
#define SMEM_REQ (98304 + 3072 + 1024)

__device__ __forceinline__ void copy32k(void* dst, const void* src, int tid) {
    const uint4* s = (const uint4*)src;
    uint4* d = (uint4*)dst;
#pragma unroll
    for (int i = 0; i < 8; i++) d[tid + i * 256] = s[tid + i * 256];
}

// one split-pass (8 k-steps) of the 128x128 GEMM for this warp
__device__ __forceinline__ void gemm_pass(u32 Ab, u32 Wb, int r0, int cbase, int lane,
                                          bool clear, float c[2][8][4]) {
    const int q = lane >> 3, sr = lane & 7;
    if (clear) {
#pragma unroll
        for (int mt = 0; mt < 2; mt++)
#pragma unroll
            for (int nt = 0; nt < 8; nt++)
#pragma unroll
                for (int j = 0; j < 4; j++) c[mt][nt][j] = 0.f;
    }
#pragma unroll 1
    for (int ks = 0; ks < 8; ks++) {
        u32 a[2][4];
#pragma unroll
        for (int mt = 0; mt < 2; mt++) {
            int row = r0 + mt * 16 + ((q & 1) << 3) + sr;
            int kc = 2 * ks + (q >> 1);
            u32 ad = Ab + CH(row, kc);
            asm volatile("ldmatrix.sync.aligned.m8n8.x4.shared.b16 {%0,%1,%2,%3}, [%4];"
                         : "=r"(a[mt][0]), "=r"(a[mt][1]), "=r"(a[mt][2]), "=r"(a[mt][3])
                         : "r"(ad));
        }
        u32 b[8][2];
#pragma unroll
        for (int nb = 0; nb < 4; nb++) {
            int rown = cbase + nb * 16 + ((q >> 1) << 3) + sr;
            int kc = 2 * ks + (q & 1);
            u32 ad = Wb + CH(rown, kc);
            asm volatile("ldmatrix.sync.aligned.m8n8.x4.shared.b16 {%0,%1,%2,%3}, [%4];"
                         : "=r"(b[2 * nb][0]), "=r"(b[2 * nb][1]),
                           "=r"(b[2 * nb + 1][0]), "=r"(b[2 * nb + 1][1])
                         : "r"(ad));
        }
#pragma unroll
        for (int mt = 0; mt < 2; mt++)
#pragma unroll
            for (int nt = 0; nt < 8; nt++)
                asm volatile("mma.sync.aligned.m16n8k16.row.col.f32.f16.f16.f32 "
                             "{%0,%1,%2,%3}, {%4,%5,%6,%7}, {%8,%9}, {%0,%1,%2,%3};"
                             : "+f"(c[mt][nt][0]), "+f"(c[mt][nt][1]),
                               "+f"(c[mt][nt][2]), "+f"(c[mt][nt][3])
                             : "r"(a[mt][0]), "r"(a[mt][1]), "r"(a[mt][2]), "r"(a[mt][3]),
                               "r"(b[nt][0]), "r"(b[nt][1]));
    }
}

__global__ __launch_bounds__(256, 2)
void node_mm(const float* __restrict__ x, int nrows,
             const unsigned char* __restrict__ w1h, const unsigned char* __restrict__ w1l,
             const unsigned char* __restrict__ wgh, const unsigned char* __restrict__ wgl,
             const unsigned char* __restrict__ wsh, const unsigned char* __restrict__ wsl,
             const float* __restrict__ b1,
             const float* __restrict__ a1w, const float* __restrict__ a1bp,
             const float* __restrict__ a2w, const float* __restrict__ a2bp,
             const float* __restrict__ bagg,
             __half* __restrict__ gout, float* __restrict__ a1out,
             float* __restrict__ a2out, float* __restrict__ selfout) {
    extern __shared__ char sraw[];
    const u32 sb = smem_to_u32(sraw);
    const u32 base = (sb + 1023u) & ~1023u;
    char* bp = sraw + (base - sb);
    float* sBB  = (float*)(bp + OFF_HDR);
    float* sAW1 = sBB + 128;
    float* sAW2 = sAW1 + 128;
    float* sBG  = sAW2 + 128;
    float* sPA1 = sBG + 128;
    float* sPA2 = sPA1 + 128;

    const int tid = threadIdx.x, wid = tid >> 5, lane = tid & 31;
    const int wm = wid & 3, wn = wid >> 2;
    const int r0 = wm * 32, cbase = wn * 64;
    const int rbase = blockIdx.x * 128;
    const u32 aHi = base + OFF_A_HI, aLo = base + OFF_A_LO;
    const u32 sW = base + OFF_W;

    if (tid < 128) {
        sBB[tid] = b1[tid];
        sAW1[tid] = a1w[tid];
        sAW2[tid] = a2w[tid];
        sBG[tid] = bagg[tid];
    }
    copy32k(bp + OFF_W, w1h, tid);
#pragma unroll 1
    for (int it = 0; it < 8; it++) {
        int f = tid + it * 256;
        int row = f >> 4, kc = f & 15;
        float v[8];
        if (rbase + row < nrows) {
            const float4* xp = (const float4*)(x + (size_t)(rbase + row) * 128 + kc * 8);
            float4 p0 = xp[0], p1 = xp[1];
            v[0] = p0.x; v[1] = p0.y; v[2] = p0.z; v[3] = p0.w;
            v[4] = p1.x; v[5] = p1.y; v[6] = p1.z; v[7] = p1.w;
        } else {
#pragma unroll
            for (int j = 0; j < 8; j++) v[j] = 0.f;
        }
        uint4 hi, lo;
        split8h(v, hi, lo);
        u32 ad = CH(row, kc);
        *(uint4*)(bp + OFF_A_HI + ad) = hi;
        *(uint4*)(bp + OFF_A_LO + ad) = lo;
    }
    __syncthreads();

    float c[2][8][4];
    float pph1[4], pph2[4];

    // ---- GEMM1: h = x @ W1^T  (passes: aHi*W1hi, aLo*W1hi, then W<-W1lo, aHi*W1lo) ----
    gemm_pass(aHi, sW, r0, cbase, lane, true, c);
    gemm_pass(aLo, sW, r0, cbase, lane, false, c);
    __syncthreads();
    copy32k(bp + OFF_W, w1l, tid);
    __syncthreads();
    gemm_pass(aHi, sW, r0, cbase, lane, false, c);
    __syncthreads();   // all warps done reading sA(x) and sW before overwrite

    // epilogue 1: bias+relu, attention dots, h -> sA fp16 hi/lo
#pragma unroll
    for (int mt = 0; mt < 2; mt++)
#pragma unroll
        for (int half = 0; half < 2; half++) {
            int row = r0 + mt * 16 + half * 8 + (lane >> 2);
            float ph1 = 0.f, ph2 = 0.f;
#pragma unroll
            for (int nt = 0; nt < 8; nt++) {
                int col = cbase + nt * 8 + 2 * (lane & 3);
                float h0 = fmaxf(c[mt][nt][half * 2 + 0] + sBB[col], 0.f);
                float h1 = fmaxf(c[mt][nt][half * 2 + 1] + sBB[col + 1], 0.f);
                ph1 += h0 * sAW1[col] + h1 * sAW1[col + 1];
                ph2 += h0 * sAW2[col] + h1 * sAW2[col + 1];
                __half hh0 = __float2half_rn(h0), hh1 = __float2half_rn(h1);
                __half2 hhi = __halves2half2(hh0, hh1);
                __half2 hlo = __floats2half2_rn(h0 - __half2float(hh0),
                                                h1 - __half2float(hh1));
                u32 ao = (u32)(row * 256 + (((col >> 3) ^ (row & 7)) << 4) + (col & 7) * 2);
                *(u32*)(bp + OFF_A_HI + ao) = *(u32*)&hhi;
                *(u32*)(bp + OFF_A_LO + ao) = *(u32*)&hlo;
            }
            ph1 += __shfl_xor_sync(0xffffffffu, ph1, 1);
            ph1 += __shfl_xor_sync(0xffffffffu, ph1, 2);
            ph2 += __shfl_xor_sync(0xffffffffu, ph2, 1);
            ph2 += __shfl_xor_sync(0xffffffffu, ph2, 2);
            pph1[mt * 2 + half] = ph1;
            pph2[mt * 2 + half] = ph2;
            if (wn == 0 && (lane & 3) == 0) {
                sPA1[row] = ph1;
                sPA2[row] = ph2;
            }
        }
    copy32k(bp + OFF_W, wgh, tid);   // stage Wg hi (safe: post-GEMM1 barrier above)
    __syncthreads();
    if (wn == 1 && (lane & 3) == 0) {
        const float a1b = *a1bp, a2b = *a2bp;
#pragma unroll
        for (int mt = 0; mt < 2; mt++)
#pragma unroll
            for (int half = 0; half < 2; half++) {
                int row = r0 + mt * 16 + half * 8 + (lane >> 2);
                int grow = rbase + row;
                if (grow < nrows) {
                    if (a1out) a1out[grow] = sPA1[row] + pph1[mt * 2 + half] + a1b;
                    a2out[grow] = sPA2[row] + pph2[mt * 2 + half] + a2b;
                }
            }
    }

    // ---- GEMM2: g = h @ Wg^T -> fp16 global ----
    gemm_pass(aHi, sW, r0, cbase, lane, true, c);
    gemm_pass(aLo, sW, r0, cbase, lane, false, c);
    __syncthreads();
    copy32k(bp + OFF_W, wgl, tid);
    __syncthreads();
    gemm_pass(aHi, sW, r0, cbase, lane, false, c);
#pragma unroll
    for (int mt = 0; mt < 2; mt++)
#pragma unroll
        for (int half = 0; half < 2; half++) {
            int row = r0 + mt * 16 + half * 8 + (lane >> 2);
            int grow = rbase + row;
            if (grow < nrows) {
#pragma unroll
                for (int nt = 0; nt < 8; nt++) {
                    int col = cbase + nt * 8 + 2 * (lane & 3);
                    __half2 hv = __floats2half2_rn(c[mt][nt][half * 2 + 0],
                                                   c[mt][nt][half * 2 + 1]);
                    *(u32*)(gout + (size_t)grow * D + col) = *(u32*)&hv;
                }
            }
        }

    // ---- GEMM3 (x0 only): self = h @ Wself^T + bagg -> out ----
    if (wsh) {
        __syncthreads();   // all warps done reading sW(Wg lo)
        copy32k(bp + OFF_W, wsh, tid);
        __syncthreads();
        gemm_pass(aHi, sW, r0, cbase, lane, true, c);
        gemm_pass(aLo, sW, r0, cbase, lane, false, c);
        __syncthreads();
        copy32k(bp + OFF_W, wsl, tid);
        __syncthreads();
        gemm_pass(aHi, sW, r0, cbase, lane, false, c);
#pragma unroll
        for (int mt = 0; mt < 2; mt++)
#pragma unroll
            for (int half = 0; half < 2; half++) {
                int row = r0 + mt * 16 + half * 8 + (lane >> 2);
                int grow = rbase + row;
                if (grow < nrows) {
#pragma unroll
                    for (int nt = 0; nt < 8; nt++) {
                        int col = cbase + nt * 8 + 2 * (lane & 3);
                        float2 v = make_float2(c[mt][nt][half * 2 + 0] + sBG[col],
                                               c[mt][nt][half * 2 + 1] + sBG[col + 1]);
                        *(float2*)(selfout + (size_t)grow * D + col) = v;
                    }
                }
            }
    }
}

// ---------------- binning kernels (combined CSR over all 3 lists) ----------------
__global__ void zero_kernel(int* p, int n) {
    int i = blockIdx.x * blockDim.x + threadIdx.x;
    if (i < n) p[i] = 0;
}

__global__ void hist_kernel(const int* __restrict__ r0, int E0,
                            const int* __restrict__ r1, int E1,
                            const int* __restrict__ r2, int E2,
                            int* __restrict__ cnt) {
    int t = blockIdx.x * blockDim.x + threadIdx.x;
    int row;
    if (t < E0) row = __ldg(r0 + t);
    else if ((t -= E0) < E1) row = __ldg(r1 + t);
    else if ((t -= E1) < E2) row = __ldg(r2 + t);
    else return;
    atomicAdd(&cnt[row], 1);
}

// ---- parallel scan phase A: per-block sums of 4096-element chunks ----
__global__ __launch_bounds__(1024)
void scanA_kernel(const int* __restrict__ cnt, int n, int* __restrict__ bsum) {
    __shared__ int wsum[32];
    const int tid = threadIdx.x, lane = tid & 31, wid = tid >> 5;
    int idx = blockIdx.x * SCAN_CHUNK + tid * 4;
    int s = 0;
#pragma unroll
    for (int j = 0; j < 4; j++) s += (idx + j < n) ? cnt[idx + j] : 0;
#pragma unroll
    for (int off = 16; off >= 1; off >>= 1) s += __shfl_down_sync(0xffffffffu, s, off);
    if (lane == 0) wsum[wid] = s;
    __syncthreads();
    if (wid == 0) {
        int y = wsum[lane];
#pragma unroll
        for (int off = 16; off >= 1; off >>= 1) y += __shfl_down_sync(0xffffffffu, y, off);
        if (lane == 0) bsum[blockIdx.x] = y;
    }
}

// ---- phase B: exclusive scan of block sums (1 warp) ----
__global__ void scanB_kernel(int* __restrict__ bsum, int nb) {
    int lane = threadIdx.x;
    int v = (lane < nb) ? bsum[lane] : 0;
    int x = v;
#pragma unroll
    for (int off = 1; off < 32; off <<= 1) {
        int t = __shfl_up_sync(0xffffffffu, x, off);
        if (lane >= off) x += t;
    }
    if (lane <= nb && lane < 32) bsum[lane] = x - v;   // exclusive
    if (lane == 31) bsum[nb] = x;   // total (nb<=25<32)
}

// ---- phase C: per-block exclusive scan + block offset -> offs, cur ----
__global__ __launch_bounds__(1024)
void scanC_kernel(const int* __restrict__ cnt, int n, const int* __restrict__ bsum,
                  int* __restrict__ offs, int* __restrict__ cur) {
    __shared__ int wsum[32];
    const int tid = threadIdx.x, lane = tid & 31, wid = tid >> 5;
    int idx = blockIdx.x * SCAN_CHUNK + tid * 4;
    int v[4];
#pragma unroll
    for (int j = 0; j < 4; j++) v[j] = (idx + j < n) ? cnt[idx + j] : 0;
    int tsum = v[0] + v[1] + v[2] + v[3];
    int xv = tsum;
#pragma unroll
    for (int off = 1; off < 32; off <<= 1) {
        int t = __shfl_up_sync(0xffffffffu, xv, off);
        if (lane >= off) xv += t;
    }
    if (lane == 31) wsum[wid] = xv;
    __syncthreads();
    if (wid == 0) {
        int y = wsum[lane];
#pragma unroll
        for (int off = 1; off < 32; off <<= 1) {
            int t = __shfl_up_sync(0xffffffffu, y, off);
            if (lane >= off) y += t;
        }
        wsum[lane] = y;
    }
    __syncthreads();
    int warpoff = (wid == 0) ? 0 : wsum[wid - 1];
    int excl = bsum[blockIdx.x] + warpoff + xv - tsum;
#pragma unroll
    for (int j = 0; j < 4; j++) {
        if (idx + j < n) { offs[idx + j] = excl; cur[idx + j] = excl; }
        excl += v[j];
    }
    if (blockIdx.x == 0 && tid == 0) offs[n] = bsum[(n + SCAN_CHUNK - 1) / SCAN_CHUNK];
}

__global__ void scat_kernel(const int* __restrict__ r0, const int* __restrict__ c0, int E0,
                            const int* __restrict__ r1, const int* __restrict__ c1, int E1,
                            const int* __restrict__ r2, const int* __restrict__ c2, int E2,
                            int base1, int base2,
                            int* __restrict__ cur, int* __restrict__ scols) {
    int t = blockIdx.x * blockDim.x + threadIdx.x;
    int row, col;
    if (t < E0) { row = __ldg(r0 + t); col = __ldg(c0 + t); }
    else if ((t -= E0) < E1) { row = __ldg(r1 + t); col = __ldg(c1 + t) + base1; }
    else if ((t -= E1) < E2) { row = __ldg(r2 + t); col = __ldg(c2 + t) + base2; }
    else return;
    int p = atomicAdd(&cur[row], 1);
    scols[p] = col;
}

// ---------------- aggregate: one warp per row, half-warp per edge ----------------
__device__ __forceinline__ float fsig(float s) {
    return 1.0f / (1.0f + __expf(-s));
}

// half-warp lane hl (0-15) accumulates cols hl*8..hl*8+7 for edge c
__device__ __forceinline__ void gacc16(int c, float sv, int hl,
                                       const __half* __restrict__ g, float acc[8]) {
    uint4 u = __ldg((const uint4*)(g + (size_t)c * D) + hl);
    float2 f0 = __half22float2(*reinterpret_cast<__half2*>(&u.x));
    float2 f1 = __half22float2(*reinterpret_cast<__half2*>(&u.y));
    float2 f2 = __half22float2(*reinterpret_cast<__half2*>(&u.z));
    float2 f3 = __half22float2(*reinterpret_cast<__half2*>(&u.w));
    acc[0] += sv * f0.x; acc[1] += sv * f0.y;
    acc[2] += sv * f1.x; acc[3] += sv * f1.y;
    acc[4] += sv * f2.x; acc[5] += sv * f2.y;
    acc[6] += sv * f3.x; acc[7] += sv * f3.y;
}

__global__ __launch_bounds__(256)
void agg_kernel(const int* __restrict__ offs, const int* __restrict__ scols,
                const __half* __restrict__ g, const float* __restrict__ a2,
                const float* __restrict__ a1, float* __restrict__ out, int n0) {
    int row = blockIdx.x * 8 + (threadIdx.x >> 5);
    if (row >= n0) return;
    int lane = threadIdx.x & 31;
    int hw = lane >> 4;        // half-warp id 0/1
    int hl = lane & 15;        // lane within half-warp
    float va1 = __ldg(a1 + row);
    float acc[8];
#pragma unroll
    for (int j = 0; j < 8; j++) acc[j] = 0.f;
    int s = __ldg(offs + row), e = __ldg(offs + row + 1);
    int i = s + hw;
    for (; i + 2 < e; i += 4) {
        int ca = __ldg(scols + i);
        int cb = __ldg(scols + i + 2);
        float sa = fsig(va1 + __ldg(a2 + ca));
        float sb = fsig(va1 + __ldg(a2 + cb));
        gacc16(ca, sa, hl, g, acc);
        gacc16(cb, sb, hl, g, acc);
    }
    for (; i < e; i += 2) {
        int ca = __ldg(scols + i);
        gacc16(ca, fsig(va1 + __ldg(a2 + ca)), hl, g, acc);
    }
#pragma unroll
    for (int j = 0; j < 8; j++) acc[j] += __shfl_down_sync(0xffffffffu, acc[j], 16);
    if (hw == 0) {
        float4* op = (float4*)(out + (size_t)row * D + hl * 8);
        float4 c0 = op[0], c1 = op[1];
        c0.x += acc[0]; c0.y += acc[1]; c0.z += acc[2]; c0.w += acc[3];
        c1.x += acc[4]; c1.y += acc[5]; c1.z += acc[6]; c1.w += acc[7];
        op[0] = c0;
        op[1] = c1;
    }
}

// ---------------- launch ----------------
extern "C" void kernel_launch(void* const* d_in, const int* in_sizes, int n_in,
                              void* d_out, int out_size) {
    const float* x0   = (const float*)d_in[0];
    const float* x1   = (const float*)d_in[1];
    const float* x2   = (const float*)d_in[2];
    const float* W1   = (const float*)d_in[3];
    const float* b1   = (const float*)d_in[4];
    const float* a1w  = (const float*)d_in[5];
    const float* a1b  = (const float*)d_in[6];
    const float* a2w  = (const float*)d_in[7];
    const float* a2b  = (const float*)d_in[8];
    const float* Wagg = (const float*)d_in[9];
    const float* bagg = (const float*)d_in[10];
    const int* ar0 = (const int*)d_in[11];
    const int* ac0 = (const int*)d_in[12];
    const int* ar1 = (const int*)d_in[13];
    const int* ac1 = (const int*)d_in[14];
    const int* ar2 = (const int*)d_in[15];
    const int* ac2 = (const int*)d_in[16];
    float* out = (float*)d_out;

    const int N0 = in_sizes[0] / D;
    const int N1 = in_sizes[1] / D;
    const int N2 = in_sizes[2] / D;
    const int E0 = in_sizes[11];
    const int E1 = in_sizes[13];
    const int E2 = in_sizes[15];

    __half* pg;
    float *pa2, *pa1;
    int *pcnt, *poff, *pcur, *pscols, *pbsum;
    unsigned char* pwp;
    cudaGetSymbolAddress((void**)&pg, g_gall);
    cudaGetSymbolAddress((void**)&pa2, g_a2all);
    cudaGetSymbolAddress((void**)&pa1, g_a1_0);
    cudaGetSymbolAddress((void**)&pcnt, g_cnt);
    cudaGetSymbolAddress((void**)&poff, g_off);
    cudaGetSymbolAddress((void**)&pcur, g_cur);
    cudaGetSymbolAddress((void**)&pscols, g_scols);
    cudaGetSymbolAddress((void**)&pwp, g_wprep);
    cudaGetSymbolAddress((void**)&pbsum, g_bsum);

    cudaFuncSetAttribute(node_mm, cudaFuncAttributeMaxDynamicSharedMemorySize, SMEM_REQ);

    #define WHI(m) (pwp + (size_t)(m) * 2 * 32768)
    #define WLO(m) (pwp + (size_t)(m) * 2 * 32768 + 32768)

    prep_w<<<5, 256>>>(W1, Wagg, pwp);
    zero_kernel<<<(N0 + 256) / 256, 256>>>(pcnt, N0 + 1);
    const int ET = E0 + E1 + E2;
    hist_kernel<<<(ET + 255) / 256, 256>>>(ar0, E0, ar1, E1, ar2, E2, pcnt);
    const int NB = (N0 + SCAN_CHUNK - 1) / SCAN_CHUNK;
    scanA_kernel<<<NB, 1024>>>(pcnt, N0, pbsum);
    scanB_kernel<<<1, 32>>>(pbsum, NB);
    scanC_kernel<<<NB, 1024>>>(pcnt, N0, pbsum, poff, pcur);
    scat_kernel<<<(ET + 255) / 256, 256>>>(ar0, ac0, E0, ar1, ac1, E1, ar2, ac2, E2,
                                           N0, N0 + N1, pcur, pscols);

    node_mm<<<(N0 + 127) / 128, 256, SMEM_REQ>>>(
        x0, N0, WHI(0), WLO(0), WHI(2), WLO(2), WHI(1), WLO(1),
        b1, a1w, a1b, a2w, a2b, bagg,
        pg, pa1, pa2, out);
    node_mm<<<(N1 + 127) / 128, 256, SMEM_REQ>>>(
        x1, N1, WHI(0), WLO(0), WHI(3), WLO(3), nullptr, nullptr,
        b1, a1w, a1b, a2w, a2b, bagg,
        pg + (size_t)N0 * D, nullptr, pa2 + N0, nullptr);
    node_mm<<<(N2 + 127) / 128, 256, SMEM_REQ>>>(
        x2, N2, WHI(0), WLO(0), WHI(4), WLO(4), nullptr, nullptr,
        b1, a1w, a1b, a2w, a2b, bagg,
        pg + (size_t)(N0 + N1) * D, nullptr, pa2 + N0 + N1, nullptr);

    agg_kernel<<<(N0 + 7) / 8, 256>>>(poff, pscols, pg, pa2, pa1, out, N0);
}

// round 12
// speedup vs baseline: 3.1160x; 1.1113x over previous
#include <cuda_runtime.h>
#include <cuda_fp16.h>
#include <cstdint>

#define D 128
#define N0MAX 100000
#define NALL  (100000 + 150000 + 80000)
#define EALL  3000000
#define SCAN_CHUNK 4096
#define SCAN_BLOCKS ((N0MAX + SCAN_CHUNK - 1) / SCAN_CHUNK)

typedef unsigned long long ull;
typedef unsigned int u32;

// ---------------- static scratch (allocation-free rule) ----------------
__device__ __half g_gall[(size_t)NALL * 128];   // fp16 projected features, concat [g0|g1|g2]
__device__ float g_a2all[NALL];                 // concat [a2_0|a2_1|a2_2]
__device__ float g_a1_0[N0MAX];
// prepped weights: 5 matrices (W1, Wagg0..3) x {hi,lo} x 32KB fp16 tiles,
// transposed to [n][k], 16B-chunk XOR-swizzled (ldmatrix-ready, raw smem copy)
__device__ unsigned char g_wprep[5 * 2 * 32768];
// combined CSR scratch
__device__ int g_cnt[N0MAX + 1];
__device__ int g_off[N0MAX + 1];
__device__ int g_cur[N0MAX];
__device__ int2 g_sedge[EALL];                  // {col, sigmoid-weight bits} per binned edge
__device__ int g_bsum[SCAN_BLOCKS + 1];

__device__ __forceinline__ u32 smem_to_u32(const void* p) {
    u32 a;
    asm("{ .reg .u64 t; cvta.to.shared.u64 t, %1; cvt.u32.u64 %0, t; }" : "=r"(a) : "l"(p));
    return a;
}

// byte offset of 16B chunk (row, kc) in a 128x128 fp16 tile (256B rows),
// XOR swizzle on chunk index by row&7 -> conflict-free ldmatrix + staging
#define CH(row, kc) ((u32)((row) * 256 + ((((kc)) ^ ((row) & 7)) << 4)))

// split 8 fp32 -> fp16 hi + fp16 lo packed uint4 (16B each)
__device__ __forceinline__ void split8h(const float* v, uint4& hi, uint4& lo) {
    u32 hw[4], lw[4];
#pragma unroll
    for (int j = 0; j < 4; j++) {
        float a = v[2 * j], b = v[2 * j + 1];
        __half ah = __float2half_rn(a), bh = __float2half_rn(b);
        float ar = a - __half2float(ah), br = b - __half2float(bh);
        __half2 hh = __halves2half2(ah, bh);
        __half2 ll = __floats2half2_rn(ar, br);
        hw[j] = *(u32*)&hh;
        lw[j] = *(u32*)&ll;
    }
    hi = make_uint4(hw[0], hw[1], hw[2], hw[3]);
    lo = make_uint4(lw[0], lw[1], lw[2], lw[3]);
}

// ---------------- weight prep: transpose + fp16 split + swizzle ----------------
__global__ void prep_w(const float* __restrict__ W1, const float* __restrict__ Wagg,
                       unsigned char* __restrict__ wp) {
    int m = blockIdx.x, tid = threadIdx.x;
    unsigned char* hip = wp + (size_t)m * 2 * 32768;
    unsigned char* lop = hip + 32768;
#pragma unroll 1
    for (int it = 0; it < 8; it++) {
        int f = tid + it * 256;           // chunk id 0..2047
        int n = f >> 4, kc = f & 15, k0 = kc * 8;
        float v[8];
#pragma unroll
        for (int j = 0; j < 8; j++) {
            int k = k0 + j;
            v[j] = (m == 0) ? W1[k * 128 + n] : Wagg[((m - 1) * 128 + k) * 128 + n];
        }
        uint4 hi, lo;
        split8h(v, hi, lo);
        u32 ad = CH(n, kc);
        *(uint4*)(hip + ad) = hi;
        *(uint4*)(lop + ad) = lo;
    }
}

// ---------------- node kernel (mma.sync m16n8k16 fp16, 3-pass split) ----------
// smem: A_hi | A_lo | W (single, phased hi->lo) | header  => 100KB, 2 CTAs/SM
#define OFF_A_HI 0
#define OFF_A_LO 32768
#define OFF_W    65536
#define OFF_HDR  98304
#define SMEM_REQ (98304 + 3072 + 1024)

__device__ __forceinline__ void copy32k(void* dst, const void* src, int tid) {
    const uint4* s = (const uint4*)src;
    uint4* d = (uint4*)dst;
#pragma unroll
    for (int i = 0; i < 8; i++) d[tid + i * 256] = s[tid + i * 256];
}

// one split-pass (8 k-steps) of the 128x128 GEMM for this warp
__device__ __forceinline__ void gemm_pass(u32 Ab, u32 Wb, int r0, int cbase, int lane,
                                          bool clear, float c[2][8][4]) {
    const int q = lane >> 3, sr = lane & 7;
    if (clear) {
#pragma unroll
        for (int mt = 0; mt < 2; mt++)
#pragma unroll
            for (int nt = 0; nt < 8; nt++)
#pragma unroll
                for (int j = 0; j < 4; j++) c[mt][nt][j] = 0.f;
    }
#pragma unroll 1
    for (int ks = 0; ks < 8; ks++) {
        u32 a[2][4];
#pragma unroll
        for (int mt = 0; mt < 2; mt++) {
            int row = r0 + mt * 16 + ((q & 1) << 3) + sr;
            int kc = 2 * ks + (q >> 1);
            u32 ad = Ab + CH(row, kc);
            asm volatile("ldmatrix.sync.aligned.m8n8.x4.shared.b16 {%0,%1,%2,%3}, [%4];"
                         : "=r"(a[mt][0]), "=r"(a[mt][1]), "=r"(a[mt][2]), "=r"(a[mt][3])
                         : "r"(ad));
        }
        u32 b[8][2];
#pragma unroll
        for (int nb = 0; nb < 4; nb++) {
            int rown = cbase + nb * 16 + ((q >> 1) << 3) + sr;
            int kc = 2 * ks + (q & 1);
            u32 ad = Wb + CH(rown, kc);
            asm volatile("ldmatrix.sync.aligned.m8n8.x4.shared.b16 {%0,%1,%2,%3}, [%4];"
                         : "=r"(b[2 * nb][0]), "=r"(b[2 * nb][1]),
                           "=r"(b[2 * nb + 1][0]), "=r"(b[2 * nb + 1][1])
                         : "r"(ad));
        }
#pragma unroll
        for (int mt = 0; mt < 2; mt++)
#pragma unroll
            for (int nt = 0; nt < 8; nt++)
                asm volatile("mma.sync.aligned.m16n8k16.row.col.f32.f16.f16.f32 "
                             "{%0,%1,%2,%3}, {%4,%5,%6,%7}, {%8,%9}, {%0,%1,%2,%3};"
                             : "+f"(c[mt][nt][0]), "+f"(c[mt][nt][1]),
                               "+f"(c[mt][nt][2]), "+f"(c[mt][nt][3])
                             : "r"(a[mt][0]), "r"(a[mt][1]), "r"(a[mt][2]), "r"(a[mt][3]),
                               "r"(b[nt][0]), "r"(b[nt][1]));
    }
}

__global__ __launch_bounds__(256, 2)
void node_mm(const float* __restrict__ x, int nrows,
             const unsigned char* __restrict__ w1h, const unsigned char* __restrict__ w1l,
             const unsigned char* __restrict__ wgh, const unsigned char* __restrict__ wgl,
             const unsigned char* __restrict__ wsh, const unsigned char* __restrict__ wsl,
             const float* __restrict__ b1,
             const float* __restrict__ a1w, const float* __restrict__ a1bp,
             const float* __restrict__ a2w, const float* __restrict__ a2bp,
             const float* __restrict__ bagg,
             __half* __restrict__ gout, float* __restrict__ a1out,
             float* __restrict__ a2out, float* __restrict__ selfout) {
    extern __shared__ char sraw[];
    const u32 sb = smem_to_u32(sraw);
    const u32 base = (sb + 1023u) & ~1023u;
    char* bp = sraw + (base - sb);
    float* sBB  = (float*)(bp + OFF_HDR);
    float* sAW1 = sBB + 128;
    float* sAW2 = sAW1 + 128;
    float* sBG  = sAW2 + 128;
    float* sPA1 = sBG + 128;
    float* sPA2 = sPA1 + 128;

    const int tid = threadIdx.x, wid = tid >> 5, lane = tid & 31;
    const int wm = wid & 3, wn = wid >> 2;
    const int r0 = wm * 32, cbase = wn * 64;
    const int rbase = blockIdx.x * 128;
    const u32 aHi = base + OFF_A_HI, aLo = base + OFF_A_LO;
    const u32 sW = base + OFF_W;

    if (tid < 128) {
        sBB[tid] = b1[tid];
        sAW1[tid] = a1w[tid];
        sAW2[tid] = a2w[tid];
        sBG[tid] = bagg[tid];
    }
    copy32k(bp + OFF_W, w1h, tid);
#pragma unroll 1
    for (int it = 0; it < 8; it++) {
        int f = tid + it * 256;
        int row = f >> 4, kc = f & 15;
        float v[8];
        if (rbase + row < nrows) {
            const float4* xp = (const float4*)(x + (size_t)(rbase + row) * 128 + kc * 8);
            float4 p0 = xp[0], p1 = xp[1];
            v[0] = p0.x; v[1] = p0.y; v[2] = p0.z; v[3] = p0.w;
            v[4] = p1.x; v[5] = p1.y; v[6] = p1.z; v[7] = p1.w;
        } else {
#pragma unroll
            for (int j = 0; j < 8; j++) v[j] = 0.f;
        }
        uint4 hi, lo;
        split8h(v, hi, lo);
        u32 ad = CH(row, kc);
        *(uint4*)(bp + OFF_A_HI + ad) = hi;
        *(uint4*)(bp + OFF_A_LO + ad) = lo;
    }
    __syncthreads();

    float c[2][8][4];
    float pph1[4], pph2[4];

    // ---- GEMM1: h = x @ W1^T  (passes: aHi*W1hi, aLo*W1hi, then W<-W1lo, aHi*W1lo) ----
    gemm_pass(aHi, sW, r0, cbase, lane, true, c);
    gemm_pass(aLo, sW, r0, cbase, lane, false, c);
    __syncthreads();
    copy32k(bp + OFF_W, w1l, tid);
    __syncthreads();
    gemm_pass(aHi, sW, r0, cbase, lane, false, c);
    __syncthreads();   // all warps done reading sA(x) and sW before overwrite

    // epilogue 1: bias+relu, attention dots, h -> sA fp16 hi/lo
#pragma unroll
    for (int mt = 0; mt < 2; mt++)
#pragma unroll
        for (int half = 0; half < 2; half++) {
            int row = r0 + mt * 16 + half * 8 + (lane >> 2);
            float ph1 = 0.f, ph2 = 0.f;
#pragma unroll
            for (int nt = 0; nt < 8; nt++) {
                int col = cbase + nt * 8 + 2 * (lane & 3);
                float h0 = fmaxf(c[mt][nt][half * 2 + 0] + sBB[col], 0.f);
                float h1 = fmaxf(c[mt][nt][half * 2 + 1] + sBB[col + 1], 0.f);
                ph1 += h0 * sAW1[col] + h1 * sAW1[col + 1];
                ph2 += h0 * sAW2[col] + h1 * sAW2[col + 1];
                __half hh0 = __float2half_rn(h0), hh1 = __float2half_rn(h1);
                __half2 hhi = __halves2half2(hh0, hh1);
                __half2 hlo = __floats2half2_rn(h0 - __half2float(hh0),
                                                h1 - __half2float(hh1));
                u32 ao = (u32)(row * 256 + (((col >> 3) ^ (row & 7)) << 4) + (col & 7) * 2);
                *(u32*)(bp + OFF_A_HI + ao) = *(u32*)&hhi;
                *(u32*)(bp + OFF_A_LO + ao) = *(u32*)&hlo;
            }
            ph1 += __shfl_xor_sync(0xffffffffu, ph1, 1);
            ph1 += __shfl_xor_sync(0xffffffffu, ph1, 2);
            ph2 += __shfl_xor_sync(0xffffffffu, ph2, 1);
            ph2 += __shfl_xor_sync(0xffffffffu, ph2, 2);
            pph1[mt * 2 + half] = ph1;
            pph2[mt * 2 + half] = ph2;
            if (wn == 0 && (lane & 3) == 0) {
                sPA1[row] = ph1;
                sPA2[row] = ph2;
            }
        }
    copy32k(bp + OFF_W, wgh, tid);   // stage Wg hi (safe: post-GEMM1 barrier above)
    __syncthreads();
    if (wn == 1 && (lane & 3) == 0) {
        const float a1b = *a1bp, a2b = *a2bp;
#pragma unroll
        for (int mt = 0; mt < 2; mt++)
#pragma unroll
            for (int half = 0; half < 2; half++) {
                int row = r0 + mt * 16 + half * 8 + (lane >> 2);
                int grow = rbase + row;
                if (grow < nrows) {
                    if (a1out) a1out[grow] = sPA1[row] + pph1[mt * 2 + half] + a1b;
                    a2out[grow] = sPA2[row] + pph2[mt * 2 + half] + a2b;
                }
            }
    }

    // ---- GEMM2: g = h @ Wg^T -> fp16 global ----
    gemm_pass(aHi, sW, r0, cbase, lane, true, c);
    gemm_pass(aLo, sW, r0, cbase, lane, false, c);
    __syncthreads();
    copy32k(bp + OFF_W, wgl, tid);
    __syncthreads();
    gemm_pass(aHi, sW, r0, cbase, lane, false, c);
#pragma unroll
    for (int mt = 0; mt < 2; mt++)
#pragma unroll
        for (int half = 0; half < 2; half++) {
            int row = r0 + mt * 16 + half * 8 + (lane >> 2);
            int grow = rbase + row;
            if (grow < nrows) {
#pragma unroll
                for (int nt = 0; nt < 8; nt++) {
                    int col = cbase + nt * 8 + 2 * (lane & 3);
                    __half2 hv = __floats2half2_rn(c[mt][nt][half * 2 + 0],
                                                   c[mt][nt][half * 2 + 1]);
                    *(u32*)(gout + (size_t)grow * D + col) = *(u32*)&hv;
                }
            }
        }

    // ---- GEMM3 (x0 only): self = h @ Wself^T + bagg -> out ----
    if (wsh) {
        __syncthreads();   // all warps done reading sW(Wg lo)
        copy32k(bp + OFF_W, wsh, tid);
        __syncthreads();
        gemm_pass(aHi, sW, r0, cbase, lane, true, c);
        gemm_pass(aLo, sW, r0, cbase, lane, false, c);
        __syncthreads();
        copy32k(bp + OFF_W, wsl, tid);
        __syncthreads();
        gemm_pass(aHi, sW, r0, cbase, lane, false, c);
#pragma unroll
        for (int mt = 0; mt < 2; mt++)
#pragma unroll
            for (int half = 0; half < 2; half++) {
                int row = r0 + mt * 16 + half * 8 + (lane >> 2);
                int grow = rbase + row;
                if (grow < nrows) {
#pragma unroll
                    for (int nt = 0; nt < 8; nt++) {
                        int col = cbase + nt * 8 + 2 * (lane & 3);
                        float2 v = make_float2(c[mt][nt][half * 2 + 0] + sBG[col],
                                               c[mt][nt][half * 2 + 1] + sBG[col + 1]);
                        *(float2*)(selfout + (size_t)grow * D + col) = v;
                    }
                }
            }
    }
}

// ---------------- binning kernels (combined CSR over all 3 lists) ----------------
__global__ void zero_kernel(int* p, int n) {
    int i = blockIdx.x * blockDim.x + threadIdx.x;
    if (i < n) p[i] = 0;
}

__global__ void hist_kernel(const int* __restrict__ r0, int E0,
                            const int* __restrict__ r1, int E1,
                            const int* __restrict__ r2, int E2,
                            int* __restrict__ cnt) {
    int t = blockIdx.x * blockDim.x + threadIdx.x;
    int row;
    if (t < E0) row = __ldg(r0 + t);
    else if ((t -= E0) < E1) row = __ldg(r1 + t);
    else if ((t -= E1) < E2) row = __ldg(r2 + t);
    else return;
    atomicAdd(&cnt[row], 1);
}

// ---- parallel scan phase A: per-block sums of 4096-element chunks ----
__global__ __launch_bounds__(1024)
void scanA_kernel(const int* __restrict__ cnt, int n, int* __restrict__ bsum) {
    __shared__ int wsum[32];
    const int tid = threadIdx.x, lane = tid & 31, wid = tid >> 5;
    int idx = blockIdx.x * SCAN_CHUNK + tid * 4;
    int s = 0;
#pragma unroll
    for (int j = 0; j < 4; j++) s += (idx + j < n) ? cnt[idx + j] : 0;
#pragma unroll
    for (int off = 16; off >= 1; off >>= 1) s += __shfl_down_sync(0xffffffffu, s, off);
    if (lane == 0) wsum[wid] = s;
    __syncthreads();
    if (wid == 0) {
        int y = wsum[lane];
#pragma unroll
        for (int off = 16; off >= 1; off >>= 1) y += __shfl_down_sync(0xffffffffu, y, off);
        if (lane == 0) bsum[blockIdx.x] = y;
    }
}

// ---- phase B: exclusive scan of block sums (1 warp) ----
__global__ void scanB_kernel(int* __restrict__ bsum, int nb) {
    int lane = threadIdx.x;
    int v = (lane < nb) ? bsum[lane] : 0;
    int x = v;
#pragma unroll
    for (int off = 1; off < 32; off <<= 1) {
        int t = __shfl_up_sync(0xffffffffu, x, off);
        if (lane >= off) x += t;
    }
    if (lane <= nb && lane < 32) bsum[lane] = x - v;   // exclusive
    if (lane == 31) bsum[nb] = x;   // total (nb<=25<32)
}

// ---- phase C: per-block exclusive scan + block offset -> offs, cur ----
__global__ __launch_bounds__(1024)
void scanC_kernel(const int* __restrict__ cnt, int n, const int* __restrict__ bsum,
                  int* __restrict__ offs, int* __restrict__ cur) {
    __shared__ int wsum[32];
    const int tid = threadIdx.x, lane = tid & 31, wid = tid >> 5;
    int idx = blockIdx.x * SCAN_CHUNK + tid * 4;
    int v[4];
#pragma unroll
    for (int j = 0; j < 4; j++) v[j] = (idx + j < n) ? cnt[idx + j] : 0;
    int tsum = v[0] + v[1] + v[2] + v[3];
    int xv = tsum;
#pragma unroll
    for (int off = 1; off < 32; off <<= 1) {
        int t = __shfl_up_sync(0xffffffffu, xv, off);
        if (lane >= off) xv += t;
    }
    if (lane == 31) wsum[wid] = xv;
    __syncthreads();
    if (wid == 0) {
        int y = wsum[lane];
#pragma unroll
        for (int off = 1; off < 32; off <<= 1) {
            int t = __shfl_up_sync(0xffffffffu, y, off);
            if (lane >= off) y += t;
        }
        wsum[lane] = y;
    }
    __syncthreads();
    int warpoff = (wid == 0) ? 0 : wsum[wid - 1];
    int excl = bsum[blockIdx.x] + warpoff + xv - tsum;
#pragma unroll
    for (int j = 0; j < 4; j++) {
        if (idx + j < n) { offs[idx + j] = excl; cur[idx + j] = excl; }
        excl += v[j];
    }
    if (blockIdx.x == 0 && tid == 0) offs[n] = bsum[(n + SCAN_CHUNK - 1) / SCAN_CHUNK];
}

// ---- scat (runs AFTER node kernels): bin edge + fuse sigmoid weight ----
__device__ __forceinline__ float fsig(float s) {
    return 1.0f / (1.0f + __expf(-s));
}

__global__ void scat_kernel(const int* __restrict__ r0, const int* __restrict__ c0, int E0,
                            const int* __restrict__ r1, const int* __restrict__ c1, int E1,
                            const int* __restrict__ r2, const int* __restrict__ c2, int E2,
                            int base1, int base2,
                            const float* __restrict__ a1, const float* __restrict__ a2,
                            int* __restrict__ cur, int2* __restrict__ sedge) {
    int t = blockIdx.x * blockDim.x + threadIdx.x;
    int row, col;
    if (t < E0) { row = __ldg(r0 + t); col = __ldg(c0 + t); }
    else if ((t -= E0) < E1) { row = __ldg(r1 + t); col = __ldg(c1 + t) + base1; }
    else if ((t -= E1) < E2) { row = __ldg(r2 + t); col = __ldg(c2 + t) + base2; }
    else return;
    float s = fsig(__ldg(a1 + row) + __ldg(a2 + col));
    int p = atomicAdd(&cur[row], 1);
    sedge[p] = make_int2(col, __float_as_int(s));
}

// ---------------- aggregate: one warp per row, half-warp per edge ----------------
// half-warp lane hl (0-15) accumulates cols hl*8..hl*8+7 for edge c
__device__ __forceinline__ void gacc16(int c, float sv, int hl,
                                       const __half* __restrict__ g, float acc[8]) {
    uint4 u = __ldg((const uint4*)(g + (size_t)c * D) + hl);
    float2 f0 = __half22float2(*reinterpret_cast<__half2*>(&u.x));
    float2 f1 = __half22float2(*reinterpret_cast<__half2*>(&u.y));
    float2 f2 = __half22float2(*reinterpret_cast<__half2*>(&u.z));
    float2 f3 = __half22float2(*reinterpret_cast<__half2*>(&u.w));
    acc[0] += sv * f0.x; acc[1] += sv * f0.y;
    acc[2] += sv * f1.x; acc[3] += sv * f1.y;
    acc[4] += sv * f2.x; acc[5] += sv * f2.y;
    acc[6] += sv * f3.x; acc[7] += sv * f3.y;
}

__global__ __launch_bounds__(256)
void agg_kernel(const int* __restrict__ offs, const int2* __restrict__ sedge,
                const __half* __restrict__ g, float* __restrict__ out, int n0) {
    int row = blockIdx.x * 8 + (threadIdx.x >> 5);
    if (row >= n0) return;
    int lane = threadIdx.x & 31;
    int hw = lane >> 4;        // half-warp id 0/1
    int hl = lane & 15;        // lane within half-warp
    float acc[8];
#pragma unroll
    for (int j = 0; j < 8; j++) acc[j] = 0.f;
    int s = __ldg(offs + row), e = __ldg(offs + row + 1);
    int i = s + hw;
    for (; i + 2 < e; i += 4) {
        int2 ea = __ldg(sedge + i);
        int2 eb = __ldg(sedge + i + 2);
        gacc16(ea.x, __int_as_float(ea.y), hl, g, acc);
        gacc16(eb.x, __int_as_float(eb.y), hl, g, acc);
    }
    for (; i < e; i += 2) {
        int2 ea = __ldg(sedge + i);
        gacc16(ea.x, __int_as_float(ea.y), hl, g, acc);
    }
#pragma unroll
    for (int j = 0; j < 8; j++) acc[j] += __shfl_down_sync(0xffffffffu, acc[j], 16);
    if (hw == 0) {
        float4* op = (float4*)(out + (size_t)row * D + hl * 8);
        float4 c0 = op[0], c1 = op[1];
        c0.x += acc[0]; c0.y += acc[1]; c0.z += acc[2]; c0.w += acc[3];
        c1.x += acc[4]; c1.y += acc[5]; c1.z += acc[6]; c1.w += acc[7];
        op[0] = c0;
        op[1] = c1;
    }
}

// ---------------- launch ----------------
extern "C" void kernel_launch(void* const* d_in, const int* in_sizes, int n_in,
                              void* d_out, int out_size) {
    const float* x0   = (const float*)d_in[0];
    const float* x1   = (const float*)d_in[1];
    const float* x2   = (const float*)d_in[2];
    const float* W1   = (const float*)d_in[3];
    const float* b1   = (const float*)d_in[4];
    const float* a1w  = (const float*)d_in[5];
    const float* a1b  = (const float*)d_in[6];
    const float* a2w  = (const float*)d_in[7];
    const float* a2b  = (const float*)d_in[8];
    const float* Wagg = (const float*)d_in[9];
    const float* bagg = (const float*)d_in[10];
    const int* ar0 = (const int*)d_in[11];
    const int* ac0 = (const int*)d_in[12];
    const int* ar1 = (const int*)d_in[13];
    const int* ac1 = (const int*)d_in[14];
    const int* ar2 = (const int*)d_in[15];
    const int* ac2 = (const int*)d_in[16];
    float* out = (float*)d_out;

    const int N0 = in_sizes[0] / D;
    const int N1 = in_sizes[1] / D;
    const int N2 = in_sizes[2] / D;
    const int E0 = in_sizes[11];
    const int E1 = in_sizes[13];
    const int E2 = in_sizes[15];

    __half* pg;
    float *pa2, *pa1;
    int *pcnt, *poff, *pcur, *pbsum;
    int2* psedge;
    unsigned char* pwp;
    cudaGetSymbolAddress((void**)&pg, g_gall);
    cudaGetSymbolAddress((void**)&pa2, g_a2all);
    cudaGetSymbolAddress((void**)&pa1, g_a1_0);
    cudaGetSymbolAddress((void**)&pcnt, g_cnt);
    cudaGetSymbolAddress((void**)&poff, g_off);
    cudaGetSymbolAddress((void**)&pcur, g_cur);
    cudaGetSymbolAddress((void**)&psedge, g_sedge);
    cudaGetSymbolAddress((void**)&pwp, g_wprep);
    cudaGetSymbolAddress((void**)&pbsum, g_bsum);

    cudaFuncSetAttribute(node_mm, cudaFuncAttributeMaxDynamicSharedMemorySize, SMEM_REQ);

    #define WHI(m) (pwp + (size_t)(m) * 2 * 32768)
    #define WLO(m) (pwp + (size_t)(m) * 2 * 32768 + 32768)

    prep_w<<<5, 256>>>(W1, Wagg, pwp);
    zero_kernel<<<(N0 + 256) / 256, 256>>>(pcnt, N0 + 1);
    const int ET = E0 + E1 + E2;
    hist_kernel<<<(ET + 255) / 256, 256>>>(ar0, E0, ar1, E1, ar2, E2, pcnt);
    const int NB = (N0 + SCAN_CHUNK - 1) / SCAN_CHUNK;
    scanA_kernel<<<NB, 1024>>>(pcnt, N0, pbsum);
    scanB_kernel<<<1, 32>>>(pbsum, NB);
    scanC_kernel<<<NB, 1024>>>(pcnt, N0, pbsum, poff, pcur);

    // node kernels first (produce a1/a2/g); scat consumes a1/a2 afterwards
    node_mm<<<(N0 + 127) / 128, 256, SMEM_REQ>>>(
        x0, N0, WHI(0), WLO(0), WHI(2), WLO(2), WHI(1), WLO(1),
        b1, a1w, a1b, a2w, a2b, bagg,
        pg, pa1, pa2, out);
    node_mm<<<(N1 + 127) / 128, 256, SMEM_REQ>>>(
        x1, N1, WHI(0), WLO(0), WHI(3), WLO(3), nullptr, nullptr,
        b1, a1w, a1b, a2w, a2b, bagg,
        pg + (size_t)N0 * D, nullptr, pa2 + N0, nullptr);
    node_mm<<<(N2 + 127) / 128, 256, SMEM_REQ>>>(
        x2, N2, WHI(0), WLO(0), WHI(4), WLO(4), nullptr, nullptr,
        b1, a1w, a1b, a2w, a2b, bagg,
        pg + (size_t)(N0 + N1) * D, nullptr, pa2 + N0 + N1, nullptr);

    scat_kernel<<<(ET + 255) / 256, 256>>>(ar0, ac0, E0, ar1, ac1, E1, ar2, ac2, E2,
                                           N0, N0 + N1, pa1, pa2, pcur, psedge);

    agg_kernel<<<(N0 + 7) / 8, 256>>>(poff, psedge, pg, out, N0);
}

// round 13
// speedup vs baseline: 3.4875x; 1.1192x over previous
#include <cuda_runtime.h>
#include <cuda_fp16.h>
#include <cstdint>

#define D 128
#define N0MAX 100000
#define NALL  (100000 + 150000 + 80000)
#define EALL  3000000
#define SCAN_CHUNK 4096
#define SCAN_BLOCKS ((N0MAX + SCAN_CHUNK - 1) / SCAN_CHUNK)

typedef unsigned long long ull;
typedef unsigned int u32;

// ---------------- static scratch (allocation-free rule) ----------------
__device__ __half g_gall[(size_t)NALL * 128];   // fp16 projected features, concat [g0|g1|g2]
__device__ float g_a2all[NALL];                 // concat [a2_0|a2_1|a2_2]
__device__ float g_a1_0[N0MAX];
// prepped weights: 5 matrices (W1, Wagg0..3) x {hi,lo} x 32KB fp16 tiles,
// transposed to [n][k], 16B-chunk XOR-swizzled (ldmatrix-ready, raw smem copy)
__device__ unsigned char g_wprep[5 * 2 * 32768];
// combined CSR scratch
__device__ int g_cnt[N0MAX + 1];
__device__ int g_off[N0MAX + 1];
__device__ int g_cur[N0MAX];
__device__ int2 g_sedge[EALL];                  // {col, sigmoid-weight bits} per binned edge
__device__ int g_bsum[SCAN_BLOCKS + 1];

__device__ __forceinline__ u32 smem_to_u32(const void* p) {
    u32 a;
    asm("{ .reg .u64 t; cvta.to.shared.u64 t, %1; cvt.u32.u64 %0, t; }" : "=r"(a) : "l"(p));
    return a;
}

// byte offset of 16B chunk (row, kc) in a 128x128 fp16 tile (256B rows),
// XOR swizzle on chunk index by row&7 -> conflict-free ldmatrix + staging
#define CH(row, kc) ((u32)((row) * 256 + ((((kc)) ^ ((row) & 7)) << 4)))

// split 8 fp32 -> fp16 hi + fp16 lo packed uint4 (16B each)
__device__ __forceinline__ void split8h(const float* v, uint4& hi, uint4& lo) {
    u32 hw[4], lw[4];
#pragma unroll
    for (int j = 0; j < 4; j++) {
        float a = v[2 * j], b = v[2 * j + 1];
        __half ah = __float2half_rn(a), bh = __float2half_rn(b);
        float ar = a - __half2float(ah), br = b - __half2float(bh);
        __half2 hh = __halves2half2(ah, bh);
        __half2 ll = __floats2half2_rn(ar, br);
        hw[j] = *(u32*)&hh;
        lw[j] = *(u32*)&ll;
    }
    hi = make_uint4(hw[0], hw[1], hw[2], hw[3]);
    lo = make_uint4(lw[0], lw[1], lw[2], lw[3]);
}

// pack 8 fp32 -> fp16 uint4 (hi only)
__device__ __forceinline__ uint4 pack8h(const float* v) {
    u32 hw[4];
#pragma unroll
    for (int j = 0; j < 4; j++) {
        __half2 hh = __floats2half2_rn(v[2 * j], v[2 * j + 1]);
        hw[j] = *(u32*)&hh;
    }
    return make_uint4(hw[0], hw[1], hw[2], hw[3]);
}

// ---------------- weight prep: transpose + fp16 split + swizzle ----------------
__global__ void prep_w(const float* __restrict__ W1, const float* __restrict__ Wagg,
                       unsigned char* __restrict__ wp) {
    int m = blockIdx.x, tid = threadIdx.x;
    unsigned char* hip = wp + (size_t)m * 2 * 32768;
    unsigned char* lop = hip + 32768;
#pragma unroll 1
    for (int it = 0; it < 8; it++) {
        int f = tid + it * 256;           // chunk id 0..2047
        int n = f >> 4, kc = f & 15, k0 = kc * 8;
        float v[8];
#pragma unroll
        for (int j = 0; j < 8; j++) {
            int k = k0 + j;
            v[j] = (m == 0) ? W1[k * 128 + n] : Wagg[((m - 1) * 128 + k) * 128 + n];
        }
        uint4 hi, lo;
        split8h(v, hi, lo);
        u32 ad = CH(n, kc);
        *(uint4*)(hip + ad) = hi;
        *(uint4*)(lop + ad) = lo;
    }
}

// ---------------- node kernel (mma.sync m16n8k16 fp16, 2-pass: A_hi x {W_hi,W_lo}) ----
// smem: A (fp16 hi) | W_hi | W_lo | header  => 100KB, 2 CTAs/SM
#define OFF_A    0
#define OFF_W_HI 32768
#define OFF_W_LO 65536
#define OFF_HDR  98304
#define SMEM_REQ (98304 + 3072 + 1024)

__device__ __forceinline__ void copy32k(void* dst, const void* src, int tid) {
    const uint4* s = (const uint4*)src;
    uint4* d = (uint4*)dst;
#pragma unroll
    for (int i = 0; i < 8; i++) d[tid + i * 256] = s[tid + i * 256];
}

// one pass (8 k-steps) of the 128x128 GEMM for this warp
__device__ __forceinline__ void gemm_pass(u32 Ab, u32 Wb, int r0, int cbase, int lane,
                                          bool clear, float c[2][8][4]) {
    const int q = lane >> 3, sr = lane & 7;
    if (clear) {
#pragma unroll
        for (int mt = 0; mt < 2; mt++)
#pragma unroll
            for (int nt = 0; nt < 8; nt++)
#pragma unroll
                for (int j = 0; j < 4; j++) c[mt][nt][j] = 0.f;
    }
#pragma unroll 1
    for (int ks = 0; ks < 8; ks++) {
        u32 a[2][4];
#pragma unroll
        for (int mt = 0; mt < 2; mt++) {
            int row = r0 + mt * 16 + ((q & 1) << 3) + sr;
            int kc = 2 * ks + (q >> 1);
            u32 ad = Ab + CH(row, kc);
            asm volatile("ldmatrix.sync.aligned.m8n8.x4.shared.b16 {%0,%1,%2,%3}, [%4];"
                         : "=r"(a[mt][0]), "=r"(a[mt][1]), "=r"(a[mt][2]), "=r"(a[mt][3])
                         : "r"(ad));
        }
        u32 b[8][2];
#pragma unroll
        for (int nb = 0; nb < 4; nb++) {
            int rown = cbase + nb * 16 + ((q >> 1) << 3) + sr;
            int kc = 2 * ks + (q & 1);
            u32 ad = Wb + CH(rown, kc);
            asm volatile("ldmatrix.sync.aligned.m8n8.x4.shared.b16 {%0,%1,%2,%3}, [%4];"
                         : "=r"(b[2 * nb][0]), "=r"(b[2 * nb][1]),
                           "=r"(b[2 * nb + 1][0]), "=r"(b[2 * nb + 1][1])
                         : "r"(ad));
        }
#pragma unroll
        for (int mt = 0; mt < 2; mt++)
#pragma unroll
            for (int nt = 0; nt < 8; nt++)
                asm volatile("mma.sync.aligned.m16n8k16.row.col.f32.f16.f16.f32 "
                             "{%0,%1,%2,%3}, {%4,%5,%6,%7}, {%8,%9}, {%0,%1,%2,%3};"
                             : "+f"(c[mt][nt][0]), "+f"(c[mt][nt][1]),
                               "+f"(c[mt][nt][2]), "+f"(c[mt][nt][3])
                             : "r"(a[mt][0]), "r"(a[mt][1]), "r"(a[mt][2]), "r"(a[mt][3]),
                               "r"(b[nt][0]), "r"(b[nt][1]));
    }
}

__global__ __launch_bounds__(256, 2)
void node_mm(const float* __restrict__ x, int nrows,
             const unsigned char* __restrict__ w1h, const unsigned char* __restrict__ w1l,
             const unsigned char* __restrict__ wgh, const unsigned char* __restrict__ wgl,
             const unsigned char* __restrict__ wsh, const unsigned char* __restrict__ wsl,
             const float* __restrict__ b1,
             const float* __restrict__ a1w, const float* __restrict__ a1bp,
             const float* __restrict__ a2w, const float* __restrict__ a2bp,
             const float* __restrict__ bagg,
             __half* __restrict__ gout, float* __restrict__ a1out,
             float* __restrict__ a2out, float* __restrict__ selfout) {
    extern __shared__ char sraw[];
    const u32 sb = smem_to_u32(sraw);
    const u32 base = (sb + 1023u) & ~1023u;
    char* bp = sraw + (base - sb);
    float* sBB  = (float*)(bp + OFF_HDR);
    float* sAW1 = sBB + 128;
    float* sAW2 = sAW1 + 128;
    float* sBG  = sAW2 + 128;
    float* sPA1 = sBG + 128;
    float* sPA2 = sPA1 + 128;

    const int tid = threadIdx.x, wid = tid >> 5, lane = tid & 31;
    const int wm = wid & 3, wn = wid >> 2;
    const int r0 = wm * 32, cbase = wn * 64;
    const int rbase = blockIdx.x * 128;
    const u32 sA = base + OFF_A;
    const u32 wHi = base + OFF_W_HI, wLo = base + OFF_W_LO;

    if (tid < 128) {
        sBB[tid] = b1[tid];
        sAW1[tid] = a1w[tid];
        sAW2[tid] = a2w[tid];
        sBG[tid] = bagg[tid];
    }
    copy32k(bp + OFF_W_HI, w1h, tid);
    copy32k(bp + OFF_W_LO, w1l, tid);
#pragma unroll 1
    for (int it = 0; it < 8; it++) {
        int f = tid + it * 256;
        int row = f >> 4, kc = f & 15;
        float v[8];
        if (rbase + row < nrows) {
            const float4* xp = (const float4*)(x + (size_t)(rbase + row) * 128 + kc * 8);
            float4 p0 = xp[0], p1 = xp[1];
            v[0] = p0.x; v[1] = p0.y; v[2] = p0.z; v[3] = p0.w;
            v[4] = p1.x; v[5] = p1.y; v[6] = p1.z; v[7] = p1.w;
        } else {
#pragma unroll
            for (int j = 0; j < 8; j++) v[j] = 0.f;
        }
        *(uint4*)(bp + OFF_A + CH(row, kc)) = pack8h(v);
    }
    __syncthreads();

    float c[2][8][4];
    float pph1[4], pph2[4];

    // ---- GEMM1: h = x @ W1^T  (passes: A*W1hi + A*W1lo) ----
    gemm_pass(sA, wHi, r0, cbase, lane, true, c);
    gemm_pass(sA, wLo, r0, cbase, lane, false, c);
    __syncthreads();   // all warps done reading sA(x) and W before overwrite

    // epilogue 1: bias+relu, attention dots, h -> sA fp16
#pragma unroll
    for (int mt = 0; mt < 2; mt++)
#pragma unroll
        for (int half = 0; half < 2; half++) {
            int row = r0 + mt * 16 + half * 8 + (lane >> 2);
            float ph1 = 0.f, ph2 = 0.f;
#pragma unroll
            for (int nt = 0; nt < 8; nt++) {
                int col = cbase + nt * 8 + 2 * (lane & 3);
                float h0 = fmaxf(c[mt][nt][half * 2 + 0] + sBB[col], 0.f);
                float h1 = fmaxf(c[mt][nt][half * 2 + 1] + sBB[col + 1], 0.f);
                ph1 += h0 * sAW1[col] + h1 * sAW1[col + 1];
                ph2 += h0 * sAW2[col] + h1 * sAW2[col + 1];
                __half2 hhi = __floats2half2_rn(h0, h1);
                u32 ao = (u32)(row * 256 + (((col >> 3) ^ (row & 7)) << 4) + (col & 7) * 2);
                *(u32*)(bp + OFF_A + ao) = *(u32*)&hhi;
            }
            ph1 += __shfl_xor_sync(0xffffffffu, ph1, 1);
            ph1 += __shfl_xor_sync(0xffffffffu, ph1, 2);
            ph2 += __shfl_xor_sync(0xffffffffu, ph2, 1);
            ph2 += __shfl_xor_sync(0xffffffffu, ph2, 2);
            pph1[mt * 2 + half] = ph1;
            pph2[mt * 2 + half] = ph2;
            if (wn == 0 && (lane & 3) == 0) {
                sPA1[row] = ph1;
                sPA2[row] = ph2;
            }
        }
    copy32k(bp + OFF_W_HI, wgh, tid);   // stage Wg (safe: post-GEMM1 barrier above)
    copy32k(bp + OFF_W_LO, wgl, tid);
    __syncthreads();
    if (wn == 1 && (lane & 3) == 0) {
        const float a1b = *a1bp, a2b = *a2bp;
#pragma unroll
        for (int mt = 0; mt < 2; mt++)
#pragma unroll
            for (int half = 0; half < 2; half++) {
                int row = r0 + mt * 16 + half * 8 + (lane >> 2);
                int grow = rbase + row;
                if (grow < nrows) {
                    if (a1out) a1out[grow] = sPA1[row] + pph1[mt * 2 + half] + a1b;
                    a2out[grow] = sPA2[row] + pph2[mt * 2 + half] + a2b;
                }
            }
    }

    // ---- GEMM2: g = h @ Wg^T -> fp16 global ----
    gemm_pass(sA, wHi, r0, cbase, lane, true, c);
    gemm_pass(sA, wLo, r0, cbase, lane, false, c);
#pragma unroll
    for (int mt = 0; mt < 2; mt++)
#pragma unroll
        for (int half = 0; half < 2; half++) {
            int row = r0 + mt * 16 + half * 8 + (lane >> 2);
            int grow = rbase + row;
            if (grow < nrows) {
#pragma unroll
                for (int nt = 0; nt < 8; nt++) {
                    int col = cbase + nt * 8 + 2 * (lane & 3);
                    __half2 hv = __floats2half2_rn(c[mt][nt][half * 2 + 0],
                                                   c[mt][nt][half * 2 + 1]);
                    *(u32*)(gout + (size_t)grow * D + col) = *(u32*)&hv;
                }
            }
        }

    // ---- GEMM3 (x0 only): self = h @ Wself^T + bagg -> out ----
    if (wsh) {
        __syncthreads();   // all warps done reading W(Wg)
        copy32k(bp + OFF_W_HI, wsh, tid);
        copy32k(bp + OFF_W_LO, wsl, tid);
        __syncthreads();
        gemm_pass(sA, wHi, r0, cbase, lane, true, c);
        gemm_pass(sA, wLo, r0, cbase, lane, false, c);
#pragma unroll
        for (int mt = 0; mt < 2; mt++)
#pragma unroll
            for (int half = 0; half < 2; half++) {
                int row = r0 + mt * 16 + half * 8 + (lane >> 2);
                int grow = rbase + row;
                if (grow < nrows) {
#pragma unroll
                    for (int nt = 0; nt < 8; nt++) {
                        int col = cbase + nt * 8 + 2 * (lane & 3);
                        float2 v = make_float2(c[mt][nt][half * 2 + 0] + sBG[col],
                                               c[mt][nt][half * 2 + 1] + sBG[col + 1]);
                        *(float2*)(selfout + (size_t)grow * D + col) = v;
                    }
                }
            }
    }
}

// ---------------- binning kernels (combined CSR over all 3 lists) ----------------
__global__ void zero_kernel(int* p, int n) {
    int i = blockIdx.x * blockDim.x + threadIdx.x;
    if (i < n) p[i] = 0;
}

__global__ void hist_kernel(const int* __restrict__ r0, int E0,
                            const int* __restrict__ r1, int E1,
                            const int* __restrict__ r2, int E2,
                            int* __restrict__ cnt) {
    int t = blockIdx.x * blockDim.x + threadIdx.x;
    int row;
    if (t < E0) row = __ldg(r0 + t);
    else if ((t -= E0) < E1) row = __ldg(r1 + t);
    else if ((t -= E1) < E2) row = __ldg(r2 + t);
    else return;
    atomicAdd(&cnt[row], 1);
}

// ---- parallel scan phase A: per-block sums of 4096-element chunks ----
__global__ __launch_bounds__(1024)
void scanA_kernel(const int* __restrict__ cnt, int n, int* __restrict__ bsum) {
    __shared__ int wsum[32];
    const int tid = threadIdx.x, lane = tid & 31, wid = tid >> 5;
    int idx = blockIdx.x * SCAN_CHUNK + tid * 4;
    int s = 0;
#pragma unroll
    for (int j = 0; j < 4; j++) s += (idx + j < n) ? cnt[idx + j] : 0;
#pragma unroll
    for (int off = 16; off >= 1; off >>= 1) s += __shfl_down_sync(0xffffffffu, s, off);
    if (lane == 0) wsum[wid] = s;
    __syncthreads();
    if (wid == 0) {
        int y = wsum[lane];
#pragma unroll
        for (int off = 16; off >= 1; off >>= 1) y += __shfl_down_sync(0xffffffffu, y, off);
        if (lane == 0) bsum[blockIdx.x] = y;
    }
}

// ---- phase B: exclusive scan of block sums (1 warp) ----
__global__ void scanB_kernel(int* __restrict__ bsum, int nb) {
    int lane = threadIdx.x;
    int v = (lane < nb) ? bsum[lane] : 0;
    int x = v;
#pragma unroll
    for (int off = 1; off < 32; off <<= 1) {
        int t = __shfl_up_sync(0xffffffffu, x, off);
        if (lane >= off) x += t;
    }
    if (lane <= nb && lane < 32) bsum[lane] = x - v;   // exclusive
    if (lane == 31) bsum[nb] = x;   // total (nb<=25<32)
}

// ---- phase C: per-block exclusive scan + block offset -> offs, cur ----
__global__ __launch_bounds__(1024)
void scanC_kernel(const int* __restrict__ cnt, int n, const int* __restrict__ bsum,
                  int* __restrict__ offs, int* __restrict__ cur) {
    __shared__ int wsum[32];
    const int tid = threadIdx.x, lane = tid & 31, wid = tid >> 5;
    int idx = blockIdx.x * SCAN_CHUNK + tid * 4;
    int v[4];
#pragma unroll
    for (int j = 0; j < 4; j++) v[j] = (idx + j < n) ? cnt[idx + j] : 0;
    int tsum = v[0] + v[1] + v[2] + v[3];
    int xv = tsum;
#pragma unroll
    for (int off = 1; off < 32; off <<= 1) {
        int t = __shfl_up_sync(0xffffffffu, xv, off);
        if (lane >= off) xv += t;
    }
    if (lane == 31) wsum[wid] = xv;
    __syncthreads();
    if (wid == 0) {
        int y = wsum[lane];
#pragma unroll
        for (int off = 1; off < 32; off <<= 1) {
            int t = __shfl_up_sync(0xffffffffu, y, off);
            if (lane >= off) y += t;
        }
        wsum[lane] = y;
    }
    __syncthreads();
    int warpoff = (wid == 0) ? 0 : wsum[wid - 1];
    int excl = bsum[blockIdx.x] + warpoff + xv - tsum;
#pragma unroll
    for (int j = 0; j < 4; j++) {
        if (idx + j < n) { offs[idx + j] = excl; cur[idx + j] = excl; }
        excl += v[j];
    }
    if (blockIdx.x == 0 && tid == 0) offs[n] = bsum[(n + SCAN_CHUNK - 1) / SCAN_CHUNK];
}

// ---- scat (runs AFTER node kernels): bin edge + fuse sigmoid weight ----
__device__ __forceinline__ float fsig(float s) {
    return 1.0f / (1.0f + __expf(-s));
}

__global__ void scat_kernel(const int* __restrict__ r0, const int* __restrict__ c0, int E0,
                            const int* __restrict__ r1, const int* __restrict__ c1, int E1,
                            const int* __restrict__ r2, const int* __restrict__ c2, int E2,
                            int base1, int base2,
                            const float* __restrict__ a1, const float* __restrict__ a2,
                            int* __restrict__ cur, int2* __restrict__ sedge) {
    int t = blockIdx.x * blockDim.x + threadIdx.x;
    int row, col;
    if (t < E0) { row = __ldg(r0 + t); col = __ldg(c0 + t); }
    else if ((t -= E0) < E1) { row = __ldg(r1 + t); col = __ldg(c1 + t) + base1; }
    else if ((t -= E1) < E2) { row = __ldg(r2 + t); col = __ldg(c2 + t) + base2; }
    else return;
    float s = fsig(__ldg(a1 + row) + __ldg(a2 + col));
    int p = atomicAdd(&cur[row], 1);
    sedge[p] = make_int2(col, __float_as_int(s));
}

// ---------------- aggregate: one warp per row, half-warp per edge ----------------
// half-warp lane hl (0-15) accumulates cols hl*8..hl*8+7 for edge c
__device__ __forceinline__ void gacc16(int c, float sv, int hl,
                                       const __half* __restrict__ g, float acc[8]) {
    uint4 u = __ldg((const uint4*)(g + (size_t)c * D) + hl);
    float2 f0 = __half22float2(*reinterpret_cast<__half2*>(&u.x));
    float2 f1 = __half22float2(*reinterpret_cast<__half2*>(&u.y));
    float2 f2 = __half22float2(*reinterpret_cast<__half2*>(&u.z));
    float2 f3 = __half22float2(*reinterpret_cast<__half2*>(&u.w));
    acc[0] += sv * f0.x; acc[1] += sv * f0.y;
    acc[2] += sv * f1.x; acc[3] += sv * f1.y;
    acc[4] += sv * f2.x; acc[5] += sv * f2.y;
    acc[6] += sv * f3.x; acc[7] += sv * f3.y;
}

__global__ __launch_bounds__(256)
void agg_kernel(const int* __restrict__ offs, const int2* __restrict__ sedge,
                const __half* __restrict__ g, float* __restrict__ out, int n0) {
    int row = blockIdx.x * 8 + (threadIdx.x >> 5);
    if (row >= n0) return;
    int lane = threadIdx.x & 31;
    int hw = lane >> 4;        // half-warp id 0/1
    int hl = lane & 15;        // lane within half-warp
    float acc[8];
#pragma unroll
    for (int j = 0; j < 8; j++) acc[j] = 0.f;
    int s = __ldg(offs + row), e = __ldg(offs + row + 1);
    int i = s + hw;
    for (; i + 2 < e; i += 4) {
        int2 ea = __ldg(sedge + i);
        int2 eb = __ldg(sedge + i + 2);
        gacc16(ea.x, __int_as_float(ea.y), hl, g, acc);
        gacc16(eb.x, __int_as_float(eb.y), hl, g, acc);
    }
    for (; i < e; i += 2) {
        int2 ea = __ldg(sedge + i);
        gacc16(ea.x, __int_as_float(ea.y), hl, g, acc);
    }
#pragma unroll
    for (int j = 0; j < 8; j++) acc[j] += __shfl_down_sync(0xffffffffu, acc[j], 16);
    if (hw == 0) {
        float4* op = (float4*)(out + (size_t)row * D + hl * 8);
        float4 c0 = op[0], c1 = op[1];
        c0.x += acc[0]; c0.y += acc[1]; c0.z += acc[2]; c0.w += acc[3];
        c1.x += acc[4]; c1.y += acc[5]; c1.z += acc[6]; c1.w += acc[7];
        op[0] = c0;
        op[1] = c1;
    }
}

// ---------------- launch ----------------
extern "C" void kernel_launch(void* const* d_in, const int* in_sizes, int n_in,
                              void* d_out, int out_size) {
    const float* x0   = (const float*)d_in[0];
    const float* x1   = (const float*)d_in[1];
    const float* x2   = (const float*)d_in[2];
    const float* W1   = (const float*)d_in[3];
    const float* b1   = (const float*)d_in[4];
    const float* a1w  = (const float*)d_in[5];
    const float* a1b  = (const float*)d_in[6];
    const float* a2w  = (const float*)d_in[7];
    const float* a2b  = (const float*)d_in[8];
    const float* Wagg = (const float*)d_in[9];
    const float* bagg = (const float*)d_in[10];
    const int* ar0 = (const int*)d_in[11];
    const int* ac0 = (const int*)d_in[12];
    const int* ar1 = (const int*)d_in[13];
    const int* ac1 = (const int*)d_in[14];
    const int* ar2 = (const int*)d_in[15];
    const int* ac2 = (const int*)d_in[16];
    float* out = (float*)d_out;

    const int N0 = in_sizes[0] / D;
    const int N1 = in_sizes[1] / D;
    const int N2 = in_sizes[2] / D;
    const int E0 = in_sizes[11];
    const int E1 = in_sizes[13];
    const int E2 = in_sizes[15];

    __half* pg;
    float *pa2, *pa1;
    int *pcnt, *poff, *pcur, *pbsum;
    int2* psedge;
    unsigned char* pwp;
    cudaGetSymbolAddress((void**)&pg, g_gall);
    cudaGetSymbolAddress((void**)&pa2, g_a2all);
    cudaGetSymbolAddress((void**)&pa1, g_a1_0);
    cudaGetSymbolAddress((void**)&pcnt, g_cnt);
    cudaGetSymbolAddress((void**)&poff, g_off);
    cudaGetSymbolAddress((void**)&pcur, g_cur);
    cudaGetSymbolAddress((void**)&psedge, g_sedge);
    cudaGetSymbolAddress((void**)&pwp, g_wprep);
    cudaGetSymbolAddress((void**)&pbsum, g_bsum);

    cudaFuncSetAttribute(node_mm, cudaFuncAttributeMaxDynamicSharedMemorySize, SMEM_REQ);

    #define WHI(m) (pwp + (size_t)(m) * 2 * 32768)
    #define WLO(m) (pwp + (size_t)(m) * 2 * 32768 + 32768)

    prep_w<<<5, 256>>>(W1, Wagg, pwp);
    zero_kernel<<<(N0 + 256) / 256, 256>>>(pcnt, N0 + 1);
    const int ET = E0 + E1 + E2;
    hist_kernel<<<(ET + 255) / 256, 256>>>(ar0, E0, ar1, E1, ar2, E2, pcnt);
    const int NB = (N0 + SCAN_CHUNK - 1) / SCAN_CHUNK;
    scanA_kernel<<<NB, 1024>>>(pcnt, N0, pbsum);
    scanB_kernel<<<1, 32>>>(pbsum, NB);
    scanC_kernel<<<NB, 1024>>>(pcnt, N0, pbsum, poff, pcur);

    // node kernels first (produce a1/a2/g); scat consumes a1/a2 afterwards
    node_mm<<<(N0 + 127) / 128, 256, SMEM_REQ>>>(
        x0, N0, WHI(0), WLO(0), WHI(2), WLO(2), WHI(1), WLO(1),
        b1, a1w, a1b, a2w, a2b, bagg,
        pg, pa1, pa2, out);
    node_mm<<<(N1 + 127) / 128, 256, SMEM_REQ>>>(
        x1, N1, WHI(0), WLO(0), WHI(3), WLO(3), nullptr, nullptr,
        b1, a1w, a1b, a2w, a2b, bagg,
        pg + (size_t)N0 * D, nullptr, pa2 + N0, nullptr);
    node_mm<<<(N2 + 127) / 128, 256, SMEM_REQ>>>(
        x2, N2, WHI(0), WLO(0), WHI(4), WLO(4), nullptr, nullptr,
        b1, a1w, a1b, a2w, a2b, bagg,
        pg + (size_t)(N0 + N1) * D, nullptr, pa2 + N0 + N1, nullptr);

    scat_kernel<<<(ET + 255) / 256, 256>>>(ar0, ac0, E0, ar1, ac1, E1, ar2, ac2, E2,
                                           N0, N0 + N1, pa1, pa2, pcur, psedge);

    agg_kernel<<<(N0 + 7) / 8, 256>>>(poff, psedge, pg, out, N0);
}

// round 14
// speedup vs baseline: 4.0790x; 1.1696x over previous
#include <cuda_runtime.h>
#include <cuda_fp16.h>
#include <cstdint>

#define D 128
#define N0MAX 100000
#define NALL  (100000 + 150000 + 80000)
#define EALL  3000000
#define SCAN_CHUNK 4096
#define SCAN_BLOCKS ((N0MAX + SCAN_CHUNK - 1) / SCAN_CHUNK)

typedef unsigned long long ull;
typedef unsigned int u32;

// ---------------- static scratch (allocation-free rule) ----------------
__device__ __half g_gall[(size_t)NALL * 128];   // fp16 projected features, concat [g0|g1|g2]
__device__ float g_a2all[NALL];                 // concat [a2_0|a2_1|a2_2]
__device__ float g_a1_0[N0MAX];
// prepped weights: 5 matrices (W1, Wagg0..3) x {hi,lo} x 32KB fp16 tiles,
// transposed to [n][k], 16B-chunk XOR-swizzled (ldmatrix-ready, raw smem copy)
// (lo planes currently unused by node_mm; kept for safety/rollback)
__device__ unsigned char g_wprep[5 * 2 * 32768];
// combined CSR scratch
__device__ int g_cnt[N0MAX + 1];
__device__ int g_off[N0MAX + 1];
__device__ int g_cur[N0MAX];
__device__ int2 g_sedge[EALL];                  // {col, sigmoid-weight bits} per binned edge
__device__ int g_bsum[SCAN_BLOCKS + 1];

__device__ __forceinline__ u32 smem_to_u32(const void* p) {
    u32 a;
    asm("{ .reg .u64 t; cvta.to.shared.u64 t, %1; cvt.u32.u64 %0, t; }" : "=r"(a) : "l"(p));
    return a;
}

// byte offset of 16B chunk (row, kc) in a 128x128 fp16 tile (256B rows),
// XOR swizzle on chunk index by row&7 -> conflict-free ldmatrix + staging
#define CH(row, kc) ((u32)((row) * 256 + ((((kc)) ^ ((row) & 7)) << 4)))

// split 8 fp32 -> fp16 hi + fp16 lo packed uint4 (16B each)
__device__ __forceinline__ void split8h(const float* v, uint4& hi, uint4& lo) {
    u32 hw[4], lw[4];
#pragma unroll
    for (int j = 0; j < 4; j++) {
        float a = v[2 * j], b = v[2 * j + 1];
        __half ah = __float2half_rn(a), bh = __float2half_rn(b);
        float ar = a - __half2float(ah), br = b - __half2float(bh);
        __half2 hh = __halves2half2(ah, bh);
        __half2 ll = __floats2half2_rn(ar, br);
        hw[j] = *(u32*)&hh;
        lw[j] = *(u32*)&ll;
    }
    hi = make_uint4(hw[0], hw[1], hw[2], hw[3]);
    lo = make_uint4(lw[0], lw[1], lw[2], lw[3]);
}

// pack 8 fp32 -> fp16 uint4
__device__ __forceinline__ uint4 pack8h(const float* v) {
    u32 hw[4];
#pragma unroll
    for (int j = 0; j < 4; j++) {
        __half2 hh = __floats2half2_rn(v[2 * j], v[2 * j + 1]);
        hw[j] = *(u32*)&hh;
    }
    return make_uint4(hw[0], hw[1], hw[2], hw[3]);
}

// ---------------- weight prep: transpose + fp16 split + swizzle ----------------
__global__ void prep_w(const float* __restrict__ W1, const float* __restrict__ Wagg,
                       unsigned char* __restrict__ wp) {
    int m = blockIdx.x, tid = threadIdx.x;
    unsigned char* hip = wp + (size_t)m * 2 * 32768;
    unsigned char* lop = hip + 32768;
#pragma unroll 1
    for (int it = 0; it < 8; it++) {
        int f = tid + it * 256;           // chunk id 0..2047
        int n = f >> 4, kc = f & 15, k0 = kc * 8;
        float v[8];
#pragma unroll
        for (int j = 0; j < 8; j++) {
            int k = k0 + j;
            v[j] = (m == 0) ? W1[k * 128 + n] : Wagg[((m - 1) * 128 + k) * 128 + n];
        }
        uint4 hi, lo;
        split8h(v, hi, lo);
        u32 ad = CH(n, kc);
        *(uint4*)(hip + ad) = hi;
        *(uint4*)(lop + ad) = lo;
    }
}

// ---------------- node kernel (mma.sync m16n8k16 fp16, single pass) ----------
// smem: A (fp16) | W (fp16) | header  => 68KB, 2 CTAs/SM
#define OFF_A    0
#define OFF_W    32768
#define OFF_HDR  65536
#define SMEM_REQ (65536 + 3072 + 1024)

__device__ __forceinline__ void copy32k(void* dst, const void* src, int tid) {
    const uint4* s = (const uint4*)src;
    uint4* d = (uint4*)dst;
#pragma unroll
    for (int i = 0; i < 8; i++) d[tid + i * 256] = s[tid + i * 256];
}

// full K=128 (8 k-steps) of the 128x128 GEMM for this warp
__device__ __forceinline__ void gemm_pass(u32 Ab, u32 Wb, int r0, int cbase, int lane,
                                          float c[2][8][4]) {
    const int q = lane >> 3, sr = lane & 7;
#pragma unroll
    for (int mt = 0; mt < 2; mt++)
#pragma unroll
        for (int nt = 0; nt < 8; nt++)
#pragma unroll
            for (int j = 0; j < 4; j++) c[mt][nt][j] = 0.f;
#pragma unroll 1
    for (int ks = 0; ks < 8; ks++) {
        u32 a[2][4];
#pragma unroll
        for (int mt = 0; mt < 2; mt++) {
            int row = r0 + mt * 16 + ((q & 1) << 3) + sr;
            int kc = 2 * ks + (q >> 1);
            u32 ad = Ab + CH(row, kc);
            asm volatile("ldmatrix.sync.aligned.m8n8.x4.shared.b16 {%0,%1,%2,%3}, [%4];"
                         : "=r"(a[mt][0]), "=r"(a[mt][1]), "=r"(a[mt][2]), "=r"(a[mt][3])
                         : "r"(ad));
        }
        u32 b[8][2];
#pragma unroll
        for (int nb = 0; nb < 4; nb++) {
            int rown = cbase + nb * 16 + ((q >> 1) << 3) + sr;
            int kc = 2 * ks + (q & 1);
            u32 ad = Wb + CH(rown, kc);
            asm volatile("ldmatrix.sync.aligned.m8n8.x4.shared.b16 {%0,%1,%2,%3}, [%4];"
                         : "=r"(b[2 * nb][0]), "=r"(b[2 * nb][1]),
                           "=r"(b[2 * nb + 1][0]), "=r"(b[2 * nb + 1][1])
                         : "r"(ad));
        }
#pragma unroll
        for (int mt = 0; mt < 2; mt++)
#pragma unroll
            for (int nt = 0; nt < 8; nt++)
                asm volatile("mma.sync.aligned.m16n8k16.row.col.f32.f16.f16.f32 "
                             "{%0,%1,%2,%3}, {%4,%5,%6,%7}, {%8,%9}, {%0,%1,%2,%3};"
                             : "+f"(c[mt][nt][0]), "+f"(c[mt][nt][1]),
                               "+f"(c[mt][nt][2]), "+f"(c[mt][nt][3])
                             : "r"(a[mt][0]), "r"(a[mt][1]), "r"(a[mt][2]), "r"(a[mt][3]),
                               "r"(b[nt][0]), "r"(b[nt][1]));
    }
}

__global__ __launch_bounds__(256, 2)
void node_mm(const float* __restrict__ x, int nrows,
             const unsigned char* __restrict__ w1h,
             const unsigned char* __restrict__ wgh,
             const unsigned char* __restrict__ wsh,
             const float* __restrict__ b1,
             const float* __restrict__ a1w, const float* __restrict__ a1bp,
             const float* __restrict__ a2w, const float* __restrict__ a2bp,
             const float* __restrict__ bagg,
             __half* __restrict__ gout, float* __restrict__ a1out,
             float* __restrict__ a2out, float* __restrict__ selfout) {
    extern __shared__ char sraw[];
    const u32 sb = smem_to_u32(sraw);
    const u32 base = (sb + 1023u) & ~1023u;
    char* bp = sraw + (base - sb);
    float* sBB  = (float*)(bp + OFF_HDR);
    float* sAW1 = sBB + 128;
    float* sAW2 = sAW1 + 128;
    float* sBG  = sAW2 + 128;
    float* sPA1 = sBG + 128;
    float* sPA2 = sPA1 + 128;

    const int tid = threadIdx.x, wid = tid >> 5, lane = tid & 31;
    const int wm = wid & 3, wn = wid >> 2;
    const int r0 = wm * 32, cbase = wn * 64;
    const int rbase = blockIdx.x * 128;
    const u32 sA = base + OFF_A;
    const u32 sW = base + OFF_W;

    if (tid < 128) {
        sBB[tid] = b1[tid];
        sAW1[tid] = a1w[tid];
        sAW2[tid] = a2w[tid];
        sBG[tid] = bagg[tid];
    }
    copy32k(bp + OFF_W, w1h, tid);
#pragma unroll 1
    for (int it = 0; it < 8; it++) {
        int f = tid + it * 256;
        int row = f >> 4, kc = f & 15;
        float v[8];
        if (rbase + row < nrows) {
            const float4* xp = (const float4*)(x + (size_t)(rbase + row) * 128 + kc * 8);
            float4 p0 = xp[0], p1 = xp[1];
            v[0] = p0.x; v[1] = p0.y; v[2] = p0.z; v[3] = p0.w;
            v[4] = p1.x; v[5] = p1.y; v[6] = p1.z; v[7] = p1.w;
        } else {
#pragma unroll
            for (int j = 0; j < 8; j++) v[j] = 0.f;
        }
        *(uint4*)(bp + OFF_A + CH(row, kc)) = pack8h(v);
    }
    __syncthreads();

    float c[2][8][4];
    float pph1[4], pph2[4];

    // ---- GEMM1: h = x @ W1^T ----
    gemm_pass(sA, sW, r0, cbase, lane, c);
    __syncthreads();   // all warps done reading sA(x)/sW before overwrite

    // epilogue 1: bias+relu, attention dots, h -> sA fp16
#pragma unroll
    for (int mt = 0; mt < 2; mt++)
#pragma unroll
        for (int half = 0; half < 2; half++) {
            int row = r0 + mt * 16 + half * 8 + (lane >> 2);
            float ph1 = 0.f, ph2 = 0.f;
#pragma unroll
            for (int nt = 0; nt < 8; nt++) {
                int col = cbase + nt * 8 + 2 * (lane & 3);
                float h0 = fmaxf(c[mt][nt][half * 2 + 0] + sBB[col], 0.f);
                float h1 = fmaxf(c[mt][nt][half * 2 + 1] + sBB[col + 1], 0.f);
                ph1 += h0 * sAW1[col] + h1 * sAW1[col + 1];
                ph2 += h0 * sAW2[col] + h1 * sAW2[col + 1];
                __half2 hhi = __floats2half2_rn(h0, h1);
                u32 ao = (u32)(row * 256 + (((col >> 3) ^ (row & 7)) << 4) + (col & 7) * 2);
                *(u32*)(bp + OFF_A + ao) = *(u32*)&hhi;
            }
            ph1 += __shfl_xor_sync(0xffffffffu, ph1, 1);
            ph1 += __shfl_xor_sync(0xffffffffu, ph1, 2);
            ph2 += __shfl_xor_sync(0xffffffffu, ph2, 1);
            ph2 += __shfl_xor_sync(0xffffffffu, ph2, 2);
            pph1[mt * 2 + half] = ph1;
            pph2[mt * 2 + half] = ph2;
            if (wn == 0 && (lane & 3) == 0) {
                sPA1[row] = ph1;
                sPA2[row] = ph2;
            }
        }
    copy32k(bp + OFF_W, wgh, tid);   // stage Wg (safe: post-GEMM1 barrier above)
    __syncthreads();
    if (wn == 1 && (lane & 3) == 0) {
        const float a1b = *a1bp, a2b = *a2bp;
#pragma unroll
        for (int mt = 0; mt < 2; mt++)
#pragma unroll
            for (int half = 0; half < 2; half++) {
                int row = r0 + mt * 16 + half * 8 + (lane >> 2);
                int grow = rbase + row;
                if (grow < nrows) {
                    if (a1out) a1out[grow] = sPA1[row] + pph1[mt * 2 + half] + a1b;
                    a2out[grow] = sPA2[row] + pph2[mt * 2 + half] + a2b;
                }
            }
    }

    // ---- GEMM2: g = h @ Wg^T -> fp16 global ----
    gemm_pass(sA, sW, r0, cbase, lane, c);
#pragma unroll
    for (int mt = 0; mt < 2; mt++)
#pragma unroll
        for (int half = 0; half < 2; half++) {
            int row = r0 + mt * 16 + half * 8 + (lane >> 2);
            int grow = rbase + row;
            if (grow < nrows) {
#pragma unroll
                for (int nt = 0; nt < 8; nt++) {
                    int col = cbase + nt * 8 + 2 * (lane & 3);
                    __half2 hv = __floats2half2_rn(c[mt][nt][half * 2 + 0],
                                                   c[mt][nt][half * 2 + 1]);
                    *(u32*)(gout + (size_t)grow * D + col) = *(u32*)&hv;
                }
            }
        }

    // ---- GEMM3 (x0 only): self = h @ Wself^T + bagg -> out ----
    if (wsh) {
        __syncthreads();   // all warps done reading sW(Wg)
        copy32k(bp + OFF_W, wsh, tid);
        __syncthreads();
        gemm_pass(sA, sW, r0, cbase, lane, c);
#pragma unroll
        for (int mt = 0; mt < 2; mt++)
#pragma unroll
            for (int half = 0; half < 2; half++) {
                int row = r0 + mt * 16 + half * 8 + (lane >> 2);
                int grow = rbase + row;
                if (grow < nrows) {
#pragma unroll
                    for (int nt = 0; nt < 8; nt++) {
                        int col = cbase + nt * 8 + 2 * (lane & 3);
                        float2 v = make_float2(c[mt][nt][half * 2 + 0] + sBG[col],
                                               c[mt][nt][half * 2 + 1] + sBG[col + 1]);
                        *(float2*)(selfout + (size_t)grow * D + col) = v;
                    }
                }
            }
    }
}

// ---------------- binning kernels (combined CSR over all 3 lists) ----------------
__global__ void zero_kernel(int* p, int n) {
    int i = blockIdx.x * blockDim.x + threadIdx.x;
    if (i < n) p[i] = 0;
}

__global__ void hist_kernel(const int* __restrict__ r0, int E0,
                            const int* __restrict__ r1, int E1,
                            const int* __restrict__ r2, int E2,
                            int* __restrict__ cnt) {
    int t = blockIdx.x * blockDim.x + threadIdx.x;
    int row;
    if (t < E0) row = __ldg(r0 + t);
    else if ((t -= E0) < E1) row = __ldg(r1 + t);
    else if ((t -= E1) < E2) row = __ldg(r2 + t);
    else return;
    atomicAdd(&cnt[row], 1);
}

// ---- parallel scan phase A: per-block sums of 4096-element chunks ----
__global__ __launch_bounds__(1024)
void scanA_kernel(const int* __restrict__ cnt, int n, int* __restrict__ bsum) {
    __shared__ int wsum[32];
    const int tid = threadIdx.x, lane = tid & 31, wid = tid >> 5;
    int idx = blockIdx.x * SCAN_CHUNK + tid * 4;
    int s = 0;
#pragma unroll
    for (int j = 0; j < 4; j++) s += (idx + j < n) ? cnt[idx + j] : 0;
#pragma unroll
    for (int off = 16; off >= 1; off >>= 1) s += __shfl_down_sync(0xffffffffu, s, off);
    if (lane == 0) wsum[wid] = s;
    __syncthreads();
    if (wid == 0) {
        int y = wsum[lane];
#pragma unroll
        for (int off = 16; off >= 1; off >>= 1) y += __shfl_down_sync(0xffffffffu, y, off);
        if (lane == 0) bsum[blockIdx.x] = y;
    }
}

// ---- phase B: exclusive scan of block sums (1 warp) ----
__global__ void scanB_kernel(int* __restrict__ bsum, int nb) {
    int lane = threadIdx.x;
    int v = (lane < nb) ? bsum[lane] : 0;
    int x = v;
#pragma unroll
    for (int off = 1; off < 32; off <<= 1) {
        int t = __shfl_up_sync(0xffffffffu, x, off);
        if (lane >= off) x += t;
    }
    if (lane <= nb && lane < 32) bsum[lane] = x - v;   // exclusive
    if (lane == 31) bsum[nb] = x;   // total (nb<=25<32)
}

// ---- phase C: per-block exclusive scan + block offset -> offs, cur ----
__global__ __launch_bounds__(1024)
void scanC_kernel(const int* __restrict__ cnt, int n, const int* __restrict__ bsum,
                  int* __restrict__ offs, int* __restrict__ cur) {
    __shared__ int wsum[32];
    const int tid = threadIdx.x, lane = tid & 31, wid = tid >> 5;
    int idx = blockIdx.x * SCAN_CHUNK + tid * 4;
    int v[4];
#pragma unroll
    for (int j = 0; j < 4; j++) v[j] = (idx + j < n) ? cnt[idx + j] : 0;
    int tsum = v[0] + v[1] + v[2] + v[3];
    int xv = tsum;
#pragma unroll
    for (int off = 1; off < 32; off <<= 1) {
        int t = __shfl_up_sync(0xffffffffu, xv, off);
        if (lane >= off) xv += t;
    }
    if (lane == 31) wsum[wid] = xv;
    __syncthreads();
    if (wid == 0) {
        int y = wsum[lane];
#pragma unroll
        for (int off = 1; off < 32; off <<= 1) {
            int t = __shfl_up_sync(0xffffffffu, y, off);
            if (lane >= off) y += t;
        }
        wsum[lane] = y;
    }
    __syncthreads();
    int warpoff = (wid == 0) ? 0 : wsum[wid - 1];
    int excl = bsum[blockIdx.x] + warpoff + xv - tsum;
#pragma unroll
    for (int j = 0; j < 4; j++) {
        if (idx + j < n) { offs[idx + j] = excl; cur[idx + j] = excl; }
        excl += v[j];
    }
    if (blockIdx.x == 0 && tid == 0) offs[n] = bsum[(n + SCAN_CHUNK - 1) / SCAN_CHUNK];
}

// ---- scat (runs AFTER node kernels): bin edge + fuse sigmoid weight ----
__device__ __forceinline__ float fsig(float s) {
    return 1.0f / (1.0f + __expf(-s));
}

__global__ void scat_kernel(const int* __restrict__ r0, const int* __restrict__ c0, int E0,
                            const int* __restrict__ r1, const int* __restrict__ c1, int E1,
                            const int* __restrict__ r2, const int* __restrict__ c2, int E2,
                            int base1, int base2,
                            const float* __restrict__ a1, const float* __restrict__ a2,
                            int* __restrict__ cur, int2* __restrict__ sedge) {
    int t = blockIdx.x * blockDim.x + threadIdx.x;
    int row, col;
    if (t < E0) { row = __ldg(r0 + t); col = __ldg(c0 + t); }
    else if ((t -= E0) < E1) { row = __ldg(r1 + t); col = __ldg(c1 + t) + base1; }
    else if ((t -= E1) < E2) { row = __ldg(r2 + t); col = __ldg(c2 + t) + base2; }
    else return;
    float s = fsig(__ldg(a1 + row) + __ldg(a2 + col));
    int p = atomicAdd(&cur[row], 1);
    sedge[p] = make_int2(col, __float_as_int(s));
}

// ---------------- aggregate: one warp per row, half-warp per edge ----------------
// half-warp lane hl (0-15) accumulates cols hl*8..hl*8+7 for edge c
__device__ __forceinline__ void gacc16(int c, float sv, int hl,
                                       const __half* __restrict__ g, float acc[8]) {
    uint4 u = __ldg((const uint4*)(g + (size_t)c * D) + hl);
    float2 f0 = __half22float2(*reinterpret_cast<__half2*>(&u.x));
    float2 f1 = __half22float2(*reinterpret_cast<__half2*>(&u.y));
    float2 f2 = __half22float2(*reinterpret_cast<__half2*>(&u.z));
    float2 f3 = __half22float2(*reinterpret_cast<__half2*>(&u.w));
    acc[0] += sv * f0.x; acc[1] += sv * f0.y;
    acc[2] += sv * f1.x; acc[3] += sv * f1.y;
    acc[4] += sv * f2.x; acc[5] += sv * f2.y;
    acc[6] += sv * f3.x; acc[7] += sv * f3.y;
}

__global__ __launch_bounds__(256)
void agg_kernel(const int* __restrict__ offs, const int2* __restrict__ sedge,
                const __half* __restrict__ g, float* __restrict__ out, int n0) {
    int row = blockIdx.x * 8 + (threadIdx.x >> 5);
    if (row >= n0) return;
    int lane = threadIdx.x & 31;
    int hw = lane >> 4;        // half-warp id 0/1
    int hl = lane & 15;        // lane within half-warp
    float acc[8];
#pragma unroll
    for (int j = 0; j < 8; j++) acc[j] = 0.f;
    int s = __ldg(offs + row), e = __ldg(offs + row + 1);
    int i = s + hw;
    for (; i + 2 < e; i += 4) {
        int2 ea = __ldg(sedge + i);
        int2 eb = __ldg(sedge + i + 2);
        gacc16(ea.x, __int_as_float(ea.y), hl, g, acc);
        gacc16(eb.x, __int_as_float(eb.y), hl, g, acc);
    }
    for (; i < e; i += 2) {
        int2 ea = __ldg(sedge + i);
        gacc16(ea.x, __int_as_float(ea.y), hl, g, acc);
    }
#pragma unroll
    for (int j = 0; j < 8; j++) acc[j] += __shfl_down_sync(0xffffffffu, acc[j], 16);
    if (hw == 0) {
        float4* op = (float4*)(out + (size_t)row * D + hl * 8);
        float4 c0 = op[0], c1 = op[1];
        c0.x += acc[0]; c0.y += acc[1]; c0.z += acc[2]; c0.w += acc[3];
        c1.x += acc[4]; c1.y += acc[5]; c1.z += acc[6]; c1.w += acc[7];
        op[0] = c0;
        op[1] = c1;
    }
}

// ---------------- launch ----------------
extern "C" void kernel_launch(void* const* d_in, const int* in_sizes, int n_in,
                              void* d_out, int out_size) {
    const float* x0   = (const float*)d_in[0];
    const float* x1   = (const float*)d_in[1];
    const float* x2   = (const float*)d_in[2];
    const float* W1   = (const float*)d_in[3];
    const float* b1   = (const float*)d_in[4];
    const float* a1w  = (const float*)d_in[5];
    const float* a1b  = (const float*)d_in[6];
    const float* a2w  = (const float*)d_in[7];
    const float* a2b  = (const float*)d_in[8];
    const float* Wagg = (const float*)d_in[9];
    const float* bagg = (const float*)d_in[10];
    const int* ar0 = (const int*)d_in[11];
    const int* ac0 = (const int*)d_in[12];
    const int* ar1 = (const int*)d_in[13];
    const int* ac1 = (const int*)d_in[14];
    const int* ar2 = (const int*)d_in[15];
    const int* ac2 = (const int*)d_in[16];
    float* out = (float*)d_out;

    const int N0 = in_sizes[0] / D;
    const int N1 = in_sizes[1] / D;
    const int N2 = in_sizes[2] / D;
    const int E0 = in_sizes[11];
    const int E1 = in_sizes[13];
    const int E2 = in_sizes[15];

    __half* pg;
    float *pa2, *pa1;
    int *pcnt, *poff, *pcur, *pbsum;
    int2* psedge;
    unsigned char* pwp;
    cudaGetSymbolAddress((void**)&pg, g_gall);
    cudaGetSymbolAddress((void**)&pa2, g_a2all);
    cudaGetSymbolAddress((void**)&pa1, g_a1_0);
    cudaGetSymbolAddress((void**)&pcnt, g_cnt);
    cudaGetSymbolAddress((void**)&poff, g_off);
    cudaGetSymbolAddress((void**)&pcur, g_cur);
    cudaGetSymbolAddress((void**)&psedge, g_sedge);
    cudaGetSymbolAddress((void**)&pwp, g_wprep);
    cudaGetSymbolAddress((void**)&pbsum, g_bsum);

    cudaFuncSetAttribute(node_mm, cudaFuncAttributeMaxDynamicSharedMemorySize, SMEM_REQ);

    #define WHI(m) (pwp + (size_t)(m) * 2 * 32768)

    prep_w<<<5, 256>>>(W1, Wagg, pwp);
    zero_kernel<<<(N0 + 256) / 256, 256>>>(pcnt, N0 + 1);
    const int ET = E0 + E1 + E2;
    hist_kernel<<<(ET + 255) / 256, 256>>>(ar0, E0, ar1, E1, ar2, E2, pcnt);
    const int NB = (N0 + SCAN_CHUNK - 1) / SCAN_CHUNK;
    scanA_kernel<<<NB, 1024>>>(pcnt, N0, pbsum);
    scanB_kernel<<<1, 32>>>(pbsum, NB);
    scanC_kernel<<<NB, 1024>>>(pcnt, N0, pbsum, poff, pcur);

    // node kernels first (produce a1/a2/g); scat consumes a1/a2 afterwards
    node_mm<<<(N0 + 127) / 128, 256, SMEM_REQ>>>(
        x0, N0, WHI(0), WHI(2), WHI(1),
        b1, a1w, a1b, a2w, a2b, bagg,
        pg, pa1, pa2, out);
    node_mm<<<(N1 + 127) / 128, 256, SMEM_REQ>>>(
        x1, N1, WHI(0), WHI(3), nullptr,
        b1, a1w, a1b, a2w, a2b, bagg,
        pg + (size_t)N0 * D, nullptr, pa2 + N0, nullptr);
    node_mm<<<(N2 + 127) / 128, 256, SMEM_REQ>>>(
        x2, N2, WHI(0), WHI(4), nullptr,
        b1, a1w, a1b, a2w, a2b, bagg,
        pg + (size_t)(N0 + N1) * D, nullptr, pa2 + N0 + N1, nullptr);

    scat_kernel<<<(ET + 255) / 256, 256>>>(ar0, ac0, E0, ar1, ac1, E1, ar2, ac2, E2,
                                           N0, N0 + N1, pa1, pa2, pcur, psedge);

    agg_kernel<<<(N0 + 7) / 8, 256>>>(poff, psedge, pg, out, N0);
}

// round 15
// speedup vs baseline: 4.5096x; 1.1056x over previous
#include <cuda_runtime.h>
#include <cuda_fp16.h>
#include <cstdint>

#define D 128
#define N0MAX 100000
#define NALL  (100000 + 150000 + 80000)
#define EALL  3000000
#define SCAN_CHUNK 4096
#define SCAN_BLOCKS ((N0MAX + SCAN_CHUNK - 1) / SCAN_CHUNK)

typedef unsigned long long ull;
typedef unsigned int u32;

// ---------------- static scratch (allocation-free rule) ----------------
__device__ __half g_gall[(size_t)NALL * 128];   // fp16 projected features, concat [g0|g1|g2]
__device__ float g_a2all[NALL];                 // concat [a2_0|a2_1|a2_2]
__device__ float g_a1_0[N0MAX];
// prepped weights: 5 matrices (W1, Wagg0..3) x 32KB fp16 tiles (hi plane only used),
// transposed to [n][k], 16B-chunk XOR-swizzled (ldmatrix-ready, raw smem copy)
__device__ unsigned char g_wprep[5 * 2 * 32768];
// combined CSR scratch
__device__ int g_cnt[N0MAX + 1];
__device__ int g_off[N0MAX + 1];
__device__ int g_cur[N0MAX];
__device__ int2 g_sedge[EALL];                  // {col, sigmoid-weight bits} per binned edge
__device__ int g_bsum[SCAN_BLOCKS + 1];

__device__ __forceinline__ u32 smem_to_u32(const void* p) {
    u32 a;
    asm("{ .reg .u64 t; cvta.to.shared.u64 t, %1; cvt.u32.u64 %0, t; }" : "=r"(a) : "l"(p));
    return a;
}

// byte offset of 16B chunk (row, kc) in a 128x128 fp16 tile (256B rows),
// XOR swizzle on chunk index by row&7 -> conflict-free ldmatrix + staging
#define CH(row, kc) ((u32)((row) * 256 + ((((kc)) ^ ((row) & 7)) << 4)))

// pack 8 fp32 -> fp16 uint4
__device__ __forceinline__ uint4 pack8h(const float* v) {
    u32 hw[4];
#pragma unroll
    for (int j = 0; j < 4; j++) {
        __half2 hh = __floats2half2_rn(v[2 * j], v[2 * j + 1]);
        hw[j] = *(u32*)&hh;
    }
    return make_uint4(hw[0], hw[1], hw[2], hw[3]);
}

// ---------------- weight prep: transpose + fp16 + swizzle (40 blocks) ----------
__global__ void prep_w(const float* __restrict__ W1, const float* __restrict__ Wagg,
                       unsigned char* __restrict__ wp) {
    int m = blockIdx.x >> 3, it = blockIdx.x & 7, tid = threadIdx.x;
    unsigned char* hip = wp + (size_t)m * 2 * 32768;
    int f = it * 256 + tid;               // chunk id 0..2047
    int n = f >> 4, kc = f & 15, k0 = kc * 8;
    float v[8];
#pragma unroll
    for (int j = 0; j < 8; j++) {
        int k = k0 + j;
        v[j] = (m == 0) ? W1[k * 128 + n] : Wagg[((m - 1) * 128 + k) * 128 + n];
    }
    *(uint4*)(hip + CH(n, kc)) = pack8h(v);
}

// ---------------- node kernel (mma.sync m16n8k16 fp16, single pass, merged) --
// smem: A (fp16) | W (fp16) | header  => 68KB, 2 CTAs/SM
#define OFF_A    0
#define OFF_W    32768
#define OFF_HDR  65536
#define SMEM_REQ (65536 + 3072 + 1024)

__device__ __forceinline__ void copy32k(void* dst, const void* src, int tid) {
    const uint4* s = (const uint4*)src;
    uint4* d = (uint4*)dst;
#pragma unroll
    for (int i = 0; i < 8; i++) d[tid + i * 256] = s[tid + i * 256];
}

// full K=128 (8 k-steps) of the 128x128 GEMM for this warp
__device__ __forceinline__ void gemm_pass(u32 Ab, u32 Wb, int r0, int cbase, int lane,
                                          float c[2][8][4]) {
    const int q = lane >> 3, sr = lane & 7;
#pragma unroll
    for (int mt = 0; mt < 2; mt++)
#pragma unroll
        for (int nt = 0; nt < 8; nt++)
#pragma unroll
            for (int j = 0; j < 4; j++) c[mt][nt][j] = 0.f;
#pragma unroll 1
    for (int ks = 0; ks < 8; ks++) {
        u32 a[2][4];
#pragma unroll
        for (int mt = 0; mt < 2; mt++) {
            int row = r0 + mt * 16 + ((q & 1) << 3) + sr;
            int kc = 2 * ks + (q >> 1);
            u32 ad = Ab + CH(row, kc);
            asm volatile("ldmatrix.sync.aligned.m8n8.x4.shared.b16 {%0,%1,%2,%3}, [%4];"
                         : "=r"(a[mt][0]), "=r"(a[mt][1]), "=r"(a[mt][2]), "=r"(a[mt][3])
                         : "r"(ad));
        }
        u32 b[8][2];
#pragma unroll
        for (int nb = 0; nb < 4; nb++) {
            int rown = cbase + nb * 16 + ((q >> 1) << 3) + sr;
            int kc = 2 * ks + (q & 1);
            u32 ad = Wb + CH(rown, kc);
            asm volatile("ldmatrix.sync.aligned.m8n8.x4.shared.b16 {%0,%1,%2,%3}, [%4];"
                         : "=r"(b[2 * nb][0]), "=r"(b[2 * nb][1]),
                           "=r"(b[2 * nb + 1][0]), "=r"(b[2 * nb + 1][1])
                         : "r"(ad));
        }
#pragma unroll
        for (int mt = 0; mt < 2; mt++)
#pragma unroll
            for (int nt = 0; nt < 8; nt++)
                asm volatile("mma.sync.aligned.m16n8k16.row.col.f32.f16.f16.f32 "
                             "{%0,%1,%2,%3}, {%4,%5,%6,%7}, {%8,%9}, {%0,%1,%2,%3};"
                             : "+f"(c[mt][nt][0]), "+f"(c[mt][nt][1]),
                               "+f"(c[mt][nt][2]), "+f"(c[mt][nt][3])
                             : "r"(a[mt][0]), "r"(a[mt][1]), "r"(a[mt][2]), "r"(a[mt][3]),
                               "r"(b[nt][0]), "r"(b[nt][1]));
    }
}

__global__ __launch_bounds__(256, 2)
void node_all(const float* __restrict__ x0, const float* __restrict__ x1,
              const float* __restrict__ x2,
              int N0, int N1, int N2, int NB0, int NB1,
              const unsigned char* __restrict__ w1p,
              const unsigned char* __restrict__ wg0p,
              const unsigned char* __restrict__ wg1p,
              const unsigned char* __restrict__ wg2p,
              const unsigned char* __restrict__ wsp,
              const float* __restrict__ b1,
              const float* __restrict__ a1w, const float* __restrict__ a1bp,
              const float* __restrict__ a2w, const float* __restrict__ a2bp,
              const float* __restrict__ bagg,
              __half* __restrict__ gall, float* __restrict__ a1out,
              float* __restrict__ a2all, float* __restrict__ selfout) {
    extern __shared__ char sraw[];
    const u32 sb = smem_to_u32(sraw);
    const u32 base = (sb + 1023u) & ~1023u;
    char* bp = sraw + (base - sb);
    float* sBB  = (float*)(bp + OFF_HDR);
    float* sAW1 = sBB + 128;
    float* sAW2 = sAW1 + 128;
    float* sBG  = sAW2 + 128;
    float* sPA1 = sBG + 128;
    float* sPA2 = sPA1 + 128;

    // dataset select by block id
    int b = blockIdx.x;
    const float* x;
    const unsigned char* wgh;
    int nrows, goff, tile;
    bool ds0 = false;
    if (b < NB0) {
        x = x0; nrows = N0; goff = 0; wgh = wg0p; tile = b; ds0 = true;
    } else if (b < NB0 + NB1) {
        x = x1; nrows = N1; goff = N0; wgh = wg1p; tile = b - NB0;
    } else {
        x = x2; nrows = N2; goff = N0 + N1; wgh = wg2p; tile = b - NB0 - NB1;
    }
    __half* gout = gall + (size_t)goff * D;
    float* a2out = a2all + goff;
    const int rbase = tile * 128;

    const int tid = threadIdx.x, wid = tid >> 5, lane = tid & 31;
    const int wm = wid & 3, wn = wid >> 2;
    const int r0 = wm * 32, cbase = wn * 64;
    const u32 sA = base + OFF_A;
    const u32 sW = base + OFF_W;

    if (tid < 128) {
        sBB[tid] = b1[tid];
        sAW1[tid] = a1w[tid];
        sAW2[tid] = a2w[tid];
        sBG[tid] = bagg[tid];
    }
    copy32k(bp + OFF_W, w1p, tid);
#pragma unroll 1
    for (int it = 0; it < 8; it++) {
        int f = tid + it * 256;
        int row = f >> 4, kc = f & 15;
        float v[8];
        if (rbase + row < nrows) {
            const float4* xp = (const float4*)(x + (size_t)(rbase + row) * 128 + kc * 8);
            float4 p0 = xp[0], p1 = xp[1];
            v[0] = p0.x; v[1] = p0.y; v[2] = p0.z; v[3] = p0.w;
            v[4] = p1.x; v[5] = p1.y; v[6] = p1.z; v[7] = p1.w;
        } else {
#pragma unroll
            for (int j = 0; j < 8; j++) v[j] = 0.f;
        }
        *(uint4*)(bp + OFF_A + CH(row, kc)) = pack8h(v);
    }
    __syncthreads();

    float c[2][8][4];
    float pph1[4], pph2[4];

    // ---- GEMM1: h = x @ W1^T ----
    gemm_pass(sA, sW, r0, cbase, lane, c);
    __syncthreads();   // all warps done reading sA(x)/sW before overwrite

    // epilogue 1: bias+relu, attention dots, h -> sA fp16
#pragma unroll
    for (int mt = 0; mt < 2; mt++)
#pragma unroll
        for (int half = 0; half < 2; half++) {
            int row = r0 + mt * 16 + half * 8 + (lane >> 2);
            float ph1 = 0.f, ph2 = 0.f;
#pragma unroll
            for (int nt = 0; nt < 8; nt++) {
                int col = cbase + nt * 8 + 2 * (lane & 3);
                float h0 = fmaxf(c[mt][nt][half * 2 + 0] + sBB[col], 0.f);
                float h1 = fmaxf(c[mt][nt][half * 2 + 1] + sBB[col + 1], 0.f);
                ph1 += h0 * sAW1[col] + h1 * sAW1[col + 1];
                ph2 += h0 * sAW2[col] + h1 * sAW2[col + 1];
                __half2 hhi = __floats2half2_rn(h0, h1);
                u32 ao = (u32)(row * 256 + (((col >> 3) ^ (row & 7)) << 4) + (col & 7) * 2);
                *(u32*)(bp + OFF_A + ao) = *(u32*)&hhi;
            }
            ph1 += __shfl_xor_sync(0xffffffffu, ph1, 1);
            ph1 += __shfl_xor_sync(0xffffffffu, ph1, 2);
            ph2 += __shfl_xor_sync(0xffffffffu, ph2, 1);
            ph2 += __shfl_xor_sync(0xffffffffu, ph2, 2);
            pph1[mt * 2 + half] = ph1;
            pph2[mt * 2 + half] = ph2;
            if (wn == 0 && (lane & 3) == 0) {
                sPA1[row] = ph1;
                sPA2[row] = ph2;
            }
        }
    copy32k(bp + OFF_W, wgh, tid);   // stage Wg (safe: post-GEMM1 barrier above)
    __syncthreads();
    if (wn == 1 && (lane & 3) == 0) {
        const float a1b = *a1bp, a2b = *a2bp;
#pragma unroll
        for (int mt = 0; mt < 2; mt++)
#pragma unroll
            for (int half = 0; half < 2; half++) {
                int row = r0 + mt * 16 + half * 8 + (lane >> 2);
                int grow = rbase + row;
                if (grow < nrows) {
                    if (ds0) a1out[grow] = sPA1[row] + pph1[mt * 2 + half] + a1b;
                    a2out[grow] = sPA2[row] + pph2[mt * 2 + half] + a2b;
                }
            }
    }

    // ---- GEMM2: g = h @ Wg^T -> fp16 global ----
    gemm_pass(sA, sW, r0, cbase, lane, c);
#pragma unroll
    for (int mt = 0; mt < 2; mt++)
#pragma unroll
        for (int half = 0; half < 2; half++) {
            int row = r0 + mt * 16 + half * 8 + (lane >> 2);
            int grow = rbase + row;
            if (grow < nrows) {
#pragma unroll
                for (int nt = 0; nt < 8; nt++) {
                    int col = cbase + nt * 8 + 2 * (lane & 3);
                    __half2 hv = __floats2half2_rn(c[mt][nt][half * 2 + 0],
                                                   c[mt][nt][half * 2 + 1]);
                    *(u32*)(gout + (size_t)grow * D + col) = *(u32*)&hv;
                }
            }
        }

    // ---- GEMM3 (x0 only): self = h @ Wself^T + bagg -> out ----
    if (ds0) {
        __syncthreads();   // all warps done reading sW(Wg)
        copy32k(bp + OFF_W, wsp, tid);
        __syncthreads();
        gemm_pass(sA, sW, r0, cbase, lane, c);
#pragma unroll
        for (int mt = 0; mt < 2; mt++)
#pragma unroll
            for (int half = 0; half < 2; half++) {
                int row = r0 + mt * 16 + half * 8 + (lane >> 2);
                int grow = rbase + row;
                if (grow < nrows) {
#pragma unroll
                    for (int nt = 0; nt < 8; nt++) {
                        int col = cbase + nt * 8 + 2 * (lane & 3);
                        float2 v = make_float2(c[mt][nt][half * 2 + 0] + sBG[col],
                                               c[mt][nt][half * 2 + 1] + sBG[col + 1]);
                        *(float2*)(selfout + (size_t)grow * D + col) = v;
                    }
                }
            }
    }
}

// ---------------- binning kernels (combined CSR over all 3 lists) ----------------
__global__ void zero_kernel(int* p, int n) {
    int i = blockIdx.x * blockDim.x + threadIdx.x;
    if (i < n) p[i] = 0;
}

__global__ void hist_kernel(const int* __restrict__ r0, int E0,
                            const int* __restrict__ r1, int E1,
                            const int* __restrict__ r2, int E2,
                            int* __restrict__ cnt) {
    int t = blockIdx.x * blockDim.x + threadIdx.x;
    int row;
    if (t < E0) row = __ldg(r0 + t);
    else if ((t -= E0) < E1) row = __ldg(r1 + t);
    else if ((t -= E1) < E2) row = __ldg(r2 + t);
    else return;
    atomicAdd(&cnt[row], 1);
}

// ---- parallel scan phase A: per-block sums of 4096-element chunks ----
__global__ __launch_bounds__(1024)
void scanA_kernel(const int* __restrict__ cnt, int n, int* __restrict__ bsum) {
    __shared__ int wsum[32];
    const int tid = threadIdx.x, lane = tid & 31, wid = tid >> 5;
    int idx = blockIdx.x * SCAN_CHUNK + tid * 4;
    int s = 0;
#pragma unroll
    for (int j = 0; j < 4; j++) s += (idx + j < n) ? cnt[idx + j] : 0;
#pragma unroll
    for (int off = 16; off >= 1; off >>= 1) s += __shfl_down_sync(0xffffffffu, s, off);
    if (lane == 0) wsum[wid] = s;
    __syncthreads();
    if (wid == 0) {
        int y = wsum[lane];
#pragma unroll
        for (int off = 16; off >= 1; off >>= 1) y += __shfl_down_sync(0xffffffffu, y, off);
        if (lane == 0) bsum[blockIdx.x] = y;
    }
}

// ---- phase B: exclusive scan of block sums (1 warp) ----
__global__ void scanB_kernel(int* __restrict__ bsum, int nb) {
    int lane = threadIdx.x;
    int v = (lane < nb) ? bsum[lane] : 0;
    int x = v;
#pragma unroll
    for (int off = 1; off < 32; off <<= 1) {
        int t = __shfl_up_sync(0xffffffffu, x, off);
        if (lane >= off) x += t;
    }
    if (lane <= nb && lane < 32) bsum[lane] = x - v;   // exclusive
    if (lane == 31) bsum[nb] = x;   // total (nb<=25<32)
}

// ---- phase C: per-block exclusive scan + block offset -> offs, cur ----
__global__ __launch_bounds__(1024)
void scanC_kernel(const int* __restrict__ cnt, int n, const int* __restrict__ bsum,
                  int* __restrict__ offs, int* __restrict__ cur) {
    __shared__ int wsum[32];
    const int tid = threadIdx.x, lane = tid & 31, wid = tid >> 5;
    int idx = blockIdx.x * SCAN_CHUNK + tid * 4;
    int v[4];
#pragma unroll
    for (int j = 0; j < 4; j++) v[j] = (idx + j < n) ? cnt[idx + j] : 0;
    int tsum = v[0] + v[1] + v[2] + v[3];
    int xv = tsum;
#pragma unroll
    for (int off = 1; off < 32; off <<= 1) {
        int t = __shfl_up_sync(0xffffffffu, xv, off);
        if (lane >= off) xv += t;
    }
    if (lane == 31) wsum[wid] = xv;
    __syncthreads();
    if (wid == 0) {
        int y = wsum[lane];
#pragma unroll
        for (int off = 1; off < 32; off <<= 1) {
            int t = __shfl_up_sync(0xffffffffu, y, off);
            if (lane >= off) y += t;
        }
        wsum[lane] = y;
    }
    __syncthreads();
    int warpoff = (wid == 0) ? 0 : wsum[wid - 1];
    int excl = bsum[blockIdx.x] + warpoff + xv - tsum;
#pragma unroll
    for (int j = 0; j < 4; j++) {
        if (idx + j < n) { offs[idx + j] = excl; cur[idx + j] = excl; }
        excl += v[j];
    }
    if (blockIdx.x == 0 && tid == 0) offs[n] = bsum[(n + SCAN_CHUNK - 1) / SCAN_CHUNK];
}

// ---- scat (runs AFTER node kernels): bin edge + fuse sigmoid weight ----
__device__ __forceinline__ float fsig(float s) {
    return 1.0f / (1.0f + __expf(-s));
}

__global__ void scat_kernel(const int* __restrict__ r0, const int* __restrict__ c0, int E0,
                            const int* __restrict__ r1, const int* __restrict__ c1, int E1,
                            const int* __restrict__ r2, const int* __restrict__ c2, int E2,
                            int base1, int base2,
                            const float* __restrict__ a1, const float* __restrict__ a2,
                            int* __restrict__ cur, int2* __restrict__ sedge) {
    int t = blockIdx.x * blockDim.x + threadIdx.x;
    int row, col;
    if (t < E0) { row = __ldg(r0 + t); col = __ldg(c0 + t); }
    else if ((t -= E0) < E1) { row = __ldg(r1 + t); col = __ldg(c1 + t) + base1; }
    else if ((t -= E1) < E2) { row = __ldg(r2 + t); col = __ldg(c2 + t) + base2; }
    else return;
    float s = fsig(__ldg(a1 + row) + __ldg(a2 + col));
    int p = atomicAdd(&cur[row], 1);
    sedge[p] = make_int2(col, __float_as_int(s));
}

// ---------------- aggregate: one warp per row, half-warp per edge ----------------
// half-warp lane hl (0-15) accumulates cols hl*8..hl*8+7 for edge c
__device__ __forceinline__ void gacc16(int c, float sv, int hl,
                                       const __half* __restrict__ g, float acc[8]) {
    uint4 u = __ldg((const uint4*)(g + (size_t)c * D) + hl);
    float2 f0 = __half22float2(*reinterpret_cast<__half2*>(&u.x));
    float2 f1 = __half22float2(*reinterpret_cast<__half2*>(&u.y));
    float2 f2 = __half22float2(*reinterpret_cast<__half2*>(&u.z));
    float2 f3 = __half22float2(*reinterpret_cast<__half2*>(&u.w));
    acc[0] += sv * f0.x; acc[1] += sv * f0.y;
    acc[2] += sv * f1.x; acc[3] += sv * f1.y;
    acc[4] += sv * f2.x; acc[5] += sv * f2.y;
    acc[6] += sv * f3.x; acc[7] += sv * f3.y;
}

__global__ __launch_bounds__(256)
void agg_kernel(const int* __restrict__ offs, const int2* __restrict__ sedge,
                const __half* __restrict__ g, float* __restrict__ out, int n0) {
    int row = blockIdx.x * 8 + (threadIdx.x >> 5);
    if (row >= n0) return;
    int lane = threadIdx.x & 31;
    int hw = lane >> 4;        // half-warp id 0/1
    int hl = lane & 15;        // lane within half-warp
    float acc[8];
#pragma unroll
    for (int j = 0; j < 8; j++) acc[j] = 0.f;
    int s = __ldg(offs + row), e = __ldg(offs + row + 1);
    int i = s + hw;
    for (; i + 2 < e; i += 4) {
        int2 ea = __ldg(sedge + i);
        int2 eb = __ldg(sedge + i + 2);
        gacc16(ea.x, __int_as_float(ea.y), hl, g, acc);
        gacc16(eb.x, __int_as_float(eb.y), hl, g, acc);
    }
    for (; i < e; i += 2) {
        int2 ea = __ldg(sedge + i);
        gacc16(ea.x, __int_as_float(ea.y), hl, g, acc);
    }
#pragma unroll
    for (int j = 0; j < 8; j++) acc[j] += __shfl_down_sync(0xffffffffu, acc[j], 16);
    if (hw == 0) {
        float4* op = (float4*)(out + (size_t)row * D + hl * 8);
        float4 c0 = op[0], c1 = op[1];
        c0.x += acc[0]; c0.y += acc[1]; c0.z += acc[2]; c0.w += acc[3];
        c1.x += acc[4]; c1.y += acc[5]; c1.z += acc[6]; c1.w += acc[7];
        op[0] = c0;
        op[1] = c1;
    }
}

// ---------------- launch ----------------
extern "C" void kernel_launch(void* const* d_in, const int* in_sizes, int n_in,
                              void* d_out, int out_size) {
    const float* x0   = (const float*)d_in[0];
    const float* x1   = (const float*)d_in[1];
    const float* x2   = (const float*)d_in[2];
    const float* W1   = (const float*)d_in[3];
    const float* b1   = (const float*)d_in[4];
    const float* a1w  = (const float*)d_in[5];
    const float* a1b  = (const float*)d_in[6];
    const float* a2w  = (const float*)d_in[7];
    const float* a2b  = (const float*)d_in[8];
    const float* Wagg = (const float*)d_in[9];
    const float* bagg = (const float*)d_in[10];
    const int* ar0 = (const int*)d_in[11];
    const int* ac0 = (const int*)d_in[12];
    const int* ar1 = (const int*)d_in[13];
    const int* ac1 = (const int*)d_in[14];
    const int* ar2 = (const int*)d_in[15];
    const int* ac2 = (const int*)d_in[16];
    float* out = (float*)d_out;

    const int N0 = in_sizes[0] / D;
    const int N1 = in_sizes[1] / D;
    const int N2 = in_sizes[2] / D;
    const int E0 = in_sizes[11];
    const int E1 = in_sizes[13];
    const int E2 = in_sizes[15];

    __half* pg;
    float *pa2, *pa1;
    int *pcnt, *poff, *pcur, *pbsum;
    int2* psedge;
    unsigned char* pwp;
    cudaGetSymbolAddress((void**)&pg, g_gall);
    cudaGetSymbolAddress((void**)&pa2, g_a2all);
    cudaGetSymbolAddress((void**)&pa1, g_a1_0);
    cudaGetSymbolAddress((void**)&pcnt, g_cnt);
    cudaGetSymbolAddress((void**)&poff, g_off);
    cudaGetSymbolAddress((void**)&pcur, g_cur);
    cudaGetSymbolAddress((void**)&psedge, g_sedge);
    cudaGetSymbolAddress((void**)&pwp, g_wprep);
    cudaGetSymbolAddress((void**)&pbsum, g_bsum);

    cudaFuncSetAttribute(node_all, cudaFuncAttributeMaxDynamicSharedMemorySize, SMEM_REQ);

    #define WHI(m) (pwp + (size_t)(m) * 2 * 32768)

    prep_w<<<40, 256>>>(W1, Wagg, pwp);
    zero_kernel<<<(N0 + 256) / 256, 256>>>(pcnt, N0 + 1);
    const int ET = E0 + E1 + E2;
    hist_kernel<<<(ET + 255) / 256, 256>>>(ar0, E0, ar1, E1, ar2, E2, pcnt);
    const int NB = (N0 + SCAN_CHUNK - 1) / SCAN_CHUNK;
    scanA_kernel<<<NB, 1024>>>(pcnt, N0, pbsum);
    scanB_kernel<<<1, 32>>>(pbsum, NB);
    scanC_kernel<<<NB, 1024>>>(pcnt, N0, pbsum, poff, pcur);

    // merged node kernel: datasets 0/1/2 by block range
    const int NB0 = (N0 + 127) / 128;
    const int NB1 = (N1 + 127) / 128;
    const int NB2 = (N2 + 127) / 128;
    node_all<<<NB0 + NB1 + NB2, 256, SMEM_REQ>>>(
        x0, x1, x2, N0, N1, N2, NB0, NB1,
        WHI(0), WHI(2), WHI(3), WHI(4), WHI(1),
        b1, a1w, a1b, a2w, a2b, bagg,
        pg, pa1, pa2, out);

    scat_kernel<<<(ET + 255) / 256, 256>>>(ar0, ac0, E0, ar1, ac1, E1, ar2, ac2, E2,
                                           N0, N0 + N1, pa1, pa2, pcur, psedge);

    agg_kernel<<<(N0 + 7) / 8, 256>>>(poff, psedge, pg, out, N0);
}

// round 16
// speedup vs baseline: 4.6346x; 1.0277x over previous
#include <cuda_runtime.h>
#include <cuda_fp16.h>
#include <cstdint>

#define D 128
#define N0MAX 100000
#define NALL  (100000 + 150000 + 80000)
#define EALL  3000000
#define SCAN_CHUNK 4096
#define SCAN_BLOCKS ((N0MAX + SCAN_CHUNK - 1) / SCAN_CHUNK)

typedef unsigned long long ull;
typedef unsigned int u32;

// ---------------- static scratch (allocation-free rule) ----------------
__device__ __half g_gall[(size_t)NALL * 128];   // fp16 projected features, concat [g0|g1|g2]
__device__ float g_a2all[NALL];                 // concat [a2_0|a2_1|a2_2]
__device__ float g_a1_0[N0MAX];
// prepped weights: 5 matrices (W1, Wagg0..3) x 32KB fp16 tiles (hi plane only used),
// transposed to [n][k], 16B-chunk XOR-swizzled (ldmatrix-ready, raw smem copy)
__device__ unsigned char g_wprep[5 * 2 * 32768];
// combined CSR scratch
__device__ int g_cnt[N0MAX + 1];
__device__ int g_off[N0MAX + 1];
__device__ int g_cur[N0MAX];
__device__ int2 g_sedge[EALL];                  // {col, sigmoid-weight bits} per binned edge
__device__ int g_bsum[SCAN_BLOCKS + 1];

__device__ __forceinline__ u32 smem_to_u32(const void* p) {
    u32 a;
    asm("{ .reg .u64 t; cvta.to.shared.u64 t, %1; cvt.u32.u64 %0, t; }" : "=r"(a) : "l"(p));
    return a;
}

// byte offset of 16B chunk (row, kc) in a 128x128 fp16 tile (256B rows),
// XOR swizzle on chunk index by row&7 -> conflict-free ldmatrix + staging
#define CH(row, kc) ((u32)((row) * 256 + ((((kc)) ^ ((row) & 7)) << 4)))

// pack 8 fp32 -> fp16 uint4
__device__ __forceinline__ uint4 pack8h(const float* v) {
    u32 hw[4];
#pragma unroll
    for (int j = 0; j < 4; j++) {
        __half2 hh = __floats2half2_rn(v[2 * j], v[2 * j + 1]);
        hw[j] = *(u32*)&hh;
    }
    return make_uint4(hw[0], hw[1], hw[2], hw[3]);
}

// ---------------- weight prep: transpose + fp16 + swizzle (40 blocks) ----------
__global__ void prep_w(const float* __restrict__ W1, const float* __restrict__ Wagg,
                       unsigned char* __restrict__ wp) {
    int m = blockIdx.x >> 3, it = blockIdx.x & 7, tid = threadIdx.x;
    unsigned char* hip = wp + (size_t)m * 2 * 32768;
    int f = it * 256 + tid;               // chunk id 0..2047
    int n = f >> 4, kc = f & 15, k0 = kc * 8;
    float v[8];
#pragma unroll
    for (int j = 0; j < 8; j++) {
        int k = k0 + j;
        v[j] = (m == 0) ? W1[k * 128 + n] : Wagg[((m - 1) * 128 + k) * 128 + n];
    }
    *(uint4*)(hip + CH(n, kc)) = pack8h(v);
}

// ---------------- node kernel (mma.sync m16n8k16 fp16, single pass, merged) --
// smem: A (fp16) | W (fp16) | header  => 68KB, 2 CTAs/SM
#define OFF_A    0
#define OFF_W    32768
#define OFF_HDR  65536
#define SMEM_REQ (65536 + 3072 + 1024)

__device__ __forceinline__ void copy32k(void* dst, const void* src, int tid) {
    const uint4* s = (const uint4*)src;
    uint4* d = (uint4*)dst;
#pragma unroll
    for (int i = 0; i < 8; i++) d[tid + i * 256] = s[tid + i * 256];
}

// full K=128 (8 k-steps) of the 128x128 GEMM for this warp
__device__ __forceinline__ void gemm_pass(u32 Ab, u32 Wb, int r0, int cbase, int lane,
                                          float c[2][8][4]) {
    const int q = lane >> 3, sr = lane & 7;
#pragma unroll
    for (int mt = 0; mt < 2; mt++)
#pragma unroll
        for (int nt = 0; nt < 8; nt++)
#pragma unroll
            for (int j = 0; j < 4; j++) c[mt][nt][j] = 0.f;
#pragma unroll 1
    for (int ks = 0; ks < 8; ks++) {
        u32 a[2][4];
#pragma unroll
        for (int mt = 0; mt < 2; mt++) {
            int row = r0 + mt * 16 + ((q & 1) << 3) + sr;
            int kc = 2 * ks + (q >> 1);
            u32 ad = Ab + CH(row, kc);
            asm volatile("ldmatrix.sync.aligned.m8n8.x4.shared.b16 {%0,%1,%2,%3}, [%4];"
                         : "=r"(a[mt][0]), "=r"(a[mt][1]), "=r"(a[mt][2]), "=r"(a[mt][3])
                         : "r"(ad));
        }
        u32 b[8][2];
#pragma unroll
        for (int nb = 0; nb < 4; nb++) {
            int rown = cbase + nb * 16 + ((q >> 1) << 3) + sr;
            int kc = 2 * ks + (q & 1);
            u32 ad = Wb + CH(rown, kc);
            asm volatile("ldmatrix.sync.aligned.m8n8.x4.shared.b16 {%0,%1,%2,%3}, [%4];"
                         : "=r"(b[2 * nb][0]), "=r"(b[2 * nb][1]),
                           "=r"(b[2 * nb + 1][0]), "=r"(b[2 * nb + 1][1])
                         : "r"(ad));
        }
#pragma unroll
        for (int mt = 0; mt < 2; mt++)
#pragma unroll
            for (int nt = 0; nt < 8; nt++)
                asm volatile("mma.sync.aligned.m16n8k16.row.col.f32.f16.f16.f32 "
                             "{%0,%1,%2,%3}, {%4,%5,%6,%7}, {%8,%9}, {%0,%1,%2,%3};"
                             : "+f"(c[mt][nt][0]), "+f"(c[mt][nt][1]),
                               "+f"(c[mt][nt][2]), "+f"(c[mt][nt][3])
                             : "r"(a[mt][0]), "r"(a[mt][1]), "r"(a[mt][2]), "r"(a[mt][3]),
                               "r"(b[nt][0]), "r"(b[nt][1]));
    }
}

__global__ __launch_bounds__(256, 2)
void node_all(const float* __restrict__ x0, const float* __restrict__ x1,
              const float* __restrict__ x2,
              int N0, int N1, int N2, int NB0, int NB1,
              const unsigned char* __restrict__ w1p,
              const unsigned char* __restrict__ wg0p,
              const unsigned char* __restrict__ wg1p,
              const unsigned char* __restrict__ wg2p,
              const unsigned char* __restrict__ wsp,
              const float* __restrict__ b1,
              const float* __restrict__ a1w, const float* __restrict__ a1bp,
              const float* __restrict__ a2w, const float* __restrict__ a2bp,
              const float* __restrict__ bagg,
              __half* __restrict__ gall, float* __restrict__ a1out,
              float* __restrict__ a2all, float* __restrict__ selfout) {
    extern __shared__ char sraw[];
    const u32 sb = smem_to_u32(sraw);
    const u32 base = (sb + 1023u) & ~1023u;
    char* bp = sraw + (base - sb);
    float* sBB  = (float*)(bp + OFF_HDR);
    float* sAW1 = sBB + 128;
    float* sAW2 = sAW1 + 128;
    float* sBG  = sAW2 + 128;
    float* sPA1 = sBG + 128;
    float* sPA2 = sPA1 + 128;

    // dataset select by block id
    int b = blockIdx.x;
    const float* x;
    const unsigned char* wgh;
    int nrows, goff, tile;
    bool ds0 = false;
    if (b < NB0) {
        x = x0; nrows = N0; goff = 0; wgh = wg0p; tile = b; ds0 = true;
    } else if (b < NB0 + NB1) {
        x = x1; nrows = N1; goff = N0; wgh = wg1p; tile = b - NB0;
    } else {
        x = x2; nrows = N2; goff = N0 + N1; wgh = wg2p; tile = b - NB0 - NB1;
    }
    __half* gout = gall + (size_t)goff * D;
    float* a2out = a2all + goff;
    const int rbase = tile * 128;

    const int tid = threadIdx.x, wid = tid >> 5, lane = tid & 31;
    const int wm = wid & 3, wn = wid >> 2;
    const int r0 = wm * 32, cbase = wn * 64;
    const u32 sA = base + OFF_A;
    const u32 sW = base + OFF_W;

    if (tid < 128) {
        sBB[tid] = b1[tid];
        sAW1[tid] = a1w[tid];
        sAW2[tid] = a2w[tid];
        sBG[tid] = bagg[tid];
    }
    copy32k(bp + OFF_W, w1p, tid);
#pragma unroll 1
    for (int it = 0; it < 8; it++) {
        int f = tid + it * 256;
        int row = f >> 4, kc = f & 15;
        float v[8];
        if (rbase + row < nrows) {
            const float4* xp = (const float4*)(x + (size_t)(rbase + row) * 128 + kc * 8);
            float4 p0 = xp[0], p1 = xp[1];
            v[0] = p0.x; v[1] = p0.y; v[2] = p0.z; v[3] = p0.w;
            v[4] = p1.x; v[5] = p1.y; v[6] = p1.z; v[7] = p1.w;
        } else {
#pragma unroll
            for (int j = 0; j < 8; j++) v[j] = 0.f;
        }
        *(uint4*)(bp + OFF_A + CH(row, kc)) = pack8h(v);
    }
    __syncthreads();

    float c[2][8][4];
    float pph1[4], pph2[4];

    // ---- GEMM1: h = x @ W1^T ----
    gemm_pass(sA, sW, r0, cbase, lane, c);
    __syncthreads();   // all warps done reading sA(x)/sW before overwrite

    // epilogue 1: bias+relu, attention dots, h -> sA fp16
#pragma unroll
    for (int mt = 0; mt < 2; mt++)
#pragma unroll
        for (int half = 0; half < 2; half++) {
            int row = r0 + mt * 16 + half * 8 + (lane >> 2);
            float ph1 = 0.f, ph2 = 0.f;
#pragma unroll
            for (int nt = 0; nt < 8; nt++) {
                int col = cbase + nt * 8 + 2 * (lane & 3);
                float h0 = fmaxf(c[mt][nt][half * 2 + 0] + sBB[col], 0.f);
                float h1 = fmaxf(c[mt][nt][half * 2 + 1] + sBB[col + 1], 0.f);
                ph1 += h0 * sAW1[col] + h1 * sAW1[col + 1];
                ph2 += h0 * sAW2[col] + h1 * sAW2[col + 1];
                __half2 hhi = __floats2half2_rn(h0, h1);
                u32 ao = (u32)(row * 256 + (((col >> 3) ^ (row & 7)) << 4) + (col & 7) * 2);
                *(u32*)(bp + OFF_A + ao) = *(u32*)&hhi;
            }
            ph1 += __shfl_xor_sync(0xffffffffu, ph1, 1);
            ph1 += __shfl_xor_sync(0xffffffffu, ph1, 2);
            ph2 += __shfl_xor_sync(0xffffffffu, ph2, 1);
            ph2 += __shfl_xor_sync(0xffffffffu, ph2, 2);
            pph1[mt * 2 + half] = ph1;
            pph2[mt * 2 + half] = ph2;
            if (wn == 0 && (lane & 3) == 0) {
                sPA1[row] = ph1;
                sPA2[row] = ph2;
            }
        }
    copy32k(bp + OFF_W, wgh, tid);   // stage Wg (safe: post-GEMM1 barrier above)
    __syncthreads();
    if (wn == 1 && (lane & 3) == 0) {
        const float a1b = *a1bp, a2b = *a2bp;
#pragma unroll
        for (int mt = 0; mt < 2; mt++)
#pragma unroll
            for (int half = 0; half < 2; half++) {
                int row = r0 + mt * 16 + half * 8 + (lane >> 2);
                int grow = rbase + row;
                if (grow < nrows) {
                    if (ds0) a1out[grow] = sPA1[row] + pph1[mt * 2 + half] + a1b;
                    a2out[grow] = sPA2[row] + pph2[mt * 2 + half] + a2b;
                }
            }
    }

    // ---- GEMM2: g = h @ Wg^T -> fp16 global ----
    gemm_pass(sA, sW, r0, cbase, lane, c);
#pragma unroll
    for (int mt = 0; mt < 2; mt++)
#pragma unroll
        for (int half = 0; half < 2; half++) {
            int row = r0 + mt * 16 + half * 8 + (lane >> 2);
            int grow = rbase + row;
            if (grow < nrows) {
#pragma unroll
                for (int nt = 0; nt < 8; nt++) {
                    int col = cbase + nt * 8 + 2 * (lane & 3);
                    __half2 hv = __floats2half2_rn(c[mt][nt][half * 2 + 0],
                                                   c[mt][nt][half * 2 + 1]);
                    *(u32*)(gout + (size_t)grow * D + col) = *(u32*)&hv;
                }
            }
        }

    // ---- GEMM3 (x0 only): self = h @ Wself^T + bagg -> out ----
    if (ds0) {
        __syncthreads();   // all warps done reading sW(Wg)
        copy32k(bp + OFF_W, wsp, tid);
        __syncthreads();
        gemm_pass(sA, sW, r0, cbase, lane, c);
#pragma unroll
        for (int mt = 0; mt < 2; mt++)
#pragma unroll
            for (int half = 0; half < 2; half++) {
                int row = r0 + mt * 16 + half * 8 + (lane >> 2);
                int grow = rbase + row;
                if (grow < nrows) {
#pragma unroll
                    for (int nt = 0; nt < 8; nt++) {
                        int col = cbase + nt * 8 + 2 * (lane & 3);
                        float2 v = make_float2(c[mt][nt][half * 2 + 0] + sBG[col],
                                               c[mt][nt][half * 2 + 1] + sBG[col + 1]);
                        *(float2*)(selfout + (size_t)grow * D + col) = v;
                    }
                }
            }
    }
}

// ---------------- binning kernels (combined CSR over all 3 lists) ----------------
__global__ void zero_kernel(int* p, int n) {
    int i = blockIdx.x * blockDim.x + threadIdx.x;
    if (i < n) p[i] = 0;
}

__global__ void hist_kernel(const int* __restrict__ r0, int E0,
                            const int* __restrict__ r1, int E1,
                            const int* __restrict__ r2, int E2,
                            int* __restrict__ cnt) {
    int t = blockIdx.x * blockDim.x + threadIdx.x;
    int row;
    if (t < E0) row = __ldg(r0 + t);
    else if ((t -= E0) < E1) row = __ldg(r1 + t);
    else if ((t -= E1) < E2) row = __ldg(r2 + t);
    else return;
    atomicAdd(&cnt[row], 1);
}

// ---- parallel scan phase A: per-block sums of 4096-element chunks ----
__global__ __launch_bounds__(1024)
void scanA_kernel(const int* __restrict__ cnt, int n, int* __restrict__ bsum) {
    __shared__ int wsum[32];
    const int tid = threadIdx.x, lane = tid & 31, wid = tid >> 5;
    int idx = blockIdx.x * SCAN_CHUNK + tid * 4;
    int s = 0;
#pragma unroll
    for (int j = 0; j < 4; j++) s += (idx + j < n) ? cnt[idx + j] : 0;
#pragma unroll
    for (int off = 16; off >= 1; off >>= 1) s += __shfl_down_sync(0xffffffffu, s, off);
    if (lane == 0) wsum[wid] = s;
    __syncthreads();
    if (wid == 0) {
        int y = wsum[lane];
#pragma unroll
        for (int off = 16; off >= 1; off >>= 1) y += __shfl_down_sync(0xffffffffu, y, off);
        if (lane == 0) bsum[blockIdx.x] = y;
    }
}

// ---- phase C: per-block exclusive scan; block offset self-computed from bsum ----
__global__ __launch_bounds__(1024)
void scanC_kernel(const int* __restrict__ cnt, int n, int nb,
                  const int* __restrict__ bsum,
                  int* __restrict__ offs, int* __restrict__ cur) {
    __shared__ int wsum[32];
    __shared__ int s_boff, s_total;
    const int tid = threadIdx.x, lane = tid & 31, wid = tid >> 5;
    if (wid == 0) {
        int v = (lane < nb) ? bsum[lane] : 0;            // nb <= 25 < 32
        int pre = (lane < blockIdx.x) ? v : 0;
        int tot = v;
#pragma unroll
        for (int off = 16; off >= 1; off >>= 1) {
            pre += __shfl_down_sync(0xffffffffu, pre, off);
            tot += __shfl_down_sync(0xffffffffu, tot, off);
        }
        if (lane == 0) { s_boff = pre; s_total = tot; }
    }
    int idx = blockIdx.x * SCAN_CHUNK + tid * 4;
    int v[4];
#pragma unroll
    for (int j = 0; j < 4; j++) v[j] = (idx + j < n) ? cnt[idx + j] : 0;
    int tsum = v[0] + v[1] + v[2] + v[3];
    int xv = tsum;
#pragma unroll
    for (int off = 1; off < 32; off <<= 1) {
        int t = __shfl_up_sync(0xffffffffu, xv, off);
        if (lane >= off) xv += t;
    }
    if (lane == 31) wsum[wid] = xv;
    __syncthreads();
    if (wid == 0) {
        int y = wsum[lane];
#pragma unroll
        for (int off = 1; off < 32; off <<= 1) {
            int t = __shfl_up_sync(0xffffffffu, y, off);
            if (lane >= off) y += t;
        }
        wsum[lane] = y;
    }
    __syncthreads();
    int warpoff = (wid == 0) ? 0 : wsum[wid - 1];
    int excl = s_boff + warpoff + xv - tsum;
#pragma unroll
    for (int j = 0; j < 4; j++) {
        if (idx + j < n) { offs[idx + j] = excl; cur[idx + j] = excl; }
        excl += v[j];
    }
    if (blockIdx.x == 0 && tid == 0) offs[n] = s_total;
}

// ---- scat (after node + scanC): bin edge + fuse sigmoid weight ----
__device__ __forceinline__ float fsig(float s) {
    return 1.0f / (1.0f + __expf(-s));
}

__global__ void scat_kernel(const int* __restrict__ r0, const int* __restrict__ c0, int E0,
                            const int* __restrict__ r1, const int* __restrict__ c1, int E1,
                            const int* __restrict__ r2, const int* __restrict__ c2, int E2,
                            int base1, int base2,
                            const float* __restrict__ a1, const float* __restrict__ a2,
                            int* __restrict__ cur, int2* __restrict__ sedge) {
    int t = blockIdx.x * blockDim.x + threadIdx.x;
    int row, col;
    if (t < E0) { row = __ldg(r0 + t); col = __ldg(c0 + t); }
    else if ((t -= E0) < E1) { row = __ldg(r1 + t); col = __ldg(c1 + t) + base1; }
    else if ((t -= E1) < E2) { row = __ldg(r2 + t); col = __ldg(c2 + t) + base2; }
    else return;
    float s = fsig(__ldg(a1 + row) + __ldg(a2 + col));
    int p = atomicAdd(&cur[row], 1);
    sedge[p] = make_int2(col, __float_as_int(s));
}

// ---------------- aggregate: one warp per row, half-warp per edge ----------------
// half-warp lane hl (0-15) accumulates cols hl*8..hl*8+7 for edge c
__device__ __forceinline__ void gacc16(int c, float sv, int hl,
                                       const __half* __restrict__ g, float acc[8]) {
    uint4 u = __ldg((const uint4*)(g + (size_t)c * D) + hl);
    float2 f0 = __half22float2(*reinterpret_cast<__half2*>(&u.x));
    float2 f1 = __half22float2(*reinterpret_cast<__half2*>(&u.y));
    float2 f2 = __half22float2(*reinterpret_cast<__half2*>(&u.z));
    float2 f3 = __half22float2(*reinterpret_cast<__half2*>(&u.w));
    acc[0] += sv * f0.x; acc[1] += sv * f0.y;
    acc[2] += sv * f1.x; acc[3] += sv * f1.y;
    acc[4] += sv * f2.x; acc[5] += sv * f2.y;
    acc[6] += sv * f3.x; acc[7] += sv * f3.y;
}

__global__ __launch_bounds__(256)
void agg_kernel(const int* __restrict__ offs, const int2* __restrict__ sedge,
                const __half* __restrict__ g, float* __restrict__ out, int n0) {
    int row = blockIdx.x * 8 + (threadIdx.x >> 5);
    if (row >= n0) return;
    int lane = threadIdx.x & 31;
    int hw = lane >> 4;        // half-warp id 0/1
    int hl = lane & 15;        // lane within half-warp
    float acc[8];
#pragma unroll
    for (int j = 0; j < 8; j++) acc[j] = 0.f;
    int s = __ldg(offs + row), e = __ldg(offs + row + 1);
    int i = s + hw;
    for (; i + 2 < e; i += 4) {
        int2 ea = __ldg(sedge + i);
        int2 eb = __ldg(sedge + i + 2);
        gacc16(ea.x, __int_as_float(ea.y), hl, g, acc);
        gacc16(eb.x, __int_as_float(eb.y), hl, g, acc);
    }
    for (; i < e; i += 2) {
        int2 ea = __ldg(sedge + i);
        gacc16(ea.x, __int_as_float(ea.y), hl, g, acc);
    }
#pragma unroll
    for (int j = 0; j < 8; j++) acc[j] += __shfl_down_sync(0xffffffffu, acc[j], 16);
    if (hw == 0) {
        float4* op = (float4*)(out + (size_t)row * D + hl * 8);
        float4 c0 = op[0], c1 = op[1];
        c0.x += acc[0]; c0.y += acc[1]; c0.z += acc[2]; c0.w += acc[3];
        c1.x += acc[4]; c1.y += acc[5]; c1.z += acc[6]; c1.w += acc[7];
        op[0] = c0;
        op[1] = c1;
    }
}

// ---------------- launch ----------------
extern "C" void kernel_launch(void* const* d_in, const int* in_sizes, int n_in,
                              void* d_out, int out_size) {
    const float* x0   = (const float*)d_in[0];
    const float* x1   = (const float*)d_in[1];
    const float* x2   = (const float*)d_in[2];
    const float* W1   = (const float*)d_in[3];
    const float* b1   = (const float*)d_in[4];
    const float* a1w  = (const float*)d_in[5];
    const float* a1b  = (const float*)d_in[6];
    const float* a2w  = (const float*)d_in[7];
    const float* a2b  = (const float*)d_in[8];
    const float* Wagg = (const float*)d_in[9];
    const float* bagg = (const float*)d_in[10];
    const int* ar0 = (const int*)d_in[11];
    const int* ac0 = (const int*)d_in[12];
    const int* ar1 = (const int*)d_in[13];
    const int* ac1 = (const int*)d_in[14];
    const int* ar2 = (const int*)d_in[15];
    const int* ac2 = (const int*)d_in[16];
    float* out = (float*)d_out;

    const int N0 = in_sizes[0] / D;
    const int N1 = in_sizes[1] / D;
    const int N2 = in_sizes[2] / D;
    const int E0 = in_sizes[11];
    const int E1 = in_sizes[13];
    const int E2 = in_sizes[15];

    __half* pg;
    float *pa2, *pa1;
    int *pcnt, *poff, *pcur, *pbsum;
    int2* psedge;
    unsigned char* pwp;
    cudaGetSymbolAddress((void**)&pg, g_gall);
    cudaGetSymbolAddress((void**)&pa2, g_a2all);
    cudaGetSymbolAddress((void**)&pa1, g_a1_0);
    cudaGetSymbolAddress((void**)&pcnt, g_cnt);
    cudaGetSymbolAddress((void**)&poff, g_off);
    cudaGetSymbolAddress((void**)&pcur, g_cur);
    cudaGetSymbolAddress((void**)&psedge, g_sedge);
    cudaGetSymbolAddress((void**)&pwp, g_wprep);
    cudaGetSymbolAddress((void**)&pbsum, g_bsum);

    cudaFuncSetAttribute(node_all, cudaFuncAttributeMaxDynamicSharedMemorySize, SMEM_REQ);

    #define WHI(m) (pwp + (size_t)(m) * 2 * 32768)

    // fork a side stream for the binning chain (independent of node GEMMs)
    cudaStream_t s2;
    cudaEvent_t eRoot, eJoin;
    cudaStreamCreateWithFlags(&s2, cudaStreamNonBlocking);
    cudaEventCreateWithFlags(&eRoot, cudaEventDisableTiming);
    cudaEventCreateWithFlags(&eJoin, cudaEventDisableTiming);
    cudaEventRecord(eRoot, 0);
    cudaStreamWaitEvent(s2, eRoot, 0);

    const int ET = E0 + E1 + E2;
    const int NB = (N0 + SCAN_CHUNK - 1) / SCAN_CHUNK;

    // side chain: zero -> hist -> scanA -> scanC
    zero_kernel<<<(N0 + 256) / 256, 256, 0, s2>>>(pcnt, N0 + 1);
    hist_kernel<<<(ET + 255) / 256, 256, 0, s2>>>(ar0, E0, ar1, E1, ar2, E2, pcnt);
    scanA_kernel<<<NB, 1024, 0, s2>>>(pcnt, N0, pbsum);
    scanC_kernel<<<NB, 1024, 0, s2>>>(pcnt, N0, NB, pbsum, poff, pcur);
    cudaEventRecord(eJoin, s2);

    // main chain: prep_w -> node_all
    prep_w<<<40, 256>>>(W1, Wagg, pwp);
    const int NB0 = (N0 + 127) / 128;
    const int NB1 = (N1 + 127) / 128;
    const int NB2 = (N2 + 127) / 128;
    node_all<<<NB0 + NB1 + NB2, 256, SMEM_REQ>>>(
        x0, x1, x2, N0, N1, N2, NB0, NB1,
        WHI(0), WHI(2), WHI(3), WHI(4), WHI(1),
        b1, a1w, a1b, a2w, a2b, bagg,
        pg, pa1, pa2, out);

    // join: scat needs cur (side) + a1/a2 (main)
    cudaStreamWaitEvent(0, eJoin, 0);
    scat_kernel<<<(ET + 255) / 256, 256>>>(ar0, ac0, E0, ar1, ac1, E1, ar2, ac2, E2,
                                           N0, N0 + N1, pa1, pa2, pcur, psedge);

    agg_kernel<<<(N0 + 7) / 8, 256>>>(poff, psedge, pg, out, N0);

    // cleanup only when not capturing (leaks a few streams across the
    // harness's handful of calls; no device memory involved)
    cudaStreamCaptureStatus cst = cudaStreamCaptureStatusNone;
    cudaStreamIsCapturing(0, &cst);
    if (cst == cudaStreamCaptureStatusNone) {
        cudaStreamDestroy(s2);
        cudaEventDestroy(eRoot);
        cudaEventDestroy(eJoin);
    }
}